// round 2
// baseline (speedup 1.0000x reference)
#include <cuda_runtime.h>
#include <cuda_bf16.h>
#include <math.h>

// Problem dims
#define LL 512
#define BB 64
#define II 256
#define HH 512
#define G4 2048   // 4*H

// ---------------- scratch (static device globals; no allocation) ----------------
__device__ float g_xT[(size_t)LL * BB * II];          // [t][b][I]
__device__ float g_gates_f[(size_t)LL * BB * G4];     // [t][b][4H]
__device__ float g_gates_r[(size_t)LL * BB * G4];     // [t][b][4H]
__device__ float g_hcat[(size_t)LL * BB * 2 * HH];    // [t][b][2H]
__device__ float g_state[2 * 2 * BB * HH];            // per dir: h_even, h_odd
__device__ unsigned g_bar;                            // global barrier counter

// ---------------- transpose x[b][l][i] -> xT[l][b][i] ----------------
__global__ void transpose_x(const float4* __restrict__ x, float4* __restrict__ xT) {
    int idx = blockIdx.x * blockDim.x + threadIdx.x;   // over LL*BB*(II/4) = 2097152
    int i4 = idx & 63;            // II/4 = 64
    int m  = idx >> 6;            // t*64 + b
    int t  = m >> 6;
    int b  = m & 63;
    xT[idx] = x[((size_t)(b * LL + t)) * 64 + i4];
}

// ---------------- fp32 SGEMM: C[M,N] = A[M,K] * W[N,K]^T + (b1[n]+b2[n]) ----------------
__global__ __launch_bounds__(256) void sgemm_tn(
    int M, int N, int K,
    const float* __restrict__ A,
    const float* __restrict__ W,
    const float* __restrict__ bias1,
    const float* __restrict__ bias2,
    float* __restrict__ C)
{
    __shared__ float As[8][128];
    __shared__ float Ws[8][128];

    int tid = threadIdx.x;
    int m0 = blockIdx.y * 128;
    int n0 = blockIdx.x * 128;

    int lr = tid >> 1;            // 0..127 row within tile
    int lk = (tid & 1) * 4;       // 0 or 4
    int tx = tid & 15;            // 0..15
    int ty = tid >> 4;            // 0..15

    const float* Arow = A + (size_t)(m0 + lr) * K + lk;
    const float* Wrow = W + (size_t)(n0 + lr) * K + lk;

    float acc[8][8];
#pragma unroll
    for (int i = 0; i < 8; i++)
#pragma unroll
        for (int j = 0; j < 8; j++) acc[i][j] = 0.0f;

    for (int k0 = 0; k0 < K; k0 += 8) {
        float4 a4 = *(const float4*)(Arow + k0);
        float4 w4 = *(const float4*)(Wrow + k0);
        __syncthreads();
        As[lk + 0][lr] = a4.x; As[lk + 1][lr] = a4.y;
        As[lk + 2][lr] = a4.z; As[lk + 3][lr] = a4.w;
        Ws[lk + 0][lr] = w4.x; Ws[lk + 1][lr] = w4.y;
        Ws[lk + 2][lr] = w4.z; Ws[lk + 3][lr] = w4.w;
        __syncthreads();
#pragma unroll
        for (int k = 0; k < 8; k++) {
            float a[8], w[8];
            *(float4*)(a)     = *(const float4*)&As[k][ty * 8];
            *(float4*)(a + 4) = *(const float4*)&As[k][ty * 8 + 4];
            *(float4*)(w)     = *(const float4*)&Ws[k][tx * 8];
            *(float4*)(w + 4) = *(const float4*)&Ws[k][tx * 8 + 4];
#pragma unroll
            for (int i = 0; i < 8; i++)
#pragma unroll
                for (int j = 0; j < 8; j++)
                    acc[i][j] += a[i] * w[j];
        }
    }

#pragma unroll
    for (int i = 0; i < 8; i++) {
        int m = m0 + ty * 8 + i;
        float* crow = C + (size_t)m * N + n0 + tx * 8;
#pragma unroll
        for (int j = 0; j < 8; j++) {
            int n = n0 + tx * 8 + j;
            crow[j] = acc[i][j] + bias1[n] + bias2[n];
        }
    }
}

// ---------------- persistent LSTM layer kernel ----------------
// Grid: 128 CTAs = dir(2) x hslice(32: 16 units each) x bslice(2: 32 batches each).
// All 128 CTAs are co-resident (1 CTA/SM, 148 SMs) -> global spin barrier is safe.
// 256 threads: tu = tid&15 (unit within slice), tbg = tid>>4 (batch pair {tbg, tbg+16}).
// Each thread persistently owns 1 unit x 2 batches: cell state c stays in registers.
// Whh slice (4 gates x 16 units x 512) is staged into SMEM ONCE (128 KB).
// h state goes through gmem (double-buffered) with a global barrier per step.
#define PK_SMEM ((4 * 16 * 512 + 32 * 516) * 4)   // 131072 + 66048 = 197120 B

__global__ __launch_bounds__(256) void lstm_layer(
    const float* __restrict__ gates_f,
    const float* __restrict__ gates_r,
    const float* __restrict__ Whh_f,
    const float* __restrict__ Whh_r,
    float* __restrict__ state,
    float* __restrict__ outbuf,
    int out_mode)
{
    extern __shared__ float smem[];
    float4* sh_w4 = (float4*)smem;          // [(g*128 + k4)*16 + u] -> W[g][u][k4*4..+3]
    float*  sh_h  = smem + 4 * 16 * 512;    // [32][516] padded rows

    int tid = threadIdx.x;
    int bx  = blockIdx.x;
    int dir = bx >> 6;
    int hs  = (bx >> 1) & 31;
    int bs  = bx & 1;
    int u0  = hs * 16;
    int b0  = bs * 32;

    const float* gates = dir ? gates_r : gates_f;
    const float* Whh   = dir ? Whh_r : Whh_f;
    float* sbase = state + dir * 2 * (BB * HH);

    // ---- stage Whh slice into smem once (32 float4 per thread) ----
#pragma unroll
    for (int j = 0; j < 32; j++) {
        int idx = tid + j * 256;            // 0..8191  = (g, k4, u)
        int u   = idx & 15;
        int k4  = (idx >> 4) & 127;
        int g   = idx >> 11;
        sh_w4[idx] = *(const float4*)(Whh + (size_t)(g * HH + u0 + u) * HH + k4 * 4);
    }

    int tu  = tid & 15;
    int tbg = tid >> 4;                     // 0..15
    int bA  = b0 + tbg;
    int bB  = b0 + tbg + 16;
    int u   = u0 + tu;

    float cA = 0.0f, cB = 0.0f;

    for (int s = 0; s < LL; s++) {
        int t   = dir ? (LL - 1 - s) : s;
        int par = s & 1;
        const float* h_in  = sbase + par * (BB * HH);
        float*       h_out = sbase + (par ^ 1) * (BB * HH);

        // ---- stage h tile (32 batches x 512) from gmem (L2, bypass L1) ----
        __syncthreads();
#pragma unroll
        for (int j = 0; j < 16; j++) {
            int idx = tid + j * 256;        // 0..4095 float4
            int b   = idx >> 7;
            int k4  = idx & 127;
            float4 v = __ldcg((const float4*)(h_in + (size_t)(b0 + b) * HH) + k4);
            *(float4*)&sh_h[b * 516 + k4 * 4] = v;
        }
        __syncthreads();

        // ---- gates GEMM fragment: acc[gate][batch of 2] ----
        float acc[4][2];
#pragma unroll
        for (int g = 0; g < 4; g++) { acc[g][0] = 0.0f; acc[g][1] = 0.0f; }

        const float* hrowA = sh_h + tbg * 516;
        const float* hrowB = sh_h + (tbg + 16) * 516;
#pragma unroll 4
        for (int k4 = 0; k4 < 128; k4++) {
            float4 h0 = *(const float4*)(hrowA + k4 * 4);
            float4 h1 = *(const float4*)(hrowB + k4 * 4);
#pragma unroll
            for (int g = 0; g < 4; g++) {
                float4 w = sh_w4[(g * 128 + k4) * 16 + tu];
                acc[g][0] += w.x * h0.x + w.y * h0.y + w.z * h0.z + w.w * h0.w;
                acc[g][1] += w.x * h1.x + w.y * h1.y + w.z * h1.z + w.w * h1.w;
            }
        }

        // ---- LSTM pointwise (thread-local c) ----
        size_t gbA = ((size_t)t * BB + bA) * G4 + u;
        size_t gbB = ((size_t)t * BB + bB) * G4 + u;
        {
            float gi = gates[gbA + 0 * HH] + acc[0][0];
            float gf = gates[gbA + 1 * HH] + acc[1][0];
            float gg = gates[gbA + 2 * HH] + acc[2][0];
            float go = gates[gbA + 3 * HH] + acc[3][0];
            float si = 1.0f / (1.0f + expf(-gi));
            float sf = 1.0f / (1.0f + expf(-gf));
            float so = 1.0f / (1.0f + expf(-go));
            cA = sf * cA + si * tanhf(gg);
            float h2 = so * tanhf(cA);
            __stcg(&h_out[bA * HH + u], h2);
            size_t orow = out_mode ? ((size_t)bA * LL + t) : ((size_t)t * BB + bA);
            outbuf[orow * (2 * HH) + dir * HH + u] = h2;
        }
        {
            float gi = gates[gbB + 0 * HH] + acc[0][1];
            float gf = gates[gbB + 1 * HH] + acc[1][1];
            float gg = gates[gbB + 2 * HH] + acc[2][1];
            float go = gates[gbB + 3 * HH] + acc[3][1];
            float si = 1.0f / (1.0f + expf(-gi));
            float sf = 1.0f / (1.0f + expf(-gf));
            float so = 1.0f / (1.0f + expf(-go));
            cB = sf * cB + si * tanhf(gg);
            float h2 = so * tanhf(cB);
            __stcg(&h_out[bB * HH + u], h2);
            size_t orow = out_mode ? ((size_t)bB * LL + t) : ((size_t)t * BB + bB);
            outbuf[orow * (2 * HH) + dir * HH + u] = h2;
        }

        // ---- global barrier across 128 CTAs ----
        __threadfence();
        __syncthreads();
        if (tid == 0) {
            atomicAdd(&g_bar, 1u);
            unsigned target = (unsigned)(s + 1) * gridDim.x;
            while (*(volatile unsigned*)&g_bar < target) { }
        }
        __syncthreads();
    }
}

// ---------------- host launcher ----------------
extern "C" void kernel_launch(void* const* d_in, const int* in_sizes, int n_in,
                              void* d_out, int out_size)
{
    const float* x       = (const float*)d_in[0];
    const float* Wih_f0  = (const float*)d_in[1];
    const float* Whh_f0  = (const float*)d_in[2];
    const float* bih_f0  = (const float*)d_in[3];
    const float* bhh_f0  = (const float*)d_in[4];
    const float* Wih_r0  = (const float*)d_in[5];
    const float* Whh_r0  = (const float*)d_in[6];
    const float* bih_r0  = (const float*)d_in[7];
    const float* bhh_r0  = (const float*)d_in[8];
    const float* Wih_f1  = (const float*)d_in[9];
    const float* Whh_f1  = (const float*)d_in[10];
    const float* bih_f1  = (const float*)d_in[11];
    const float* bhh_f1  = (const float*)d_in[12];
    const float* Wih_r1  = (const float*)d_in[13];
    const float* Whh_r1  = (const float*)d_in[14];
    const float* bih_r1  = (const float*)d_in[15];
    const float* bhh_r1  = (const float*)d_in[16];

    float *xT, *gf, *gr, *hcat, *state;
    unsigned* bar;
    cudaGetSymbolAddress((void**)&xT,    g_xT);
    cudaGetSymbolAddress((void**)&gf,    g_gates_f);
    cudaGetSymbolAddress((void**)&gr,    g_gates_r);
    cudaGetSymbolAddress((void**)&hcat,  g_hcat);
    cudaGetSymbolAddress((void**)&state, g_state);
    cudaGetSymbolAddress((void**)&bar,   g_bar);

    cudaFuncSetAttribute(lstm_layer, cudaFuncAttributeMaxDynamicSharedMemorySize, PK_SMEM);

    const int M = LL * BB;   // 32768

    // x -> xT [t][b][I]
    transpose_x<<<8192, 256>>>((const float4*)x, (float4*)xT);

    dim3 gdim(G4 / 128, M / 128);   // (16, 256)

    // ---- layer 0 ----
    sgemm_tn<<<gdim, 256>>>(M, G4, II, xT, Wih_f0, bih_f0, bhh_f0, gf);
    sgemm_tn<<<gdim, 256>>>(M, G4, II, xT, Wih_r0, bih_r0, bhh_r0, gr);
    cudaMemsetAsync(state, 0, sizeof(float) * 2 * 2 * BB * HH, 0);
    cudaMemsetAsync(bar,   0, sizeof(unsigned), 0);
    lstm_layer<<<128, 256, PK_SMEM>>>(gf, gr, Whh_f0, Whh_r0, state, hcat, 0);

    // ---- layer 1 ----
    sgemm_tn<<<gdim, 256>>>(M, G4, 2 * HH, hcat, Wih_f1, bih_f1, bhh_f1, gf);
    sgemm_tn<<<gdim, 256>>>(M, G4, 2 * HH, hcat, Wih_r1, bih_r1, bhh_r1, gr);
    cudaMemsetAsync(state, 0, sizeof(float) * 2 * 2 * BB * HH, 0);
    cudaMemsetAsync(bar,   0, sizeof(unsigned), 0);
    lstm_layer<<<128, 256, PK_SMEM>>>(gf, gr, Whh_f1, Whh_r1, state, (float*)d_out, 1);
}

// round 3
// speedup vs baseline: 1.2394x; 1.2394x over previous
#include <cuda_runtime.h>
#include <cuda_bf16.h>
#include <math.h>

// Problem dims
#define LL 512
#define BB 64
#define II 256
#define HH 512
#define G4 2048   // 4*H

// ---------------- scratch (static device globals; no allocation) ----------------
__device__ float g_xT[(size_t)LL * BB * II];          // [t][b][I]
__device__ float g_gates_f[(size_t)LL * BB * G4];     // [t][b][4H]
__device__ float g_gates_r[(size_t)LL * BB * G4];     // [t][b][4H]
__device__ float g_hcat[(size_t)LL * BB * 2 * HH];    // [t][b][2H]
__device__ float g_state[2 * 2 * BB * HH];            // per dir: h_even, h_odd
__device__ unsigned g_bar;                            // global barrier counter

// ---------------- transpose x[b][l][i] -> xT[l][b][i] ----------------
__global__ void transpose_x(const float4* __restrict__ x, float4* __restrict__ xT) {
    int idx = blockIdx.x * blockDim.x + threadIdx.x;   // over LL*BB*(II/4) = 2097152
    int i4 = idx & 63;            // II/4 = 64
    int m  = idx >> 6;            // t*64 + b
    int t  = m >> 6;
    int b  = m & 63;
    xT[idx] = x[((size_t)(b * LL + t)) * 64 + i4];
}

// ---------------- tf32 tensor-core GEMM ----------------
// C[M,N] = A[M,K] @ W[N,K]^T + (b1[n] + b2[n])
// Block 128x256, BK=16, 256 threads = 8 warps in 2(m) x 4(n), warp tile 64x64.
// mma.sync.m16n8k8.row.col.f32.tf32.tf32.f32
#define BM 128
#define BN 256
#define BK 16

__device__ __forceinline__ unsigned f2tf32(float x) {
    unsigned r;
    asm("cvt.rna.tf32.f32 %0, %1;" : "=r"(r) : "f"(x));
    return r;
}

__global__ __launch_bounds__(256, 1) void gemm_tf32(
    int M, int N, int K,
    const float* __restrict__ A,
    const float* __restrict__ W,
    const float* __restrict__ bias1,
    const float* __restrict__ bias2,
    float* __restrict__ C)
{
    __shared__ unsigned As[BK][BM + 4];
    __shared__ unsigned Bs[BK][BN + 4];

    int tid  = threadIdx.x;
    int lane = tid & 31;
    int warp = tid >> 5;
    int gid  = lane >> 2;      // 0..7
    int tg   = lane & 3;       // 0..3
    int wm   = warp >> 2;      // 0..1
    int wn   = warp & 3;       // 0..3
    int m0   = blockIdx.y * BM;
    int n0   = blockIdx.x * BN;

    float acc[4][8][4];
#pragma unroll
    for (int i = 0; i < 4; i++)
#pragma unroll
        for (int j = 0; j < 8; j++)
#pragma unroll
            for (int r = 0; r < 4; r++) acc[i][j][r] = 0.0f;

    // staging register buffers
    float4 ar[2], br[4];

    // A tile: 128 rows x 4 float4 = 512 float4; thread handles idx = tid + j*256
    // B tile: 256 rows x 4 float4 = 1024 float4
#define LOAD_TILES(k0)                                                          \
    {                                                                           \
        _Pragma("unroll")                                                       \
        for (int j = 0; j < 2; j++) {                                           \
            int idx = tid + j * 256;                                            \
            int row = idx >> 2, kq = idx & 3;                                   \
            ar[j] = ((const float4*)(A + (size_t)(m0 + row) * K + (k0)))[kq];   \
        }                                                                       \
        _Pragma("unroll")                                                       \
        for (int j = 0; j < 4; j++) {                                           \
            int idx = tid + j * 256;                                            \
            int row = idx >> 2, kq = idx & 3;                                   \
            br[j] = ((const float4*)(W + (size_t)(n0 + row) * K + (k0)))[kq];   \
        }                                                                       \
    }

    LOAD_TILES(0);

    for (int k0 = 0; k0 < K; k0 += BK) {
        __syncthreads();   // previous compute done before overwrite
#pragma unroll
        for (int j = 0; j < 2; j++) {
            int idx = tid + j * 256;
            int row = idx >> 2, kq = idx & 3;
            As[kq * 4 + 0][row] = f2tf32(ar[j].x);
            As[kq * 4 + 1][row] = f2tf32(ar[j].y);
            As[kq * 4 + 2][row] = f2tf32(ar[j].z);
            As[kq * 4 + 3][row] = f2tf32(ar[j].w);
        }
#pragma unroll
        for (int j = 0; j < 4; j++) {
            int idx = tid + j * 256;
            int row = idx >> 2, kq = idx & 3;
            Bs[kq * 4 + 0][row] = f2tf32(br[j].x);
            Bs[kq * 4 + 1][row] = f2tf32(br[j].y);
            Bs[kq * 4 + 2][row] = f2tf32(br[j].z);
            Bs[kq * 4 + 3][row] = f2tf32(br[j].w);
        }
        __syncthreads();

        if (k0 + BK < K) LOAD_TILES(k0 + BK);

#pragma unroll
        for (int ks = 0; ks < 2; ks++) {
            int kb = ks * 8;
            unsigned af[4][4];
#pragma unroll
            for (int mt = 0; mt < 4; mt++) {
                int rb = wm * 64 + mt * 16;
                af[mt][0] = As[kb + tg][rb + gid];
                af[mt][1] = As[kb + tg][rb + gid + 8];
                af[mt][2] = As[kb + tg + 4][rb + gid];
                af[mt][3] = As[kb + tg + 4][rb + gid + 8];
            }
            unsigned bf[8][2];
#pragma unroll
            for (int nt = 0; nt < 8; nt++) {
                int cb = wn * 64 + nt * 8;
                bf[nt][0] = Bs[kb + tg][cb + gid];
                bf[nt][1] = Bs[kb + tg + 4][cb + gid];
            }
#pragma unroll
            for (int mt = 0; mt < 4; mt++)
#pragma unroll
                for (int nt = 0; nt < 8; nt++) {
                    asm volatile(
                        "mma.sync.aligned.m16n8k8.row.col.f32.tf32.tf32.f32 "
                        "{%0,%1,%2,%3}, {%4,%5,%6,%7}, {%8,%9}, {%0,%1,%2,%3};"
                        : "+f"(acc[mt][nt][0]), "+f"(acc[mt][nt][1]),
                          "+f"(acc[mt][nt][2]), "+f"(acc[mt][nt][3])
                        : "r"(af[mt][0]), "r"(af[mt][1]), "r"(af[mt][2]), "r"(af[mt][3]),
                          "r"(bf[nt][0]), "r"(bf[nt][1]));
                }
        }
    }

    // epilogue: C rows m0+wm*64+mt*16+{gid, gid+8}; cols n0+wn*64+nt*8+2*tg+{0,1}
#pragma unroll
    for (int mt = 0; mt < 4; mt++) {
        int r0 = m0 + wm * 64 + mt * 16 + gid;
#pragma unroll
        for (int nt = 0; nt < 8; nt++) {
            int col = n0 + wn * 64 + nt * 8 + 2 * tg;
            float bsum0 = __ldg(bias1 + col)     + __ldg(bias2 + col);
            float bsum1 = __ldg(bias1 + col + 1) + __ldg(bias2 + col + 1);
            float2 v0 = make_float2(acc[mt][nt][0] + bsum0, acc[mt][nt][1] + bsum1);
            float2 v1 = make_float2(acc[mt][nt][2] + bsum0, acc[mt][nt][3] + bsum1);
            *(float2*)(C + (size_t)r0 * N + col)       = v0;
            *(float2*)(C + (size_t)(r0 + 8) * N + col) = v1;
        }
    }
}

// ---------------- persistent LSTM layer kernel (unchanged, known-good) ----------------
#define PK_SMEM ((4 * 16 * 512 + 32 * 516) * 4)   // 131072 + 66048 = 197120 B

__global__ __launch_bounds__(256) void lstm_layer(
    const float* __restrict__ gates_f,
    const float* __restrict__ gates_r,
    const float* __restrict__ Whh_f,
    const float* __restrict__ Whh_r,
    float* __restrict__ state,
    float* __restrict__ outbuf,
    int out_mode)
{
    extern __shared__ float smem[];
    float4* sh_w4 = (float4*)smem;          // [(g*128 + k4)*16 + u]
    float*  sh_h  = smem + 4 * 16 * 512;    // [32][516] padded rows

    int tid = threadIdx.x;
    int bx  = blockIdx.x;
    int dir = bx >> 6;
    int hs  = (bx >> 1) & 31;
    int bs  = bx & 1;
    int u0  = hs * 16;
    int b0  = bs * 32;

    const float* gates = dir ? gates_r : gates_f;
    const float* Whh   = dir ? Whh_r : Whh_f;
    float* sbase = state + dir * 2 * (BB * HH);

#pragma unroll
    for (int j = 0; j < 32; j++) {
        int idx = tid + j * 256;            // (g, k4, u)
        int u   = idx & 15;
        int k4  = (idx >> 4) & 127;
        int g   = idx >> 11;
        sh_w4[idx] = *(const float4*)(Whh + (size_t)(g * HH + u0 + u) * HH + k4 * 4);
    }

    int tu  = tid & 15;
    int tbg = tid >> 4;
    int bA  = b0 + tbg;
    int bB  = b0 + tbg + 16;
    int u   = u0 + tu;

    float cA = 0.0f, cB = 0.0f;

    for (int s = 0; s < LL; s++) {
        int t   = dir ? (LL - 1 - s) : s;
        int par = s & 1;
        const float* h_in  = sbase + par * (BB * HH);
        float*       h_out = sbase + (par ^ 1) * (BB * HH);

        __syncthreads();
#pragma unroll
        for (int j = 0; j < 16; j++) {
            int idx = tid + j * 256;
            int b   = idx >> 7;
            int k4  = idx & 127;
            float4 v = __ldcg((const float4*)(h_in + (size_t)(b0 + b) * HH) + k4);
            *(float4*)&sh_h[b * 516 + k4 * 4] = v;
        }
        __syncthreads();

        float acc[4][2];
#pragma unroll
        for (int g = 0; g < 4; g++) { acc[g][0] = 0.0f; acc[g][1] = 0.0f; }

        const float* hrowA = sh_h + tbg * 516;
        const float* hrowB = sh_h + (tbg + 16) * 516;
#pragma unroll 4
        for (int k4 = 0; k4 < 128; k4++) {
            float4 h0 = *(const float4*)(hrowA + k4 * 4);
            float4 h1 = *(const float4*)(hrowB + k4 * 4);
#pragma unroll
            for (int g = 0; g < 4; g++) {
                float4 w = sh_w4[(g * 128 + k4) * 16 + tu];
                acc[g][0] += w.x * h0.x + w.y * h0.y + w.z * h0.z + w.w * h0.w;
                acc[g][1] += w.x * h1.x + w.y * h1.y + w.z * h1.z + w.w * h1.w;
            }
        }

        size_t gbA = ((size_t)t * BB + bA) * G4 + u;
        size_t gbB = ((size_t)t * BB + bB) * G4 + u;
        {
            float gi = gates[gbA + 0 * HH] + acc[0][0];
            float gf = gates[gbA + 1 * HH] + acc[1][0];
            float gg = gates[gbA + 2 * HH] + acc[2][0];
            float go = gates[gbA + 3 * HH] + acc[3][0];
            float si = 1.0f / (1.0f + expf(-gi));
            float sf = 1.0f / (1.0f + expf(-gf));
            float so = 1.0f / (1.0f + expf(-go));
            cA = sf * cA + si * tanhf(gg);
            float h2 = so * tanhf(cA);
            __stcg(&h_out[bA * HH + u], h2);
            size_t orow = out_mode ? ((size_t)bA * LL + t) : ((size_t)t * BB + bA);
            outbuf[orow * (2 * HH) + dir * HH + u] = h2;
        }
        {
            float gi = gates[gbB + 0 * HH] + acc[0][1];
            float gf = gates[gbB + 1 * HH] + acc[1][1];
            float gg = gates[gbB + 2 * HH] + acc[2][1];
            float go = gates[gbB + 3 * HH] + acc[3][1];
            float si = 1.0f / (1.0f + expf(-gi));
            float sf = 1.0f / (1.0f + expf(-gf));
            float so = 1.0f / (1.0f + expf(-go));
            cB = sf * cB + si * tanhf(gg);
            float h2 = so * tanhf(cB);
            __stcg(&h_out[bB * HH + u], h2);
            size_t orow = out_mode ? ((size_t)bB * LL + t) : ((size_t)t * BB + bB);
            outbuf[orow * (2 * HH) + dir * HH + u] = h2;
        }

        __threadfence();
        __syncthreads();
        if (tid == 0) {
            atomicAdd(&g_bar, 1u);
            unsigned target = (unsigned)(s + 1) * gridDim.x;
            while (*(volatile unsigned*)&g_bar < target) { }
        }
        __syncthreads();
    }
}

// ---------------- host launcher ----------------
extern "C" void kernel_launch(void* const* d_in, const int* in_sizes, int n_in,
                              void* d_out, int out_size)
{
    const float* x       = (const float*)d_in[0];
    const float* Wih_f0  = (const float*)d_in[1];
    const float* Whh_f0  = (const float*)d_in[2];
    const float* bih_f0  = (const float*)d_in[3];
    const float* bhh_f0  = (const float*)d_in[4];
    const float* Wih_r0  = (const float*)d_in[5];
    const float* Whh_r0  = (const float*)d_in[6];
    const float* bih_r0  = (const float*)d_in[7];
    const float* bhh_r0  = (const float*)d_in[8];
    const float* Wih_f1  = (const float*)d_in[9];
    const float* Whh_f1  = (const float*)d_in[10];
    const float* bih_f1  = (const float*)d_in[11];
    const float* bhh_f1  = (const float*)d_in[12];
    const float* Wih_r1  = (const float*)d_in[13];
    const float* Whh_r1  = (const float*)d_in[14];
    const float* bih_r1  = (const float*)d_in[15];
    const float* bhh_r1  = (const float*)d_in[16];

    float *xT, *gf, *gr, *hcat, *state;
    unsigned* bar;
    cudaGetSymbolAddress((void**)&xT,    g_xT);
    cudaGetSymbolAddress((void**)&gf,    g_gates_f);
    cudaGetSymbolAddress((void**)&gr,    g_gates_r);
    cudaGetSymbolAddress((void**)&hcat,  g_hcat);
    cudaGetSymbolAddress((void**)&state, g_state);
    cudaGetSymbolAddress((void**)&bar,   g_bar);

    cudaFuncSetAttribute(lstm_layer, cudaFuncAttributeMaxDynamicSharedMemorySize, PK_SMEM);

    const int M = LL * BB;   // 32768

    transpose_x<<<8192, 256>>>((const float4*)x, (float4*)xT);

    dim3 gdim(G4 / BN, M / BM);   // (8, 256)

    // ---- layer 0 ----
    gemm_tf32<<<gdim, 256>>>(M, G4, II, xT, Wih_f0, bih_f0, bhh_f0, gf);
    gemm_tf32<<<gdim, 256>>>(M, G4, II, xT, Wih_r0, bih_r0, bhh_r0, gr);
    cudaMemsetAsync(state, 0, sizeof(float) * 2 * 2 * BB * HH, 0);
    cudaMemsetAsync(bar,   0, sizeof(unsigned), 0);
    lstm_layer<<<128, 256, PK_SMEM>>>(gf, gr, Whh_f0, Whh_r0, state, hcat, 0);

    // ---- layer 1 ----
    gemm_tf32<<<gdim, 256>>>(M, G4, 2 * HH, hcat, Wih_f1, bih_f1, bhh_f1, gf);
    gemm_tf32<<<gdim, 256>>>(M, G4, 2 * HH, hcat, Wih_r1, bih_r1, bhh_r1, gr);
    cudaMemsetAsync(state, 0, sizeof(float) * 2 * 2 * BB * HH, 0);
    cudaMemsetAsync(bar,   0, sizeof(unsigned), 0);
    lstm_layer<<<128, 256, PK_SMEM>>>(gf, gr, Whh_f1, Whh_r1, state, (float*)d_out, 1);
}

// round 5
// speedup vs baseline: 1.2396x; 1.0002x over previous
#include <cuda_runtime.h>
#include <cuda_bf16.h>
#include <math.h>
#include <cstdint>

// Problem dims
#define LL 512
#define BB 64
#define II 256
#define HH 512
#define G4 2048   // 4*H

// ---------------- scratch (static device globals; no allocation) ----------------
__device__ float g_xT[(size_t)LL * BB * II];          // [t][b][I]
__device__ float g_gates_f[(size_t)LL * BB * G4];     // [t][b][4H]
__device__ float g_gates_r[(size_t)LL * BB * G4];     // [t][b][4H]
__device__ float g_hcat[(size_t)LL * BB * 2 * HH];    // [t][b][2H]
__device__ float g_state[2 * 2 * BB * HH];            // per dir: h_even, h_odd
__device__ unsigned g_bar;                            // global barrier counter

// bf16 split buffers
__device__ __nv_bfloat16 g_Ahi[(size_t)LL * BB * 2 * HH];
__device__ __nv_bfloat16 g_Alo[(size_t)LL * BB * 2 * HH];
__device__ __nv_bfloat16 g_Wfhi[(size_t)G4 * 2 * HH];
__device__ __nv_bfloat16 g_Wflo[(size_t)G4 * 2 * HH];
__device__ __nv_bfloat16 g_Wrhi[(size_t)G4 * 2 * HH];
__device__ __nv_bfloat16 g_Wrlo[(size_t)G4 * 2 * HH];

__device__ __forceinline__ uint32_t smem_u32(const void* p) {
    uint32_t a;
    asm("{ .reg .u64 t; cvta.to.shared.u64 t, %1; cvt.u32.u64 %0, t; }" : "=r"(a) : "l"(p));
    return a;
}

// ---------------- transpose x[b][l][i] -> xT[l][b][i] ----------------
__global__ void transpose_x(const float4* __restrict__ x, float4* __restrict__ xT) {
    int idx = blockIdx.x * blockDim.x + threadIdx.x;
    int i4 = idx & 63;
    int m  = idx >> 6;
    int t  = m >> 6;
    int b  = m & 63;
    xT[idx] = x[((size_t)(b * LL + t)) * 64 + i4];
}

// ---------------- fp32 -> bf16 hi/lo split ----------------
__global__ void split_bf16(const float4* __restrict__ src,
                           __nv_bfloat162* __restrict__ hi,
                           __nv_bfloat162* __restrict__ lo, int n4) {
    int i = blockIdx.x * blockDim.x + threadIdx.x;
    if (i >= n4) return;
    float4 v = src[i];
    __nv_bfloat16 hx = __float2bfloat16(v.x);
    __nv_bfloat16 hy = __float2bfloat16(v.y);
    __nv_bfloat16 hz = __float2bfloat16(v.z);
    __nv_bfloat16 hw = __float2bfloat16(v.w);
    __nv_bfloat16 lx = __float2bfloat16(v.x - __bfloat162float(hx));
    __nv_bfloat16 ly = __float2bfloat16(v.y - __bfloat162float(hy));
    __nv_bfloat16 lz = __float2bfloat16(v.z - __bfloat162float(hz));
    __nv_bfloat16 lw = __float2bfloat16(v.w - __bfloat162float(hw));
    hi[i * 2 + 0] = __nv_bfloat162(hx, hy);
    hi[i * 2 + 1] = __nv_bfloat162(hz, hw);
    lo[i * 2 + 0] = __nv_bfloat162(lx, ly);
    lo[i * 2 + 1] = __nv_bfloat162(lz, lw);
}

// ---------------- bf16 split-GEMM on HMMA (mma.sync m16n8k16) ----------------
// C[M,N] = (Ahi+Alo)[M,K] @ (Bhi+Blo)[N,K]^T + bias   (3 product terms)
// Block 128x128, BK=32 bf16, 256 thr = 8 warps (2m x 4n), warp tile 64x32.
// smem tiles: 128 rows x 32 bf16, row pitch 80B (20 u32: conflict-free ldmatrix).
#define GBK   32
#define GTILE 10240                 // 128 * 80 bytes
#define GSTG  (4 * GTILE)           // Ahi, Alo, Bhi, Blo
#define GB_SMEM (2 * GSTG + 512)    // 2 stages + bias

__global__ __launch_bounds__(256, 1) void gemm_bf16s(
    int M, int N, int K,
    const __nv_bfloat16* __restrict__ Ahi, const __nv_bfloat16* __restrict__ Alo,
    const __nv_bfloat16* __restrict__ Bhi, const __nv_bfloat16* __restrict__ Blo,
    const float* __restrict__ bias1, const float* __restrict__ bias2,
    float* __restrict__ C)
{
    extern __shared__ char sm[];
    uint32_t sb = smem_u32(sm);
    int tid  = threadIdx.x;
    int lane = tid & 31;
    int warp = tid >> 5;
    int gid  = lane >> 2;
    int tg   = lane & 3;
    int wm   = warp >> 2;     // 0..1
    int wn   = warp & 3;      // 0..3
    int n0   = blockIdx.x * 128;
    int m0   = blockIdx.y * 128;

    float* shb = (float*)(sm + 2 * GSTG);
    if (tid < 128) shb[tid] = bias1[n0 + tid] + bias2[n0 + tid];

    const char* srcs[4];
    srcs[0] = (const char*)(Ahi + (size_t)m0 * K);
    srcs[1] = (const char*)(Alo + (size_t)m0 * K);
    srcs[2] = (const char*)(Bhi + (size_t)n0 * K);
    srcs[3] = (const char*)(Blo + (size_t)n0 * K);

#define LOAD_STAGE(kc, bufsel)                                                      \
    {                                                                               \
        _Pragma("unroll")                                                           \
        for (int j = 0; j < 8; j++) {                                               \
            int c    = tid + j * 256;           /* 0..2047 */                       \
            int tile = c >> 9;                                                      \
            int cc   = c & 511;                                                     \
            int row  = cc >> 2, g = cc & 3;                                         \
            uint32_t d = sb + (bufsel) * GSTG + tile * GTILE + row * 80 + g * 16;   \
            const char* s = srcs[tile] + ((size_t)row * K + (kc) * GBK) * 2 + g * 16; \
            asm volatile("cp.async.ca.shared.global [%0], [%1], 16;" :: "r"(d), "l"(s)); \
        }                                                                           \
        asm volatile("cp.async.commit_group;" ::: "memory");                        \
    }

    float acc[4][4][4];
#pragma unroll
    for (int i = 0; i < 4; i++)
#pragma unroll
        for (int j = 0; j < 4; j++)
#pragma unroll
            for (int r = 0; r < 4; r++) acc[i][j][r] = 0.0f;

    int nk = K / GBK;
    LOAD_STAGE(0, 0);

    for (int kc = 0; kc < nk; kc++) {
        int buf = kc & 1;
        if (kc + 1 < nk) {
            LOAD_STAGE(kc + 1, buf ^ 1);
            asm volatile("cp.async.wait_group 1;" ::: "memory");
        } else {
            asm volatile("cp.async.wait_group 0;" ::: "memory");
        }
        __syncthreads();

        uint32_t bAh = sb + buf * GSTG;
        uint32_t bAl = bAh + GTILE;
        uint32_t bBh = bAh + 2 * GTILE;
        uint32_t bBl = bAh + 3 * GTILE;

        // per-lane ldmatrix offsets
        uint32_t aoff = (uint32_t)(wm * 64 + (lane & 15)) * 80 + (lane >> 4) * 16;
        uint32_t boff = (uint32_t)(wn * 32 + (lane & 7)) * 80 + ((lane >> 3) & 1) * 16;

#pragma unroll
        for (int ks = 0; ks < 2; ks++) {
            uint32_t ko = ks * 32;
            uint32_t ah[4][4], al[4][4];
#pragma unroll
            for (int mt = 0; mt < 4; mt++) {
                uint32_t addr = bAh + aoff + ko + mt * (16 * 80);
                asm volatile("ldmatrix.sync.aligned.m8n8.x4.shared.b16 {%0,%1,%2,%3}, [%4];"
                    : "=r"(ah[mt][0]), "=r"(ah[mt][1]), "=r"(ah[mt][2]), "=r"(ah[mt][3])
                    : "r"(addr));
                addr = bAl + aoff + ko + mt * (16 * 80);
                asm volatile("ldmatrix.sync.aligned.m8n8.x4.shared.b16 {%0,%1,%2,%3}, [%4];"
                    : "=r"(al[mt][0]), "=r"(al[mt][1]), "=r"(al[mt][2]), "=r"(al[mt][3])
                    : "r"(addr));
            }
            uint32_t bh[4][2], bl[4][2];
#pragma unroll
            for (int nt = 0; nt < 4; nt++) {
                uint32_t addr = bBh + boff + ko + nt * (8 * 80);
                asm volatile("ldmatrix.sync.aligned.m8n8.x2.shared.b16 {%0,%1}, [%2];"
                    : "=r"(bh[nt][0]), "=r"(bh[nt][1]) : "r"(addr));
                addr = bBl + boff + ko + nt * (8 * 80);
                asm volatile("ldmatrix.sync.aligned.m8n8.x2.shared.b16 {%0,%1}, [%2];"
                    : "=r"(bl[nt][0]), "=r"(bl[nt][1]) : "r"(addr));
            }
#pragma unroll
            for (int mt = 0; mt < 4; mt++)
#pragma unroll
                for (int nt = 0; nt < 4; nt++) {
                    asm volatile(
                        "mma.sync.aligned.m16n8k16.row.col.f32.bf16.bf16.f32 "
                        "{%0,%1,%2,%3}, {%4,%5,%6,%7}, {%8,%9}, {%0,%1,%2,%3};"
                        : "+f"(acc[mt][nt][0]), "+f"(acc[mt][nt][1]),
                          "+f"(acc[mt][nt][2]), "+f"(acc[mt][nt][3])
                        : "r"(ah[mt][0]), "r"(ah[mt][1]), "r"(ah[mt][2]), "r"(ah[mt][3]),
                          "r"(bh[nt][0]), "r"(bh[nt][1]));
                    asm volatile(
                        "mma.sync.aligned.m16n8k16.row.col.f32.bf16.bf16.f32 "
                        "{%0,%1,%2,%3}, {%4,%5,%6,%7}, {%8,%9}, {%0,%1,%2,%3};"
                        : "+f"(acc[mt][nt][0]), "+f"(acc[mt][nt][1]),
                          "+f"(acc[mt][nt][2]), "+f"(acc[mt][nt][3])
                        : "r"(al[mt][0]), "r"(al[mt][1]), "r"(al[mt][2]), "r"(al[mt][3]),
                          "r"(bh[nt][0]), "r"(bh[nt][1]));
                    asm volatile(
                        "mma.sync.aligned.m16n8k16.row.col.f32.bf16.bf16.f32 "
                        "{%0,%1,%2,%3}, {%4,%5,%6,%7}, {%8,%9}, {%0,%1,%2,%3};"
                        : "+f"(acc[mt][nt][0]), "+f"(acc[mt][nt][1]),
                          "+f"(acc[mt][nt][2]), "+f"(acc[mt][nt][3])
                        : "r"(ah[mt][0]), "r"(ah[mt][1]), "r"(ah[mt][2]), "r"(ah[mt][3]),
                          "r"(bl[nt][0]), "r"(bl[nt][1]));
                }
        }
        __syncthreads();
    }

    // epilogue
#pragma unroll
    for (int mt = 0; mt < 4; mt++) {
        int r0 = m0 + wm * 64 + mt * 16 + gid;
#pragma unroll
        for (int nt = 0; nt < 4; nt++) {
            int cl = wn * 32 + nt * 8 + 2 * tg;
            float b0 = shb[cl], b1 = shb[cl + 1];
            *(float2*)(C + (size_t)r0 * N + n0 + cl) =
                make_float2(acc[mt][nt][0] + b0, acc[mt][nt][1] + b1);
            *(float2*)(C + (size_t)(r0 + 8) * N + n0 + cl) =
                make_float2(acc[mt][nt][2] + b0, acc[mt][nt][3] + b1);
        }
    }
}

// ---------------- persistent LSTM layer kernel (unchanged, known-good) ----------------
#define PK_SMEM ((4 * 16 * 512 + 32 * 516) * 4)   // 197120 B

__global__ __launch_bounds__(256) void lstm_layer(
    const float* __restrict__ gates_f,
    const float* __restrict__ gates_r,
    const float* __restrict__ Whh_f,
    const float* __restrict__ Whh_r,
    float* __restrict__ state,
    float* __restrict__ outbuf,
    int out_mode)
{
    extern __shared__ float smemf[];
    float4* sh_w4 = (float4*)smemf;
    float*  sh_h  = smemf + 4 * 16 * 512;

    int tid = threadIdx.x;
    int bx  = blockIdx.x;
    int dir = bx >> 6;
    int hs  = (bx >> 1) & 31;
    int bs  = bx & 1;
    int u0  = hs * 16;
    int b0  = bs * 32;

    const float* gates = dir ? gates_r : gates_f;
    const float* Whh   = dir ? Whh_r : Whh_f;
    float* sbase = state + dir * 2 * (BB * HH);

#pragma unroll
    for (int j = 0; j < 32; j++) {
        int idx = tid + j * 256;
        int u   = idx & 15;
        int k4  = (idx >> 4) & 127;
        int g   = idx >> 11;
        sh_w4[idx] = *(const float4*)(Whh + (size_t)(g * HH + u0 + u) * HH + k4 * 4);
    }

    int tu  = tid & 15;
    int tbg = tid >> 4;
    int bA  = b0 + tbg;
    int bB  = b0 + tbg + 16;
    int u   = u0 + tu;

    float cA = 0.0f, cB = 0.0f;

    for (int s = 0; s < LL; s++) {
        int t   = dir ? (LL - 1 - s) : s;
        int par = s & 1;
        const float* h_in  = sbase + par * (BB * HH);
        float*       h_out = sbase + (par ^ 1) * (BB * HH);

        __syncthreads();
#pragma unroll
        for (int j = 0; j < 16; j++) {
            int idx = tid + j * 256;
            int b   = idx >> 7;
            int k4  = idx & 127;
            float4 v = __ldcg((const float4*)(h_in + (size_t)(b0 + b) * HH) + k4);
            *(float4*)&sh_h[b * 516 + k4 * 4] = v;
        }
        __syncthreads();

        float acc[4][2];
#pragma unroll
        for (int g = 0; g < 4; g++) { acc[g][0] = 0.0f; acc[g][1] = 0.0f; }

        const float* hrowA = sh_h + tbg * 516;
        const float* hrowB = sh_h + (tbg + 16) * 516;
#pragma unroll 4
        for (int k4 = 0; k4 < 128; k4++) {
            float4 h0 = *(const float4*)(hrowA + k4 * 4);
            float4 h1 = *(const float4*)(hrowB + k4 * 4);
#pragma unroll
            for (int g = 0; g < 4; g++) {
                float4 w = sh_w4[(g * 128 + k4) * 16 + tu];
                acc[g][0] += w.x * h0.x + w.y * h0.y + w.z * h0.z + w.w * h0.w;
                acc[g][1] += w.x * h1.x + w.y * h1.y + w.z * h1.z + w.w * h1.w;
            }
        }

        size_t gbA = ((size_t)t * BB + bA) * G4 + u;
        size_t gbB = ((size_t)t * BB + bB) * G4 + u;
        {
            float gi = gates[gbA + 0 * HH] + acc[0][0];
            float gf = gates[gbA + 1 * HH] + acc[1][0];
            float gg = gates[gbA + 2 * HH] + acc[2][0];
            float go = gates[gbA + 3 * HH] + acc[3][0];
            float si = 1.0f / (1.0f + expf(-gi));
            float sf = 1.0f / (1.0f + expf(-gf));
            float so = 1.0f / (1.0f + expf(-go));
            cA = sf * cA + si * tanhf(gg);
            float h2 = so * tanhf(cA);
            __stcg(&h_out[bA * HH + u], h2);
            size_t orow = out_mode ? ((size_t)bA * LL + t) : ((size_t)t * BB + bA);
            outbuf[orow * (2 * HH) + dir * HH + u] = h2;
        }
        {
            float gi = gates[gbB + 0 * HH] + acc[0][1];
            float gf = gates[gbB + 1 * HH] + acc[1][1];
            float gg = gates[gbB + 2 * HH] + acc[2][1];
            float go = gates[gbB + 3 * HH] + acc[3][1];
            float si = 1.0f / (1.0f + expf(-gi));
            float sf = 1.0f / (1.0f + expf(-gf));
            float so = 1.0f / (1.0f + expf(-go));
            cB = sf * cB + si * tanhf(gg);
            float h2 = so * tanhf(cB);
            __stcg(&h_out[bB * HH + u], h2);
            size_t orow = out_mode ? ((size_t)bB * LL + t) : ((size_t)t * BB + bB);
            outbuf[orow * (2 * HH) + dir * HH + u] = h2;
        }

        __threadfence();
        __syncthreads();
        if (tid == 0) {
            atomicAdd(&g_bar, 1u);
            unsigned target = (unsigned)(s + 1) * gridDim.x;
            while (*(volatile unsigned*)&g_bar < target) { }
        }
        __syncthreads();
    }
}

// ---------------- host launcher ----------------
extern "C" void kernel_launch(void* const* d_in, const int* in_sizes, int n_in,
                              void* d_out, int out_size)
{
    const float* x       = (const float*)d_in[0];
    const float* Wih_f0  = (const float*)d_in[1];
    const float* Whh_f0  = (const float*)d_in[2];
    const float* bih_f0  = (const float*)d_in[3];
    const float* bhh_f0  = (const float*)d_in[4];
    const float* Wih_r0  = (const float*)d_in[5];
    const float* Whh_r0  = (const float*)d_in[6];
    const float* bih_r0  = (const float*)d_in[7];
    const float* bhh_r0  = (const float*)d_in[8];
    const float* Wih_f1  = (const float*)d_in[9];
    const float* Whh_f1  = (const float*)d_in[10];
    const float* bih_f1  = (const float*)d_in[11];
    const float* bhh_f1  = (const float*)d_in[12];
    const float* Wih_r1  = (const float*)d_in[13];
    const float* Whh_r1  = (const float*)d_in[14];
    const float* bih_r1  = (const float*)d_in[15];
    const float* bhh_r1  = (const float*)d_in[16];

    float *xT, *gf, *gr, *hcat, *state;
    unsigned* bar;
    __nv_bfloat16 *Ahi, *Alo, *Wfhi, *Wflo, *Wrhi, *Wrlo;
    cudaGetSymbolAddress((void**)&xT,    g_xT);
    cudaGetSymbolAddress((void**)&gf,    g_gates_f);
    cudaGetSymbolAddress((void**)&gr,    g_gates_r);
    cudaGetSymbolAddress((void**)&hcat,  g_hcat);
    cudaGetSymbolAddress((void**)&state, g_state);
    cudaGetSymbolAddress((void**)&bar,   g_bar);
    cudaGetSymbolAddress((void**)&Ahi,   g_Ahi);
    cudaGetSymbolAddress((void**)&Alo,   g_Alo);
    cudaGetSymbolAddress((void**)&Wfhi,  g_Wfhi);
    cudaGetSymbolAddress((void**)&Wflo,  g_Wflo);
    cudaGetSymbolAddress((void**)&Wrhi,  g_Wrhi);
    cudaGetSymbolAddress((void**)&Wrlo,  g_Wrlo);

    cudaFuncSetAttribute(lstm_layer, cudaFuncAttributeMaxDynamicSharedMemorySize, PK_SMEM);
    cudaFuncSetAttribute(gemm_bf16s, cudaFuncAttributeMaxDynamicSharedMemorySize, GB_SMEM);

    const int M = LL * BB;   // 32768

    transpose_x<<<8192, 256>>>((const float4*)x, (float4*)xT);

    dim3 ggrid(G4 / 128, M / 128);   // (16, 256)

    // ---- layer 0 (K = 256) ----
    {
        int n4 = (LL * BB * II) / 4;
        split_bf16<<<(n4 + 255) / 256, 256>>>((const float4*)xT,
            (__nv_bfloat162*)Ahi, (__nv_bfloat162*)Alo, n4);
        int w4 = (G4 * II) / 4;
        split_bf16<<<(w4 + 255) / 256, 256>>>((const float4*)Wih_f0,
            (__nv_bfloat162*)Wfhi, (__nv_bfloat162*)Wflo, w4);
        split_bf16<<<(w4 + 255) / 256, 256>>>((const float4*)Wih_r0,
            (__nv_bfloat162*)Wrhi, (__nv_bfloat162*)Wrlo, w4);
        gemm_bf16s<<<ggrid, 256, GB_SMEM>>>(M, G4, II, Ahi, Alo, Wfhi, Wflo, bih_f0, bhh_f0, gf);
        gemm_bf16s<<<ggrid, 256, GB_SMEM>>>(M, G4, II, Ahi, Alo, Wrhi, Wrlo, bih_r0, bhh_r0, gr);
    }
    cudaMemsetAsync(state, 0, sizeof(float) * 2 * 2 * BB * HH, 0);
    cudaMemsetAsync(bar,   0, sizeof(unsigned), 0);
    lstm_layer<<<128, 256, PK_SMEM>>>(gf, gr, Whh_f0, Whh_r0, state, hcat, 0);

    // ---- layer 1 (K = 1024) ----
    {
        int n4 = (LL * BB * 2 * HH) / 4;
        split_bf16<<<(n4 + 255) / 256, 256>>>((const float4*)hcat,
            (__nv_bfloat162*)Ahi, (__nv_bfloat162*)Alo, n4);
        int w4 = (G4 * 2 * HH) / 4;
        split_bf16<<<(w4 + 255) / 256, 256>>>((const float4*)Wih_f1,
            (__nv_bfloat162*)Wfhi, (__nv_bfloat162*)Wflo, w4);
        split_bf16<<<(w4 + 255) / 256, 256>>>((const float4*)Wih_r1,
            (__nv_bfloat162*)Wrhi, (__nv_bfloat162*)Wrlo, w4);
        gemm_bf16s<<<ggrid, 256, GB_SMEM>>>(M, G4, 2 * HH, Ahi, Alo, Wfhi, Wflo, bih_f1, bhh_f1, gf);
        gemm_bf16s<<<ggrid, 256, GB_SMEM>>>(M, G4, 2 * HH, Ahi, Alo, Wrhi, Wrlo, bih_r1, bhh_r1, gr);
    }
    cudaMemsetAsync(state, 0, sizeof(float) * 2 * 2 * BB * HH, 0);
    cudaMemsetAsync(bar,   0, sizeof(unsigned), 0);
    lstm_layer<<<128, 256, PK_SMEM>>>(gf, gr, Whh_f1, Whh_r1, state, (float*)d_out, 1);
}

// round 7
// speedup vs baseline: 2.1907x; 1.7673x over previous
#include <cuda_runtime.h>
#include <cuda_bf16.h>
#include <math.h>
#include <cstdint>

// Problem dims
#define LL 512
#define BB 64
#define II 256
#define HH 512
#define G4 2048   // 4*H

// ---------------- scratch (static device globals; no allocation) ----------------
__device__ float g_xT[(size_t)LL * BB * II];          // [t][b][I]
__device__ float g_gates_f[(size_t)LL * BB * G4];     // [t][b][4H]
__device__ float g_gates_r[(size_t)LL * BB * G4];     // [t][b][4H]
__device__ float g_hcat[(size_t)LL * BB * 2 * HH];    // [t][b][2H]
__device__ unsigned g_bar;                            // global barrier counter

// h state as bf16 hi/lo: [dir][parity][b][u]  (16B-aligned: accessed as uint4)
__device__ __align__(16) __nv_bfloat16 g_shi[2 * 2 * BB * HH];
__device__ __align__(16) __nv_bfloat16 g_slo[2 * 2 * BB * HH];

// bf16 split buffers (input GEMM operands)
__device__ __align__(16) __nv_bfloat16 g_Ahi[(size_t)LL * BB * 2 * HH];
__device__ __align__(16) __nv_bfloat16 g_Alo[(size_t)LL * BB * 2 * HH];
__device__ __align__(16) __nv_bfloat16 g_Wfhi[(size_t)G4 * 2 * HH];
__device__ __align__(16) __nv_bfloat16 g_Wflo[(size_t)G4 * 2 * HH];
__device__ __align__(16) __nv_bfloat16 g_Wrhi[(size_t)G4 * 2 * HH];
__device__ __align__(16) __nv_bfloat16 g_Wrlo[(size_t)G4 * 2 * HH];
// Whh splits for the recurrence ([2048][512] each)
__device__ __align__(16) __nv_bfloat16 g_WhfHi[(size_t)G4 * HH];
__device__ __align__(16) __nv_bfloat16 g_WhfLo[(size_t)G4 * HH];
__device__ __align__(16) __nv_bfloat16 g_WhrHi[(size_t)G4 * HH];
__device__ __align__(16) __nv_bfloat16 g_WhrLo[(size_t)G4 * HH];

__device__ __forceinline__ uint32_t smem_u32(const void* p) {
    uint32_t a;
    asm("{ .reg .u64 t; cvta.to.shared.u64 t, %1; cvt.u32.u64 %0, t; }" : "=r"(a) : "l"(p));
    return a;
}

// ---------------- transpose x[b][l][i] -> xT[l][b][i] ----------------
__global__ void transpose_x(const float4* __restrict__ x, float4* __restrict__ xT) {
    int idx = blockIdx.x * blockDim.x + threadIdx.x;
    int i4 = idx & 63;
    int m  = idx >> 6;
    int t  = m >> 6;
    int b  = m & 63;
    xT[idx] = x[((size_t)(b * LL + t)) * 64 + i4];
}

// ---------------- fp32 -> bf16 hi/lo split ----------------
__global__ void split_bf16(const float4* __restrict__ src,
                           __nv_bfloat162* __restrict__ hi,
                           __nv_bfloat162* __restrict__ lo, int n4) {
    int i = blockIdx.x * blockDim.x + threadIdx.x;
    if (i >= n4) return;
    float4 v = src[i];
    __nv_bfloat16 hx = __float2bfloat16(v.x);
    __nv_bfloat16 hy = __float2bfloat16(v.y);
    __nv_bfloat16 hz = __float2bfloat16(v.z);
    __nv_bfloat16 hw = __float2bfloat16(v.w);
    __nv_bfloat16 lx = __float2bfloat16(v.x - __bfloat162float(hx));
    __nv_bfloat16 ly = __float2bfloat16(v.y - __bfloat162float(hy));
    __nv_bfloat16 lz = __float2bfloat16(v.z - __bfloat162float(hz));
    __nv_bfloat16 lw = __float2bfloat16(v.w - __bfloat162float(hw));
    hi[i * 2 + 0] = __nv_bfloat162(hx, hy);
    hi[i * 2 + 1] = __nv_bfloat162(hz, hw);
    lo[i * 2 + 0] = __nv_bfloat162(lx, ly);
    lo[i * 2 + 1] = __nv_bfloat162(lz, lw);
}

// ---------------- bf16 split-GEMM on HMMA (unchanged, known-good) ----------------
#define GBK   32
#define GTILE 10240
#define GSTG  (4 * GTILE)
#define GB_SMEM (2 * GSTG + 512)

__global__ __launch_bounds__(256, 1) void gemm_bf16s(
    int M, int N, int K,
    const __nv_bfloat16* __restrict__ Ahi, const __nv_bfloat16* __restrict__ Alo,
    const __nv_bfloat16* __restrict__ Bhi, const __nv_bfloat16* __restrict__ Blo,
    const float* __restrict__ bias1, const float* __restrict__ bias2,
    float* __restrict__ C)
{
    extern __shared__ char sm[];
    uint32_t sb = smem_u32(sm);
    int tid  = threadIdx.x;
    int lane = tid & 31;
    int warp = tid >> 5;
    int gid  = lane >> 2;
    int tg   = lane & 3;
    int wm   = warp >> 2;
    int wn   = warp & 3;
    int n0   = blockIdx.x * 128;
    int m0   = blockIdx.y * 128;

    float* shb = (float*)(sm + 2 * GSTG);
    if (tid < 128) shb[tid] = bias1[n0 + tid] + bias2[n0 + tid];

    const char* srcs[4];
    srcs[0] = (const char*)(Ahi + (size_t)m0 * K);
    srcs[1] = (const char*)(Alo + (size_t)m0 * K);
    srcs[2] = (const char*)(Bhi + (size_t)n0 * K);
    srcs[3] = (const char*)(Blo + (size_t)n0 * K);

#define LOAD_STAGE(kc, bufsel)                                                      \
    {                                                                               \
        _Pragma("unroll")                                                           \
        for (int j = 0; j < 8; j++) {                                               \
            int c    = tid + j * 256;                                               \
            int tile = c >> 9;                                                      \
            int cc   = c & 511;                                                     \
            int row  = cc >> 2, g = cc & 3;                                         \
            uint32_t d = sb + (bufsel) * GSTG + tile * GTILE + row * 80 + g * 16;   \
            const char* s = srcs[tile] + ((size_t)row * K + (kc) * GBK) * 2 + g * 16; \
            asm volatile("cp.async.ca.shared.global [%0], [%1], 16;" :: "r"(d), "l"(s)); \
        }                                                                           \
        asm volatile("cp.async.commit_group;" ::: "memory");                        \
    }

    float acc[4][4][4];
#pragma unroll
    for (int i = 0; i < 4; i++)
#pragma unroll
        for (int j = 0; j < 4; j++)
#pragma unroll
            for (int r = 0; r < 4; r++) acc[i][j][r] = 0.0f;

    int nk = K / GBK;
    LOAD_STAGE(0, 0);

    for (int kc = 0; kc < nk; kc++) {
        int buf = kc & 1;
        if (kc + 1 < nk) {
            LOAD_STAGE(kc + 1, buf ^ 1);
            asm volatile("cp.async.wait_group 1;" ::: "memory");
        } else {
            asm volatile("cp.async.wait_group 0;" ::: "memory");
        }
        __syncthreads();

        uint32_t bAh = sb + buf * GSTG;
        uint32_t bAl = bAh + GTILE;
        uint32_t bBh = bAh + 2 * GTILE;
        uint32_t bBl = bAh + 3 * GTILE;

        uint32_t aoff = (uint32_t)(wm * 64 + (lane & 15)) * 80 + (lane >> 4) * 16;
        uint32_t boff = (uint32_t)(wn * 32 + (lane & 7)) * 80 + ((lane >> 3) & 1) * 16;

#pragma unroll
        for (int ks = 0; ks < 2; ks++) {
            uint32_t ko = ks * 32;
            uint32_t ah[4][4], al[4][4];
#pragma unroll
            for (int mt = 0; mt < 4; mt++) {
                uint32_t addr = bAh + aoff + ko + mt * (16 * 80);
                asm volatile("ldmatrix.sync.aligned.m8n8.x4.shared.b16 {%0,%1,%2,%3}, [%4];"
                    : "=r"(ah[mt][0]), "=r"(ah[mt][1]), "=r"(ah[mt][2]), "=r"(ah[mt][3])
                    : "r"(addr));
                addr = bAl + aoff + ko + mt * (16 * 80);
                asm volatile("ldmatrix.sync.aligned.m8n8.x4.shared.b16 {%0,%1,%2,%3}, [%4];"
                    : "=r"(al[mt][0]), "=r"(al[mt][1]), "=r"(al[mt][2]), "=r"(al[mt][3])
                    : "r"(addr));
            }
            uint32_t bh[4][2], bl[4][2];
#pragma unroll
            for (int nt = 0; nt < 4; nt++) {
                uint32_t addr = bBh + boff + ko + nt * (8 * 80);
                asm volatile("ldmatrix.sync.aligned.m8n8.x2.shared.b16 {%0,%1}, [%2];"
                    : "=r"(bh[nt][0]), "=r"(bh[nt][1]) : "r"(addr));
                addr = bBl + boff + ko + nt * (8 * 80);
                asm volatile("ldmatrix.sync.aligned.m8n8.x2.shared.b16 {%0,%1}, [%2];"
                    : "=r"(bl[nt][0]), "=r"(bl[nt][1]) : "r"(addr));
            }
#pragma unroll
            for (int mt = 0; mt < 4; mt++)
#pragma unroll
                for (int nt = 0; nt < 4; nt++) {
                    asm volatile(
                        "mma.sync.aligned.m16n8k16.row.col.f32.bf16.bf16.f32 "
                        "{%0,%1,%2,%3}, {%4,%5,%6,%7}, {%8,%9}, {%0,%1,%2,%3};"
                        : "+f"(acc[mt][nt][0]), "+f"(acc[mt][nt][1]),
                          "+f"(acc[mt][nt][2]), "+f"(acc[mt][nt][3])
                        : "r"(ah[mt][0]), "r"(ah[mt][1]), "r"(ah[mt][2]), "r"(ah[mt][3]),
                          "r"(bh[nt][0]), "r"(bh[nt][1]));
                    asm volatile(
                        "mma.sync.aligned.m16n8k16.row.col.f32.bf16.bf16.f32 "
                        "{%0,%1,%2,%3}, {%4,%5,%6,%7}, {%8,%9}, {%0,%1,%2,%3};"
                        : "+f"(acc[mt][nt][0]), "+f"(acc[mt][nt][1]),
                          "+f"(acc[mt][nt][2]), "+f"(acc[mt][nt][3])
                        : "r"(al[mt][0]), "r"(al[mt][1]), "r"(al[mt][2]), "r"(al[mt][3]),
                          "r"(bh[nt][0]), "r"(bh[nt][1]));
                    asm volatile(
                        "mma.sync.aligned.m16n8k16.row.col.f32.bf16.bf16.f32 "
                        "{%0,%1,%2,%3}, {%4,%5,%6,%7}, {%8,%9}, {%0,%1,%2,%3};"
                        : "+f"(acc[mt][nt][0]), "+f"(acc[mt][nt][1]),
                          "+f"(acc[mt][nt][2]), "+f"(acc[mt][nt][3])
                        : "r"(ah[mt][0]), "r"(ah[mt][1]), "r"(ah[mt][2]), "r"(ah[mt][3]),
                          "r"(bl[nt][0]), "r"(bl[nt][1]));
                }
        }
        __syncthreads();
    }

#pragma unroll
    for (int mt = 0; mt < 4; mt++) {
        int r0 = m0 + wm * 64 + mt * 16 + gid;
#pragma unroll
        for (int nt = 0; nt < 4; nt++) {
            int cl = wn * 32 + nt * 8 + 2 * tg;
            float b0 = shb[cl], b1 = shb[cl + 1];
            *(float2*)(C + (size_t)r0 * N + n0 + cl) =
                make_float2(acc[mt][nt][0] + b0, acc[mt][nt][1] + b1);
            *(float2*)(C + (size_t)(r0 + 8) * N + n0 + cl) =
                make_float2(acc[mt][nt][2] + b0, acc[mt][nt][3] + b1);
        }
    }
}

// ---------------- persistent tensor-core LSTM layer ----------------
// Grid 128 = dir(2) x us(32: 16 units) x bs(2: 32 batches). 256 threads, 8 warps.
// Per step: gates[64 rows(4g x 16u), 32 b] = Whh_slice[64,512] @ h[32,512]^T,
// bf16 hi/lo 3-term split on HMMA. Whh slice staged once; h read split from gmem.
// 8 warps = 2m x 2n x 2k-split; k-partials via two smem gate buffers (scalar
// stores: pitch 33 is odd, float2 would trap on odd rows). Cell state in regs.
#define RP     1040                   // smem row pitch bytes (512 bf16 + pad)
#define OFF_AHI 0
#define OFF_ALO (64 * RP)
#define OFF_BHI (2 * 64 * RP)
#define OFF_BLO (2 * 64 * RP + 32 * RP)
#define OFF_G0  (2 * 64 * RP + 2 * 32 * RP)
#define OFF_G1  (OFF_G0 + 64 * 33 * 4)
#define RK_SMEM (OFF_G1 + 64 * 33 * 4)   // 216576

__global__ __launch_bounds__(256, 1) void lstm_layer_tc(
    const float* __restrict__ gates_f,
    const float* __restrict__ gates_r,
    const __nv_bfloat16* __restrict__ WhfHi, const __nv_bfloat16* __restrict__ WhfLo,
    const __nv_bfloat16* __restrict__ WhrHi, const __nv_bfloat16* __restrict__ WhrLo,
    __nv_bfloat16* __restrict__ shi,
    __nv_bfloat16* __restrict__ slo,
    float* __restrict__ outbuf,
    int out_mode)
{
    extern __shared__ char sm[];
    uint32_t sb = smem_u32(sm);
    int tid  = threadIdx.x;
    int lane = tid & 31;
    int warp = tid >> 5;
    int gid  = lane >> 2;
    int tg   = lane & 3;

    int bx  = blockIdx.x;
    int dir = bx >> 6;
    int us  = (bx >> 1) & 31;
    int bs  = bx & 1;
    int u0  = us * 16;
    int b0  = bs * 32;

    const float* gates = dir ? gates_r : gates_f;
    const __nv_bfloat16* whH = dir ? WhrHi : WhfHi;
    const __nv_bfloat16* whL = dir ? WhrLo : WhfLo;

    // ---- stage Whh slice once: 64 rows (g*16+ul) x 512 bf16, hi & lo ----
#pragma unroll
    for (int j = 0; j < 16; j++) {
        int idx = tid + j * 256;        // 0..4095
        int row = idx >> 6;             // 0..63
        int ch  = idx & 63;             // 16B chunk
        int g   = row >> 4;
        int ul  = row & 15;
        size_t soff = (size_t)(g * HH + u0 + ul) * HH + ch * 8;
        *(uint4*)(sm + OFF_AHI + row * RP + ch * 16) = *(const uint4*)(whH + soff);
        *(uint4*)(sm + OFF_ALO + row * RP + ch * 16) = *(const uint4*)(whL + soff);
    }

    // warp decomposition: 2m x 2n x 2k
    int wk = warp >> 2;
    int wm = (warp >> 1) & 1;
    int wn = warp & 1;
    uint32_t apat = (uint32_t)(lane & 15) * RP + (lane >> 4) * 16;
    uint32_t bpat = (uint32_t)((lane & 7) + ((lane >> 4) << 3)) * RP + ((lane >> 3) & 1) * 16;
    uint32_t aBaseHi = sb + OFF_AHI + wm * 32 * RP + apat;
    uint32_t aBaseLo = sb + OFF_ALO + wm * 32 * RP + apat;
    uint32_t bBaseHi = sb + OFF_BHI + wn * 16 * RP + bpat;
    uint32_t bBaseLo = sb + OFF_BLO + wn * 16 * RP + bpat;
    float* gbuf = (float*)(sm + (wk ? OFF_G1 : OFF_G0));
    float* g0f  = (float*)(sm + OFF_G0);
    float* g1f  = (float*)(sm + OFF_G1);

    // epilogue ownership: pairs q = tid, tid+256 -> (ul = q>>5, b = q&31)
    float cst[2] = {0.0f, 0.0f};

    for (int s = 0; s < LL; s++) {
        int t   = dir ? (LL - 1 - s) : s;
        int par = s & 1;
        const __nv_bfloat16* hinH = shi + ((dir * 2 + par) * BB) * HH;
        const __nv_bfloat16* hinL = slo + ((dir * 2 + par) * BB) * HH;
        __nv_bfloat16* houtH = shi + ((dir * 2 + (par ^ 1)) * BB) * HH;
        __nv_bfloat16* houtL = slo + ((dir * 2 + (par ^ 1)) * BB) * HH;

        // ---- stage h tile (32 b x 512) hi/lo ----
#pragma unroll
        for (int j = 0; j < 8; j++) {
            int idx = tid + j * 256;     // 0..2047
            int row = idx >> 6;          // 0..31
            int ch  = idx & 63;
            size_t soff = (size_t)(b0 + row) * HH + ch * 8;
            uint4 vh = __ldcg((const uint4*)(hinH + soff));
            uint4 vl = __ldcg((const uint4*)(hinL + soff));
            *(uint4*)(sm + OFF_BHI + row * RP + ch * 16) = vh;
            *(uint4*)(sm + OFF_BLO + row * RP + ch * 16) = vl;
        }
        __syncthreads();

        // ---- 3-term HMMA over this warp's 16 k-chunks ----
        float t0[2][2][4], t1[2][2][4], t2[2][2][4];
#pragma unroll
        for (int i = 0; i < 2; i++)
#pragma unroll
            for (int j = 0; j < 2; j++)
#pragma unroll
                for (int r = 0; r < 4; r++) { t0[i][j][r] = 0.f; t1[i][j][r] = 0.f; t2[i][j][r] = 0.f; }

#pragma unroll 4
        for (int kc = 0; kc < 16; kc++) {
            uint32_t kb = (uint32_t)(wk * 16 + kc) * 32;   // bytes into k
            uint32_t ah[2][4], al[2][4];
#pragma unroll
            for (int mt = 0; mt < 2; mt++) {
                asm volatile("ldmatrix.sync.aligned.m8n8.x4.shared.b16 {%0,%1,%2,%3}, [%4];"
                    : "=r"(ah[mt][0]), "=r"(ah[mt][1]), "=r"(ah[mt][2]), "=r"(ah[mt][3])
                    : "r"(aBaseHi + kb + mt * (16 * RP)));
                asm volatile("ldmatrix.sync.aligned.m8n8.x4.shared.b16 {%0,%1,%2,%3}, [%4];"
                    : "=r"(al[mt][0]), "=r"(al[mt][1]), "=r"(al[mt][2]), "=r"(al[mt][3])
                    : "r"(aBaseLo + kb + mt * (16 * RP)));
            }
            uint32_t bh[4], bl[4];
            asm volatile("ldmatrix.sync.aligned.m8n8.x4.shared.b16 {%0,%1,%2,%3}, [%4];"
                : "=r"(bh[0]), "=r"(bh[1]), "=r"(bh[2]), "=r"(bh[3]) : "r"(bBaseHi + kb));
            asm volatile("ldmatrix.sync.aligned.m8n8.x4.shared.b16 {%0,%1,%2,%3}, [%4];"
                : "=r"(bl[0]), "=r"(bl[1]), "=r"(bl[2]), "=r"(bl[3]) : "r"(bBaseLo + kb));
#pragma unroll
            for (int mt = 0; mt < 2; mt++)
#pragma unroll
                for (int nf = 0; nf < 2; nf++) {
                    asm volatile(
                        "mma.sync.aligned.m16n8k16.row.col.f32.bf16.bf16.f32 "
                        "{%0,%1,%2,%3}, {%4,%5,%6,%7}, {%8,%9}, {%0,%1,%2,%3};"
                        : "+f"(t0[mt][nf][0]), "+f"(t0[mt][nf][1]),
                          "+f"(t0[mt][nf][2]), "+f"(t0[mt][nf][3])
                        : "r"(ah[mt][0]), "r"(ah[mt][1]), "r"(ah[mt][2]), "r"(ah[mt][3]),
                          "r"(bh[nf * 2]), "r"(bh[nf * 2 + 1]));
                    asm volatile(
                        "mma.sync.aligned.m16n8k16.row.col.f32.bf16.bf16.f32 "
                        "{%0,%1,%2,%3}, {%4,%5,%6,%7}, {%8,%9}, {%0,%1,%2,%3};"
                        : "+f"(t1[mt][nf][0]), "+f"(t1[mt][nf][1]),
                          "+f"(t1[mt][nf][2]), "+f"(t1[mt][nf][3])
                        : "r"(al[mt][0]), "r"(al[mt][1]), "r"(al[mt][2]), "r"(al[mt][3]),
                          "r"(bh[nf * 2]), "r"(bh[nf * 2 + 1]));
                    asm volatile(
                        "mma.sync.aligned.m16n8k16.row.col.f32.bf16.bf16.f32 "
                        "{%0,%1,%2,%3}, {%4,%5,%6,%7}, {%8,%9}, {%0,%1,%2,%3};"
                        : "+f"(t2[mt][nf][0]), "+f"(t2[mt][nf][1]),
                          "+f"(t2[mt][nf][2]), "+f"(t2[mt][nf][3])
                        : "r"(ah[mt][0]), "r"(ah[mt][1]), "r"(ah[mt][2]), "r"(ah[mt][3]),
                          "r"(bl[nf * 2]), "r"(bl[nf * 2 + 1]));
                }
        }

        // ---- write k-partials to gate buffer (scalar stores; pitch 33 is odd) ----
#pragma unroll
        for (int mt = 0; mt < 2; mt++) {
            int r0 = wm * 32 + mt * 16 + gid;
#pragma unroll
            for (int nf = 0; nf < 2; nf++) {
                int cl = wn * 16 + nf * 8 + 2 * tg;
                gbuf[r0 * 33 + cl]           = t0[mt][nf][0] + t1[mt][nf][0] + t2[mt][nf][0];
                gbuf[r0 * 33 + cl + 1]       = t0[mt][nf][1] + t1[mt][nf][1] + t2[mt][nf][1];
                gbuf[(r0 + 8) * 33 + cl]     = t0[mt][nf][2] + t1[mt][nf][2] + t2[mt][nf][2];
                gbuf[(r0 + 8) * 33 + cl + 1] = t0[mt][nf][3] + t1[mt][nf][3] + t2[mt][nf][3];
            }
        }
        __syncthreads();

        // ---- epilogue: combine k-halves + input gates -> c/h update ----
#pragma unroll
        for (int q = 0; q < 2; q++) {
            int pr = tid + q * 256;
            int ul = pr >> 5;
            int b  = pr & 31;
            int bg = b0 + b;
            int ug = u0 + ul;
            size_t gbase = ((size_t)t * BB + bg) * G4 + ug;
            float gi = gates[gbase + 0 * HH] + g0f[(0 * 16 + ul) * 33 + b] + g1f[(0 * 16 + ul) * 33 + b];
            float gf = gates[gbase + 1 * HH] + g0f[(1 * 16 + ul) * 33 + b] + g1f[(1 * 16 + ul) * 33 + b];
            float gg = gates[gbase + 2 * HH] + g0f[(2 * 16 + ul) * 33 + b] + g1f[(2 * 16 + ul) * 33 + b];
            float go = gates[gbase + 3 * HH] + g0f[(3 * 16 + ul) * 33 + b] + g1f[(3 * 16 + ul) * 33 + b];
            float si = 1.0f / (1.0f + expf(-gi));
            float sf = 1.0f / (1.0f + expf(-gf));
            float so = 1.0f / (1.0f + expf(-go));
            cst[q] = sf * cst[q] + si * tanhf(gg);
            float h2 = so * tanhf(cst[q]);
            __nv_bfloat16 hh = __float2bfloat16(h2);
            __nv_bfloat16 hl = __float2bfloat16(h2 - __bfloat162float(hh));
            size_t hoff = (size_t)bg * HH + ug;
            __stcg(&houtH[hoff], hh);
            __stcg(&houtL[hoff], hl);
            size_t orow = out_mode ? ((size_t)bg * LL + t) : ((size_t)t * BB + bg);
            outbuf[orow * (2 * HH) + dir * HH + ug] = h2;
        }

        // ---- global barrier across 128 CTAs ----
        __threadfence();
        __syncthreads();
        if (tid == 0) {
            atomicAdd(&g_bar, 1u);
            unsigned target = (unsigned)(s + 1) * gridDim.x;
            while (*(volatile unsigned*)&g_bar < target) { }
        }
        __syncthreads();
    }
}

// ---------------- host launcher ----------------
extern "C" void kernel_launch(void* const* d_in, const int* in_sizes, int n_in,
                              void* d_out, int out_size)
{
    const float* x       = (const float*)d_in[0];
    const float* Wih_f0  = (const float*)d_in[1];
    const float* Whh_f0  = (const float*)d_in[2];
    const float* bih_f0  = (const float*)d_in[3];
    const float* bhh_f0  = (const float*)d_in[4];
    const float* Wih_r0  = (const float*)d_in[5];
    const float* Whh_r0  = (const float*)d_in[6];
    const float* bih_r0  = (const float*)d_in[7];
    const float* bhh_r0  = (const float*)d_in[8];
    const float* Wih_f1  = (const float*)d_in[9];
    const float* Whh_f1  = (const float*)d_in[10];
    const float* bih_f1  = (const float*)d_in[11];
    const float* bhh_f1  = (const float*)d_in[12];
    const float* Wih_r1  = (const float*)d_in[13];
    const float* Whh_r1  = (const float*)d_in[14];
    const float* bih_r1  = (const float*)d_in[15];
    const float* bhh_r1  = (const float*)d_in[16];

    float *xT, *gf, *gr, *hcat;
    unsigned* bar;
    __nv_bfloat16 *Ahi, *Alo, *Wfhi, *Wflo, *Wrhi, *Wrlo;
    __nv_bfloat16 *WhfHi, *WhfLo, *WhrHi, *WhrLo, *shi, *slo;
    cudaGetSymbolAddress((void**)&xT,    g_xT);
    cudaGetSymbolAddress((void**)&gf,    g_gates_f);
    cudaGetSymbolAddress((void**)&gr,    g_gates_r);
    cudaGetSymbolAddress((void**)&hcat,  g_hcat);
    cudaGetSymbolAddress((void**)&bar,   g_bar);
    cudaGetSymbolAddress((void**)&Ahi,   g_Ahi);
    cudaGetSymbolAddress((void**)&Alo,   g_Alo);
    cudaGetSymbolAddress((void**)&Wfhi,  g_Wfhi);
    cudaGetSymbolAddress((void**)&Wflo,  g_Wflo);
    cudaGetSymbolAddress((void**)&Wrhi,  g_Wrhi);
    cudaGetSymbolAddress((void**)&Wrlo,  g_Wrlo);
    cudaGetSymbolAddress((void**)&WhfHi, g_WhfHi);
    cudaGetSymbolAddress((void**)&WhfLo, g_WhfLo);
    cudaGetSymbolAddress((void**)&WhrHi, g_WhrHi);
    cudaGetSymbolAddress((void**)&WhrLo, g_WhrLo);
    cudaGetSymbolAddress((void**)&shi,   g_shi);
    cudaGetSymbolAddress((void**)&slo,   g_slo);

    cudaFuncSetAttribute(gemm_bf16s,    cudaFuncAttributeMaxDynamicSharedMemorySize, GB_SMEM);
    cudaFuncSetAttribute(lstm_layer_tc, cudaFuncAttributeMaxDynamicSharedMemorySize, RK_SMEM);

    const int M = LL * BB;   // 32768
    const int whn4 = (G4 * HH) / 4;

    transpose_x<<<8192, 256>>>((const float4*)x, (float4*)xT);

    dim3 ggrid(G4 / 128, M / 128);   // (16, 256)

    // ---- layer 0 (K = 256) ----
    {
        int n4 = (LL * BB * II) / 4;
        split_bf16<<<(n4 + 255) / 256, 256>>>((const float4*)xT,
            (__nv_bfloat162*)Ahi, (__nv_bfloat162*)Alo, n4);
        int w4 = (G4 * II) / 4;
        split_bf16<<<(w4 + 255) / 256, 256>>>((const float4*)Wih_f0,
            (__nv_bfloat162*)Wfhi, (__nv_bfloat162*)Wflo, w4);
        split_bf16<<<(w4 + 255) / 256, 256>>>((const float4*)Wih_r0,
            (__nv_bfloat162*)Wrhi, (__nv_bfloat162*)Wrlo, w4);
        gemm_bf16s<<<ggrid, 256, GB_SMEM>>>(M, G4, II, Ahi, Alo, Wfhi, Wflo, bih_f0, bhh_f0, gf);
        gemm_bf16s<<<ggrid, 256, GB_SMEM>>>(M, G4, II, Ahi, Alo, Wrhi, Wrlo, bih_r0, bhh_r0, gr);
        split_bf16<<<(whn4 + 255) / 256, 256>>>((const float4*)Whh_f0,
            (__nv_bfloat162*)WhfHi, (__nv_bfloat162*)WhfLo, whn4);
        split_bf16<<<(whn4 + 255) / 256, 256>>>((const float4*)Whh_r0,
            (__nv_bfloat162*)WhrHi, (__nv_bfloat162*)WhrLo, whn4);
    }
    cudaMemsetAsync(shi, 0, sizeof(__nv_bfloat16) * 2 * 2 * BB * HH, 0);
    cudaMemsetAsync(slo, 0, sizeof(__nv_bfloat16) * 2 * 2 * BB * HH, 0);
    cudaMemsetAsync(bar, 0, sizeof(unsigned), 0);
    lstm_layer_tc<<<128, 256, RK_SMEM>>>(gf, gr, WhfHi, WhfLo, WhrHi, WhrLo,
                                         shi, slo, hcat, 0);

    // ---- layer 1 (K = 1024) ----
    {
        int n4 = (LL * BB * 2 * HH) / 4;
        split_bf16<<<(n4 + 255) / 256, 256>>>((const float4*)hcat,
            (__nv_bfloat162*)Ahi, (__nv_bfloat162*)Alo, n4);
        int w4 = (G4 * 2 * HH) / 4;
        split_bf16<<<(w4 + 255) / 256, 256>>>((const float4*)Wih_f1,
            (__nv_bfloat162*)Wfhi, (__nv_bfloat162*)Wflo, w4);
        split_bf16<<<(w4 + 255) / 256, 256>>>((const float4*)Wih_r1,
            (__nv_bfloat162*)Wrhi, (__nv_bfloat162*)Wrlo, w4);
        gemm_bf16s<<<ggrid, 256, GB_SMEM>>>(M, G4, 2 * HH, Ahi, Alo, Wfhi, Wflo, bih_f1, bhh_f1, gf);
        gemm_bf16s<<<ggrid, 256, GB_SMEM>>>(M, G4, 2 * HH, Ahi, Alo, Wrhi, Wrlo, bih_r1, bhh_r1, gr);
        split_bf16<<<(whn4 + 255) / 256, 256>>>((const float4*)Whh_f1,
            (__nv_bfloat162*)WhfHi, (__nv_bfloat162*)WhfLo, whn4);
        split_bf16<<<(whn4 + 255) / 256, 256>>>((const float4*)Whh_r1,
            (__nv_bfloat162*)WhrHi, (__nv_bfloat162*)WhrLo, whn4);
    }
    cudaMemsetAsync(shi, 0, sizeof(__nv_bfloat16) * 2 * 2 * BB * HH, 0);
    cudaMemsetAsync(slo, 0, sizeof(__nv_bfloat16) * 2 * 2 * BB * HH, 0);
    cudaMemsetAsync(bar, 0, sizeof(unsigned), 0);
    lstm_layer_tc<<<128, 256, RK_SMEM>>>(gf, gr, WhfHi, WhfLo, WhrHi, WhrLo,
                                         shi, slo, (float*)d_out, 1);
}

// round 8
// speedup vs baseline: 2.2272x; 1.0167x over previous
#include <cuda_runtime.h>
#include <cuda_bf16.h>
#include <math.h>
#include <cstdint>

// Problem dims
#define LL 512
#define BB 64
#define II 256
#define HH 512
#define G4 2048   // 4*H

// ---------------- scratch (static device globals; no allocation) ----------------
__device__ float g_xT[(size_t)LL * BB * II];          // [t][b][I]
__device__ float g_gates_f[(size_t)LL * BB * G4];     // [t][b][4H]
__device__ float g_gates_r[(size_t)LL * BB * G4];     // [t][b][4H]
__device__ float g_hcat[(size_t)LL * BB * 2 * HH];    // [t][b][2H]
__device__ unsigned g_bar4[4 * 32];                   // 4 group barriers, 128B apart

// h state as bf16 hi/lo: [dir][parity][b][u]
__device__ __align__(16) __nv_bfloat16 g_shi[2 * 2 * BB * HH];
__device__ __align__(16) __nv_bfloat16 g_slo[2 * 2 * BB * HH];

// bf16 split buffers (input GEMM operands)
__device__ __align__(16) __nv_bfloat16 g_Ahi[(size_t)LL * BB * 2 * HH];
__device__ __align__(16) __nv_bfloat16 g_Alo[(size_t)LL * BB * 2 * HH];
__device__ __align__(16) __nv_bfloat16 g_Wfhi[(size_t)G4 * 2 * HH];
__device__ __align__(16) __nv_bfloat16 g_Wflo[(size_t)G4 * 2 * HH];
__device__ __align__(16) __nv_bfloat16 g_Wrhi[(size_t)G4 * 2 * HH];
__device__ __align__(16) __nv_bfloat16 g_Wrlo[(size_t)G4 * 2 * HH];
// Whh splits for the recurrence ([2048][512] each)
__device__ __align__(16) __nv_bfloat16 g_WhfHi[(size_t)G4 * HH];
__device__ __align__(16) __nv_bfloat16 g_WhfLo[(size_t)G4 * HH];
__device__ __align__(16) __nv_bfloat16 g_WhrHi[(size_t)G4 * HH];
__device__ __align__(16) __nv_bfloat16 g_WhrLo[(size_t)G4 * HH];

__device__ __forceinline__ uint32_t smem_u32(const void* p) {
    uint32_t a;
    asm("{ .reg .u64 t; cvta.to.shared.u64 t, %1; cvt.u32.u64 %0, t; }" : "=r"(a) : "l"(p));
    return a;
}

// ---------------- transpose x[b][l][i] -> xT[l][b][i] ----------------
__global__ void transpose_x(const float4* __restrict__ x, float4* __restrict__ xT) {
    int idx = blockIdx.x * blockDim.x + threadIdx.x;
    int i4 = idx & 63;
    int m  = idx >> 6;
    int t  = m >> 6;
    int b  = m & 63;
    xT[idx] = x[((size_t)(b * LL + t)) * 64 + i4];
}

// ---------------- fp32 -> bf16 hi/lo split ----------------
__global__ void split_bf16(const float4* __restrict__ src,
                           __nv_bfloat162* __restrict__ hi,
                           __nv_bfloat162* __restrict__ lo, int n4) {
    int i = blockIdx.x * blockDim.x + threadIdx.x;
    if (i >= n4) return;
    float4 v = src[i];
    __nv_bfloat16 hx = __float2bfloat16(v.x);
    __nv_bfloat16 hy = __float2bfloat16(v.y);
    __nv_bfloat16 hz = __float2bfloat16(v.z);
    __nv_bfloat16 hw = __float2bfloat16(v.w);
    __nv_bfloat16 lx = __float2bfloat16(v.x - __bfloat162float(hx));
    __nv_bfloat16 ly = __float2bfloat16(v.y - __bfloat162float(hy));
    __nv_bfloat16 lz = __float2bfloat16(v.z - __bfloat162float(hz));
    __nv_bfloat16 lw = __float2bfloat16(v.w - __bfloat162float(hw));
    hi[i * 2 + 0] = __nv_bfloat162(hx, hy);
    hi[i * 2 + 1] = __nv_bfloat162(hz, hw);
    lo[i * 2 + 0] = __nv_bfloat162(lx, ly);
    lo[i * 2 + 1] = __nv_bfloat162(lz, lw);
}

// ---------------- bf16 split-GEMM on HMMA: 128x256 block, 64x64 warp tiles ----------------
#define GBK   32
#define GTA   10240                 // A tile: 128 * 80
#define GTB   20480                 // B tile: 256 * 80
#define GSTG  (2 * GTA + 2 * GTB)   // 61440
#define GB_SMEM (2 * GSTG + 1024)   // 123904

__global__ __launch_bounds__(256, 1) void gemm_bf16s(
    int M, int N, int K,
    const __nv_bfloat16* __restrict__ Ahi, const __nv_bfloat16* __restrict__ Alo,
    const __nv_bfloat16* __restrict__ Bhi, const __nv_bfloat16* __restrict__ Blo,
    const float* __restrict__ bias1, const float* __restrict__ bias2,
    float* __restrict__ C)
{
    extern __shared__ char sm[];
    uint32_t sb = smem_u32(sm);
    int tid  = threadIdx.x;
    int lane = tid & 31;
    int warp = tid >> 5;
    int gid  = lane >> 2;
    int tg   = lane & 3;
    int wm   = warp >> 2;     // 0..1 (64 rows)
    int wn   = warp & 3;      // 0..3 (64 cols)
    int n0   = blockIdx.x * 256;
    int m0   = blockIdx.y * 128;

    float* shb = (float*)(sm + 2 * GSTG);
    shb[tid] = bias1[n0 + tid] + bias2[n0 + tid];

    const char* srcs[4];
    srcs[0] = (const char*)(Ahi + (size_t)m0 * K);
    srcs[1] = (const char*)(Alo + (size_t)m0 * K);
    srcs[2] = (const char*)(Bhi + (size_t)n0 * K);
    srcs[3] = (const char*)(Blo + (size_t)n0 * K);

    // per stage: A hi/lo 2x(128 rows x 4 f4) = 1024 f4; B hi/lo 2x(256 x 4) = 2048 f4
#define LOAD_STAGE(kc, bufsel)                                                      \
    {                                                                               \
        _Pragma("unroll")                                                           \
        for (int j = 0; j < 12; j++) {                                              \
            int c = tid + j * 256;                                                  \
            int tile, row, g; uint32_t toff;                                        \
            if (j < 4) { tile = c >> 9; row = (c & 511) >> 2; g = c & 3;            \
                         toff = (uint32_t)tile * GTA; }                             \
            else { int c2 = c - 1024; tile = 2 + (c2 >> 10);                        \
                   row = (c2 & 1023) >> 2; g = c2 & 3;                              \
                   toff = 2 * GTA + (uint32_t)(tile - 2) * GTB; }                   \
            uint32_t d = sb + (bufsel) * GSTG + toff + row * 80 + g * 16;           \
            const char* s = srcs[tile] + ((size_t)row * K + (kc) * GBK) * 2 + g * 16; \
            asm volatile("cp.async.ca.shared.global [%0], [%1], 16;" :: "r"(d), "l"(s)); \
        }                                                                           \
        asm volatile("cp.async.commit_group;" ::: "memory");                        \
    }

    float acc[4][8][4];
#pragma unroll
    for (int i = 0; i < 4; i++)
#pragma unroll
        for (int j = 0; j < 8; j++)
#pragma unroll
            for (int r = 0; r < 4; r++) acc[i][j][r] = 0.0f;

    int nk = K / GBK;
    LOAD_STAGE(0, 0);

    for (int kc = 0; kc < nk; kc++) {
        int buf = kc & 1;
        if (kc + 1 < nk) {
            LOAD_STAGE(kc + 1, buf ^ 1);
            asm volatile("cp.async.wait_group 1;" ::: "memory");
        } else {
            asm volatile("cp.async.wait_group 0;" ::: "memory");
        }
        __syncthreads();

        uint32_t bAh = sb + buf * GSTG;
        uint32_t bAl = bAh + GTA;
        uint32_t bBh = bAh + 2 * GTA;
        uint32_t bBl = bBh + GTB;

        uint32_t aoff = (uint32_t)(wm * 64 + (lane & 15)) * 80 + (lane >> 4) * 16;
        uint32_t boff = (uint32_t)(wn * 64 + (lane & 7)) * 80 + ((lane >> 3) & 1) * 16;

#pragma unroll
        for (int ks = 0; ks < 2; ks++) {
            uint32_t ko = ks * 32;
            uint32_t ah[4][4], al[4][4];
#pragma unroll
            for (int mt = 0; mt < 4; mt++) {
                asm volatile("ldmatrix.sync.aligned.m8n8.x4.shared.b16 {%0,%1,%2,%3}, [%4];"
                    : "=r"(ah[mt][0]), "=r"(ah[mt][1]), "=r"(ah[mt][2]), "=r"(ah[mt][3])
                    : "r"(bAh + aoff + ko + mt * (16 * 80)));
                asm volatile("ldmatrix.sync.aligned.m8n8.x4.shared.b16 {%0,%1,%2,%3}, [%4];"
                    : "=r"(al[mt][0]), "=r"(al[mt][1]), "=r"(al[mt][2]), "=r"(al[mt][3])
                    : "r"(bAl + aoff + ko + mt * (16 * 80)));
            }
            uint32_t bh[8][2], bl[8][2];
#pragma unroll
            for (int nt = 0; nt < 8; nt++) {
                asm volatile("ldmatrix.sync.aligned.m8n8.x2.shared.b16 {%0,%1}, [%2];"
                    : "=r"(bh[nt][0]), "=r"(bh[nt][1]) : "r"(bBh + boff + ko + nt * (8 * 80)));
                asm volatile("ldmatrix.sync.aligned.m8n8.x2.shared.b16 {%0,%1}, [%2];"
                    : "=r"(bl[nt][0]), "=r"(bl[nt][1]) : "r"(bBl + boff + ko + nt * (8 * 80)));
            }
#pragma unroll
            for (int mt = 0; mt < 4; mt++)
#pragma unroll
                for (int nt = 0; nt < 8; nt++) {
                    asm volatile(
                        "mma.sync.aligned.m16n8k16.row.col.f32.bf16.bf16.f32 "
                        "{%0,%1,%2,%3}, {%4,%5,%6,%7}, {%8,%9}, {%0,%1,%2,%3};"
                        : "+f"(acc[mt][nt][0]), "+f"(acc[mt][nt][1]),
                          "+f"(acc[mt][nt][2]), "+f"(acc[mt][nt][3])
                        : "r"(ah[mt][0]), "r"(ah[mt][1]), "r"(ah[mt][2]), "r"(ah[mt][3]),
                          "r"(bh[nt][0]), "r"(bh[nt][1]));
                    asm volatile(
                        "mma.sync.aligned.m16n8k16.row.col.f32.bf16.bf16.f32 "
                        "{%0,%1,%2,%3}, {%4,%5,%6,%7}, {%8,%9}, {%0,%1,%2,%3};"
                        : "+f"(acc[mt][nt][0]), "+f"(acc[mt][nt][1]),
                          "+f"(acc[mt][nt][2]), "+f"(acc[mt][nt][3])
                        : "r"(al[mt][0]), "r"(al[mt][1]), "r"(al[mt][2]), "r"(al[mt][3]),
                          "r"(bh[nt][0]), "r"(bh[nt][1]));
                    asm volatile(
                        "mma.sync.aligned.m16n8k16.row.col.f32.bf16.bf16.f32 "
                        "{%0,%1,%2,%3}, {%4,%5,%6,%7}, {%8,%9}, {%0,%1,%2,%3};"
                        : "+f"(acc[mt][nt][0]), "+f"(acc[mt][nt][1]),
                          "+f"(acc[mt][nt][2]), "+f"(acc[mt][nt][3])
                        : "r"(ah[mt][0]), "r"(ah[mt][1]), "r"(ah[mt][2]), "r"(ah[mt][3]),
                          "r"(bl[nt][0]), "r"(bl[nt][1]));
                }
        }
        __syncthreads();
    }

#pragma unroll
    for (int mt = 0; mt < 4; mt++) {
        int r0 = m0 + wm * 64 + mt * 16 + gid;
#pragma unroll
        for (int nt = 0; nt < 8; nt++) {
            int cl = wn * 64 + nt * 8 + 2 * tg;
            float b0 = shb[cl], b1 = shb[cl + 1];
            *(float2*)(C + (size_t)r0 * N + n0 + cl) =
                make_float2(acc[mt][nt][0] + b0, acc[mt][nt][1] + b1);
            *(float2*)(C + (size_t)(r0 + 8) * N + n0 + cl) =
                make_float2(acc[mt][nt][2] + b0, acc[mt][nt][3] + b1);
        }
    }
}

// ---------------- persistent tensor-core LSTM layer ----------------
// Grid 128 = dir(2) x us(32) x bs(2). Barrier is per (dir,bs) group: 32 CTAs.
// Gate inputs prefetched to registers at step top; h/output written back
// coalesced through a small smem staging tile.
#define RP     1040
#define OFF_AHI 0
#define OFF_ALO (64 * RP)
#define OFF_BHI (2 * 64 * RP)
#define OFF_BLO (2 * 64 * RP + 32 * RP)
#define OFF_G0  (2 * 64 * RP + 2 * 32 * RP)
#define OFF_G1  (OFF_G0 + 64 * 33 * 4)
#define OFF_HST (OFF_G1 + 64 * 33 * 4)       // f32 h staging [32 b][16 u]
#define RK_SMEM (OFF_HST + 32 * 16 * 4)      // 218624

__global__ __launch_bounds__(256, 1) void lstm_layer_tc(
    const float* __restrict__ gates_f,
    const float* __restrict__ gates_r,
    const __nv_bfloat16* __restrict__ WhfHi, const __nv_bfloat16* __restrict__ WhfLo,
    const __nv_bfloat16* __restrict__ WhrHi, const __nv_bfloat16* __restrict__ WhrLo,
    __nv_bfloat16* __restrict__ shi,
    __nv_bfloat16* __restrict__ slo,
    float* __restrict__ outbuf,
    int out_mode)
{
    extern __shared__ char sm[];
    uint32_t sb = smem_u32(sm);
    int tid  = threadIdx.x;
    int lane = tid & 31;
    int warp = tid >> 5;
    int gid  = lane >> 2;
    int tg   = lane & 3;

    int bx  = blockIdx.x;
    int dir = bx >> 6;
    int us  = (bx >> 1) & 31;
    int bs  = bx & 1;
    int u0  = us * 16;
    int b0  = bs * 32;
    int grp = dir * 2 + bs;
    volatile unsigned* gbar = &g_bar4[grp * 32];

    const float* gates = dir ? gates_r : gates_f;
    const __nv_bfloat16* whH = dir ? WhrHi : WhfHi;
    const __nv_bfloat16* whL = dir ? WhrLo : WhfLo;

    // ---- stage Whh slice once ----
#pragma unroll
    for (int j = 0; j < 16; j++) {
        int idx = tid + j * 256;
        int row = idx >> 6;
        int ch  = idx & 63;
        int g   = row >> 4;
        int ul  = row & 15;
        size_t soff = (size_t)(g * HH + u0 + ul) * HH + ch * 8;
        *(uint4*)(sm + OFF_AHI + row * RP + ch * 16) = *(const uint4*)(whH + soff);
        *(uint4*)(sm + OFF_ALO + row * RP + ch * 16) = *(const uint4*)(whL + soff);
    }

    int wk = warp >> 2;
    int wm = (warp >> 1) & 1;
    int wn = warp & 1;
    uint32_t apat = (uint32_t)(lane & 15) * RP + (lane >> 4) * 16;
    uint32_t bpat = (uint32_t)((lane & 7) + ((lane >> 4) << 3)) * RP + ((lane >> 3) & 1) * 16;
    uint32_t aBaseHi = sb + OFF_AHI + wm * 32 * RP + apat;
    uint32_t aBaseLo = sb + OFF_ALO + wm * 32 * RP + apat;
    uint32_t bBaseHi = sb + OFF_BHI + wn * 16 * RP + bpat;
    uint32_t bBaseLo = sb + OFF_BLO + wn * 16 * RP + bpat;
    float* gbuf = (float*)(sm + (wk ? OFF_G1 : OFF_G0));
    float* g0f  = (float*)(sm + OFF_G0);
    float* g1f  = (float*)(sm + OFF_G1);
    float* hst  = (float*)(sm + OFF_HST);

    // epilogue ownership: q=0,1 -> pr = tid + q*256 -> (ul = pr>>5, b = pr&31)
    float cst[2] = {0.0f, 0.0f};

    for (int s = 0; s < LL; s++) {
        int t   = dir ? (LL - 1 - s) : s;
        int par = s & 1;
        const __nv_bfloat16* hinH = shi + ((dir * 2 + par) * BB) * HH;
        const __nv_bfloat16* hinL = slo + ((dir * 2 + par) * BB) * HH;
        __nv_bfloat16* houtH = shi + ((dir * 2 + (par ^ 1)) * BB) * HH;
        __nv_bfloat16* houtL = slo + ((dir * 2 + (par ^ 1)) * BB) * HH;

        // ---- prefetch this thread's gate inputs (independent of barrier/h) ----
        float pg[2][4];
#pragma unroll
        for (int q = 0; q < 2; q++) {
            int pr = tid + q * 256;
            int ul = pr >> 5;
            int b  = pr & 31;
            size_t gbase = ((size_t)t * BB + (b0 + b)) * G4 + (u0 + ul);
#pragma unroll
            for (int g = 0; g < 4; g++)
                pg[q][g] = __ldcg(&gates[gbase + g * HH]);
        }

        // ---- stage h tile (32 b x 512) hi/lo ----
#pragma unroll
        for (int j = 0; j < 8; j++) {
            int idx = tid + j * 256;
            int row = idx >> 6;
            int ch  = idx & 63;
            size_t soff = (size_t)(b0 + row) * HH + ch * 8;
            uint4 vh = __ldcg((const uint4*)(hinH + soff));
            uint4 vl = __ldcg((const uint4*)(hinL + soff));
            *(uint4*)(sm + OFF_BHI + row * RP + ch * 16) = vh;
            *(uint4*)(sm + OFF_BLO + row * RP + ch * 16) = vl;
        }
        __syncthreads();

        // ---- 3-term HMMA over this warp's 16 k-chunks ----
        float t0[2][2][4], t1[2][2][4], t2[2][2][4];
#pragma unroll
        for (int i = 0; i < 2; i++)
#pragma unroll
            for (int j = 0; j < 2; j++)
#pragma unroll
                for (int r = 0; r < 4; r++) { t0[i][j][r] = 0.f; t1[i][j][r] = 0.f; t2[i][j][r] = 0.f; }

#pragma unroll 4
        for (int kc = 0; kc < 16; kc++) {
            uint32_t kb = (uint32_t)(wk * 16 + kc) * 32;
            uint32_t ah[2][4], al[2][4];
#pragma unroll
            for (int mt = 0; mt < 2; mt++) {
                asm volatile("ldmatrix.sync.aligned.m8n8.x4.shared.b16 {%0,%1,%2,%3}, [%4];"
                    : "=r"(ah[mt][0]), "=r"(ah[mt][1]), "=r"(ah[mt][2]), "=r"(ah[mt][3])
                    : "r"(aBaseHi + kb + mt * (16 * RP)));
                asm volatile("ldmatrix.sync.aligned.m8n8.x4.shared.b16 {%0,%1,%2,%3}, [%4];"
                    : "=r"(al[mt][0]), "=r"(al[mt][1]), "=r"(al[mt][2]), "=r"(al[mt][3])
                    : "r"(aBaseLo + kb + mt * (16 * RP)));
            }
            uint32_t bh[4], bl[4];
            asm volatile("ldmatrix.sync.aligned.m8n8.x4.shared.b16 {%0,%1,%2,%3}, [%4];"
                : "=r"(bh[0]), "=r"(bh[1]), "=r"(bh[2]), "=r"(bh[3]) : "r"(bBaseHi + kb));
            asm volatile("ldmatrix.sync.aligned.m8n8.x4.shared.b16 {%0,%1,%2,%3}, [%4];"
                : "=r"(bl[0]), "=r"(bl[1]), "=r"(bl[2]), "=r"(bl[3]) : "r"(bBaseLo + kb));
#pragma unroll
            for (int mt = 0; mt < 2; mt++)
#pragma unroll
                for (int nf = 0; nf < 2; nf++) {
                    asm volatile(
                        "mma.sync.aligned.m16n8k16.row.col.f32.bf16.bf16.f32 "
                        "{%0,%1,%2,%3}, {%4,%5,%6,%7}, {%8,%9}, {%0,%1,%2,%3};"
                        : "+f"(t0[mt][nf][0]), "+f"(t0[mt][nf][1]),
                          "+f"(t0[mt][nf][2]), "+f"(t0[mt][nf][3])
                        : "r"(ah[mt][0]), "r"(ah[mt][1]), "r"(ah[mt][2]), "r"(ah[mt][3]),
                          "r"(bh[nf * 2]), "r"(bh[nf * 2 + 1]));
                    asm volatile(
                        "mma.sync.aligned.m16n8k16.row.col.f32.bf16.bf16.f32 "
                        "{%0,%1,%2,%3}, {%4,%5,%6,%7}, {%8,%9}, {%0,%1,%2,%3};"
                        : "+f"(t1[mt][nf][0]), "+f"(t1[mt][nf][1]),
                          "+f"(t1[mt][nf][2]), "+f"(t1[mt][nf][3])
                        : "r"(al[mt][0]), "r"(al[mt][1]), "r"(al[mt][2]), "r"(al[mt][3]),
                          "r"(bh[nf * 2]), "r"(bh[nf * 2 + 1]));
                    asm volatile(
                        "mma.sync.aligned.m16n8k16.row.col.f32.bf16.bf16.f32 "
                        "{%0,%1,%2,%3}, {%4,%5,%6,%7}, {%8,%9}, {%0,%1,%2,%3};"
                        : "+f"(t2[mt][nf][0]), "+f"(t2[mt][nf][1]),
                          "+f"(t2[mt][nf][2]), "+f"(t2[mt][nf][3])
                        : "r"(ah[mt][0]), "r"(ah[mt][1]), "r"(ah[mt][2]), "r"(ah[mt][3]),
                          "r"(bl[nf * 2]), "r"(bl[nf * 2 + 1]));
                }
        }

        // ---- write k-partials to gate buffer (scalar: pitch 33 odd) ----
#pragma unroll
        for (int mt = 0; mt < 2; mt++) {
            int r0 = wm * 32 + mt * 16 + gid;
#pragma unroll
            for (int nf = 0; nf < 2; nf++) {
                int cl = wn * 16 + nf * 8 + 2 * tg;
                gbuf[r0 * 33 + cl]           = t0[mt][nf][0] + t1[mt][nf][0] + t2[mt][nf][0];
                gbuf[r0 * 33 + cl + 1]       = t0[mt][nf][1] + t1[mt][nf][1] + t2[mt][nf][1];
                gbuf[(r0 + 8) * 33 + cl]     = t0[mt][nf][2] + t1[mt][nf][2] + t2[mt][nf][2];
                gbuf[(r0 + 8) * 33 + cl + 1] = t0[mt][nf][3] + t1[mt][nf][3] + t2[mt][nf][3];
            }
        }
        __syncthreads();

        // ---- epilogue: combine k-halves + prefetched gates -> c/h ----
#pragma unroll
        for (int q = 0; q < 2; q++) {
            int pr = tid + q * 256;
            int ul = pr >> 5;
            int b  = pr & 31;
            float gi = pg[q][0] + g0f[(0 * 16 + ul) * 33 + b] + g1f[(0 * 16 + ul) * 33 + b];
            float gf = pg[q][1] + g0f[(1 * 16 + ul) * 33 + b] + g1f[(1 * 16 + ul) * 33 + b];
            float gg = pg[q][2] + g0f[(2 * 16 + ul) * 33 + b] + g1f[(2 * 16 + ul) * 33 + b];
            float go = pg[q][3] + g0f[(3 * 16 + ul) * 33 + b] + g1f[(3 * 16 + ul) * 33 + b];
            float si = 1.0f / (1.0f + expf(-gi));
            float sf = 1.0f / (1.0f + expf(-gf));
            float so = 1.0f / (1.0f + expf(-go));
            cst[q] = sf * cst[q] + si * tanhf(gg);
            float h2 = so * tanhf(cst[q]);
            hst[b * 16 + ul] = h2;
        }
        __syncthreads();

        // ---- coalesced writeback: h state (bf16 hi/lo) + output (f32) ----
        {
            int p  = tid * 2;            // two consecutive u per thread
            int b  = p >> 4;             // 0..31
            int uu = p & 15;             // even
            float v0 = hst[p], v1 = hst[p + 1];
            __nv_bfloat16 h0 = __float2bfloat16(v0);
            __nv_bfloat16 h1 = __float2bfloat16(v1);
            __nv_bfloat16 l0 = __float2bfloat16(v0 - __bfloat162float(h0));
            __nv_bfloat16 l1 = __float2bfloat16(v1 - __bfloat162float(h1));
            int bg = b0 + b;
            size_t hoff = (size_t)bg * HH + u0 + uu;
            __stcg((__nv_bfloat162*)&houtH[hoff], __nv_bfloat162(h0, h1));
            __stcg((__nv_bfloat162*)&houtL[hoff], __nv_bfloat162(l0, l1));
            size_t orow = out_mode ? ((size_t)bg * LL + t) : ((size_t)t * BB + bg);
            *(float2*)(outbuf + orow * (2 * HH) + dir * HH + u0 + uu) = make_float2(v0, v1);
        }

        // ---- group barrier across 32 CTAs (dir,bs) ----
        __threadfence();
        __syncthreads();
        if (tid == 0) {
            atomicAdd((unsigned*)gbar, 1u);
            unsigned target = (unsigned)(s + 1) * 32u;
            while (*gbar < target) { }
        }
        __syncthreads();
    }
}

// ---------------- host launcher ----------------
extern "C" void kernel_launch(void* const* d_in, const int* in_sizes, int n_in,
                              void* d_out, int out_size)
{
    const float* x       = (const float*)d_in[0];
    const float* Wih_f0  = (const float*)d_in[1];
    const float* Whh_f0  = (const float*)d_in[2];
    const float* bih_f0  = (const float*)d_in[3];
    const float* bhh_f0  = (const float*)d_in[4];
    const float* Wih_r0  = (const float*)d_in[5];
    const float* Whh_r0  = (const float*)d_in[6];
    const float* bih_r0  = (const float*)d_in[7];
    const float* bhh_r0  = (const float*)d_in[8];
    const float* Wih_f1  = (const float*)d_in[9];
    const float* Whh_f1  = (const float*)d_in[10];
    const float* bih_f1  = (const float*)d_in[11];
    const float* bhh_f1  = (const float*)d_in[12];
    const float* Wih_r1  = (const float*)d_in[13];
    const float* Whh_r1  = (const float*)d_in[14];
    const float* bih_r1  = (const float*)d_in[15];
    const float* bhh_r1  = (const float*)d_in[16];

    float *xT, *gf, *gr, *hcat;
    unsigned* bar4;
    __nv_bfloat16 *Ahi, *Alo, *Wfhi, *Wflo, *Wrhi, *Wrlo;
    __nv_bfloat16 *WhfHi, *WhfLo, *WhrHi, *WhrLo, *shi, *slo;
    cudaGetSymbolAddress((void**)&xT,    g_xT);
    cudaGetSymbolAddress((void**)&gf,    g_gates_f);
    cudaGetSymbolAddress((void**)&gr,    g_gates_r);
    cudaGetSymbolAddress((void**)&hcat,  g_hcat);
    cudaGetSymbolAddress((void**)&bar4,  g_bar4);
    cudaGetSymbolAddress((void**)&Ahi,   g_Ahi);
    cudaGetSymbolAddress((void**)&Alo,   g_Alo);
    cudaGetSymbolAddress((void**)&Wfhi,  g_Wfhi);
    cudaGetSymbolAddress((void**)&Wflo,  g_Wflo);
    cudaGetSymbolAddress((void**)&Wrhi,  g_Wrhi);
    cudaGetSymbolAddress((void**)&Wrlo,  g_Wrlo);
    cudaGetSymbolAddress((void**)&WhfHi, g_WhfHi);
    cudaGetSymbolAddress((void**)&WhfLo, g_WhfLo);
    cudaGetSymbolAddress((void**)&WhrHi, g_WhrHi);
    cudaGetSymbolAddress((void**)&WhrLo, g_WhrLo);
    cudaGetSymbolAddress((void**)&shi,   g_shi);
    cudaGetSymbolAddress((void**)&slo,   g_slo);

    cudaFuncSetAttribute(gemm_bf16s,    cudaFuncAttributeMaxDynamicSharedMemorySize, GB_SMEM);
    cudaFuncSetAttribute(lstm_layer_tc, cudaFuncAttributeMaxDynamicSharedMemorySize, RK_SMEM);

    const int M = LL * BB;   // 32768
    const int whn4 = (G4 * HH) / 4;

    transpose_x<<<8192, 256>>>((const float4*)x, (float4*)xT);

    dim3 ggrid(G4 / 256, M / 128);   // (8, 256)

    // ---- layer 0 (K = 256) ----
    {
        int n4 = (LL * BB * II) / 4;
        split_bf16<<<(n4 + 255) / 256, 256>>>((const float4*)xT,
            (__nv_bfloat162*)Ahi, (__nv_bfloat162*)Alo, n4);
        int w4 = (G4 * II) / 4;
        split_bf16<<<(w4 + 255) / 256, 256>>>((const float4*)Wih_f0,
            (__nv_bfloat162*)Wfhi, (__nv_bfloat162*)Wflo, w4);
        split_bf16<<<(w4 + 255) / 256, 256>>>((const float4*)Wih_r0,
            (__nv_bfloat162*)Wrhi, (__nv_bfloat162*)Wrlo, w4);
        gemm_bf16s<<<ggrid, 256, GB_SMEM>>>(M, G4, II, Ahi, Alo, Wfhi, Wflo, bih_f0, bhh_f0, gf);
        gemm_bf16s<<<ggrid, 256, GB_SMEM>>>(M, G4, II, Ahi, Alo, Wrhi, Wrlo, bih_r0, bhh_r0, gr);
        split_bf16<<<(whn4 + 255) / 256, 256>>>((const float4*)Whh_f0,
            (__nv_bfloat162*)WhfHi, (__nv_bfloat162*)WhfLo, whn4);
        split_bf16<<<(whn4 + 255) / 256, 256>>>((const float4*)Whh_r0,
            (__nv_bfloat162*)WhrHi, (__nv_bfloat162*)WhrLo, whn4);
    }
    cudaMemsetAsync(shi, 0, sizeof(__nv_bfloat16) * 2 * 2 * BB * HH, 0);
    cudaMemsetAsync(slo, 0, sizeof(__nv_bfloat16) * 2 * 2 * BB * HH, 0);
    cudaMemsetAsync(bar4, 0, sizeof(unsigned) * 4 * 32, 0);
    lstm_layer_tc<<<128, 256, RK_SMEM>>>(gf, gr, WhfHi, WhfLo, WhrHi, WhrLo,
                                         shi, slo, hcat, 0);

    // ---- layer 1 (K = 1024) ----
    {
        int n4 = (LL * BB * 2 * HH) / 4;
        split_bf16<<<(n4 + 255) / 256, 256>>>((const float4*)hcat,
            (__nv_bfloat162*)Ahi, (__nv_bfloat162*)Alo, n4);
        int w4 = (G4 * 2 * HH) / 4;
        split_bf16<<<(w4 + 255) / 256, 256>>>((const float4*)Wih_f1,
            (__nv_bfloat162*)Wfhi, (__nv_bfloat162*)Wflo, w4);
        split_bf16<<<(w4 + 255) / 256, 256>>>((const float4*)Wih_r1,
            (__nv_bfloat162*)Wrhi, (__nv_bfloat162*)Wrlo, w4);
        gemm_bf16s<<<ggrid, 256, GB_SMEM>>>(M, G4, 2 * HH, Ahi, Alo, Wfhi, Wflo, bih_f1, bhh_f1, gf);
        gemm_bf16s<<<ggrid, 256, GB_SMEM>>>(M, G4, 2 * HH, Ahi, Alo, Wrhi, Wrlo, bih_r1, bhh_r1, gr);
        split_bf16<<<(whn4 + 255) / 256, 256>>>((const float4*)Whh_f1,
            (__nv_bfloat162*)WhfHi, (__nv_bfloat162*)WhfLo, whn4);
        split_bf16<<<(whn4 + 255) / 256, 256>>>((const float4*)Whh_r1,
            (__nv_bfloat162*)WhrHi, (__nv_bfloat162*)WhrLo, whn4);
    }
    cudaMemsetAsync(shi, 0, sizeof(__nv_bfloat16) * 2 * 2 * BB * HH, 0);
    cudaMemsetAsync(slo, 0, sizeof(__nv_bfloat16) * 2 * 2 * BB * HH, 0);
    cudaMemsetAsync(bar4, 0, sizeof(unsigned) * 4 * 32, 0);
    lstm_layer_tc<<<128, 256, RK_SMEM>>>(gf, gr, WhfHi, WhfLo, WhrHi, WhrLo,
                                         shi, slo, (float*)d_out, 1);
}

// round 9
// speedup vs baseline: 2.8817x; 1.2938x over previous
#include <cuda_runtime.h>
#include <cuda_bf16.h>
#include <math.h>
#include <cstdint>

// Problem dims
#define LL 512
#define BB 64
#define II 256
#define HH 512
#define G4 2048   // 4*H

// ---------------- scratch (static device globals; no allocation) ----------------
__device__ float g_xT[(size_t)LL * BB * II];          // [t][b][I]
__device__ float g_gates_f[(size_t)LL * BB * G4];     // [t][b][4H]
__device__ float g_gates_r[(size_t)LL * BB * G4];     // [t][b][4H]
__device__ float g_hcat[(size_t)LL * BB * 2 * HH];    // [t][b][2H]
__device__ unsigned g_bar4[4 * 32];                   // 4 group barriers, 128B apart

// h state as bf16 hi/lo: [dir][parity][b][u]
__device__ __align__(16) __nv_bfloat16 g_shi[2 * 2 * BB * HH];
__device__ __align__(16) __nv_bfloat16 g_slo[2 * 2 * BB * HH];

// bf16 split buffers (input GEMM operands)
__device__ __align__(16) __nv_bfloat16 g_Ahi[(size_t)LL * BB * 2 * HH];
__device__ __align__(16) __nv_bfloat16 g_Alo[(size_t)LL * BB * 2 * HH];
__device__ __align__(16) __nv_bfloat16 g_Wfhi[(size_t)G4 * 2 * HH];
__device__ __align__(16) __nv_bfloat16 g_Wflo[(size_t)G4 * 2 * HH];
__device__ __align__(16) __nv_bfloat16 g_Wrhi[(size_t)G4 * 2 * HH];
__device__ __align__(16) __nv_bfloat16 g_Wrlo[(size_t)G4 * 2 * HH];
// Whh splits for the recurrence ([2048][512] each)
__device__ __align__(16) __nv_bfloat16 g_WhfHi[(size_t)G4 * HH];
__device__ __align__(16) __nv_bfloat16 g_WhfLo[(size_t)G4 * HH];
__device__ __align__(16) __nv_bfloat16 g_WhrHi[(size_t)G4 * HH];
__device__ __align__(16) __nv_bfloat16 g_WhrLo[(size_t)G4 * HH];

__device__ __forceinline__ uint32_t smem_u32(const void* p) {
    uint32_t a;
    asm("{ .reg .u64 t; cvta.to.shared.u64 t, %1; cvt.u32.u64 %0, t; }" : "=r"(a) : "l"(p));
    return a;
}

// ---------------- transpose x[b][l][i] -> xT[l][b][i] ----------------
__global__ void transpose_x(const float4* __restrict__ x, float4* __restrict__ xT) {
    int idx = blockIdx.x * blockDim.x + threadIdx.x;
    int i4 = idx & 63;
    int m  = idx >> 6;
    int t  = m >> 6;
    int b  = m & 63;
    xT[idx] = x[((size_t)(b * LL + t)) * 64 + i4];
}

// ---------------- fp32 -> bf16 hi/lo split ----------------
__global__ void split_bf16(const float4* __restrict__ src,
                           __nv_bfloat162* __restrict__ hi,
                           __nv_bfloat162* __restrict__ lo, int n4) {
    int i = blockIdx.x * blockDim.x + threadIdx.x;
    if (i >= n4) return;
    float4 v = src[i];
    __nv_bfloat16 hx = __float2bfloat16(v.x);
    __nv_bfloat16 hy = __float2bfloat16(v.y);
    __nv_bfloat16 hz = __float2bfloat16(v.z);
    __nv_bfloat16 hw = __float2bfloat16(v.w);
    __nv_bfloat16 lx = __float2bfloat16(v.x - __bfloat162float(hx));
    __nv_bfloat16 ly = __float2bfloat16(v.y - __bfloat162float(hy));
    __nv_bfloat16 lz = __float2bfloat16(v.z - __bfloat162float(hz));
    __nv_bfloat16 lw = __float2bfloat16(v.w - __bfloat162float(hw));
    hi[i * 2 + 0] = __nv_bfloat162(hx, hy);
    hi[i * 2 + 1] = __nv_bfloat162(hz, hw);
    lo[i * 2 + 0] = __nv_bfloat162(lx, ly);
    lo[i * 2 + 1] = __nv_bfloat162(lz, lw);
}

// ---------------- bf16 split-GEMM: 128x256 block, 3-stage pipeline, 1 sync/iter ----------------
#define GBK   32
#define GTA   10240                 // A tile: 128 * 80
#define GTB   20480                 // B tile: 256 * 80
#define GSTG  (2 * GTA + 2 * GTB)   // 61440
#define GB_SMEM (3 * GSTG + 1024)   // 185344

__global__ __launch_bounds__(256, 1) void gemm_bf16s(
    int M, int N, int K,
    const __nv_bfloat16* __restrict__ Ahi, const __nv_bfloat16* __restrict__ Alo,
    const __nv_bfloat16* __restrict__ Bhi, const __nv_bfloat16* __restrict__ Blo,
    const float* __restrict__ bias1, const float* __restrict__ bias2,
    float* __restrict__ C)
{
    extern __shared__ char sm[];
    uint32_t sb = smem_u32(sm);
    int tid  = threadIdx.x;
    int lane = tid & 31;
    int warp = tid >> 5;
    int gid  = lane >> 2;
    int tg   = lane & 3;
    int wm   = warp >> 2;     // 0..1 (64 rows)
    int wn   = warp & 3;      // 0..3 (64 cols)
    int n0   = blockIdx.x * 256;
    int m0   = blockIdx.y * 128;

    float* shb = (float*)(sm + 3 * GSTG);
    shb[tid] = bias1[n0 + tid] + bias2[n0 + tid];

    const char* srcs[4];
    srcs[0] = (const char*)(Ahi + (size_t)m0 * K);
    srcs[1] = (const char*)(Alo + (size_t)m0 * K);
    srcs[2] = (const char*)(Bhi + (size_t)n0 * K);
    srcs[3] = (const char*)(Blo + (size_t)n0 * K);

#define LOAD_STAGE(kc, bufsel)                                                      \
    {                                                                               \
        _Pragma("unroll")                                                           \
        for (int j = 0; j < 12; j++) {                                              \
            int c = tid + j * 256;                                                  \
            int tile, row, g; uint32_t toff;                                        \
            if (j < 4) { tile = c >> 9; row = (c & 511) >> 2; g = c & 3;            \
                         toff = (uint32_t)tile * GTA; }                             \
            else { int c2 = c - 1024; tile = 2 + (c2 >> 10);                        \
                   row = (c2 & 1023) >> 2; g = c2 & 3;                              \
                   toff = 2 * GTA + (uint32_t)(tile - 2) * GTB; }                   \
            uint32_t d = sb + (bufsel) * GSTG + toff + row * 80 + g * 16;           \
            const char* s = srcs[tile] + ((size_t)row * K + (kc) * GBK) * 2 + g * 16; \
            asm volatile("cp.async.ca.shared.global [%0], [%1], 16;" :: "r"(d), "l"(s)); \
        }                                                                           \
        asm volatile("cp.async.commit_group;" ::: "memory");                        \
    }

    float acc[4][8][4];
#pragma unroll
    for (int i = 0; i < 4; i++)
#pragma unroll
        for (int j = 0; j < 8; j++)
#pragma unroll
            for (int r = 0; r < 4; r++) acc[i][j][r] = 0.0f;

    int nk = K / GBK;      // >= 8 always here
    LOAD_STAGE(0, 0);
    LOAD_STAGE(1, 1);

    for (int kc = 0; kc < nk; kc++) {
        if (kc + 1 < nk)
            asm volatile("cp.async.wait_group 1;" ::: "memory");
        else
            asm volatile("cp.async.wait_group 0;" ::: "memory");
        __syncthreads();   // stage kc ready; buffer (kc-1)%3 free (compute kc-1 done)

        if (kc + 2 < nk) LOAD_STAGE(kc + 2, (kc + 2) % 3);

        int buf;
        { int m3 = kc % 3; buf = m3; }
        uint32_t bAh = sb + buf * GSTG;
        uint32_t bAl = bAh + GTA;
        uint32_t bBh = bAh + 2 * GTA;
        uint32_t bBl = bBh + GTB;

        uint32_t aoff = (uint32_t)(wm * 64 + (lane & 15)) * 80 + (lane >> 4) * 16;
        uint32_t boff = (uint32_t)(wn * 64 + (lane & 7)) * 80 + ((lane >> 3) & 1) * 16;

#pragma unroll
        for (int ks = 0; ks < 2; ks++) {
            uint32_t ko = ks * 32;
            uint32_t ah[4][4], al[4][4];
#pragma unroll
            for (int mt = 0; mt < 4; mt++) {
                asm volatile("ldmatrix.sync.aligned.m8n8.x4.shared.b16 {%0,%1,%2,%3}, [%4];"
                    : "=r"(ah[mt][0]), "=r"(ah[mt][1]), "=r"(ah[mt][2]), "=r"(ah[mt][3])
                    : "r"(bAh + aoff + ko + mt * (16 * 80)));
                asm volatile("ldmatrix.sync.aligned.m8n8.x4.shared.b16 {%0,%1,%2,%3}, [%4];"
                    : "=r"(al[mt][0]), "=r"(al[mt][1]), "=r"(al[mt][2]), "=r"(al[mt][3])
                    : "r"(bAl + aoff + ko + mt * (16 * 80)));
            }
            uint32_t bh[8][2], bl[8][2];
#pragma unroll
            for (int nt = 0; nt < 8; nt++) {
                asm volatile("ldmatrix.sync.aligned.m8n8.x2.shared.b16 {%0,%1}, [%2];"
                    : "=r"(bh[nt][0]), "=r"(bh[nt][1]) : "r"(bBh + boff + ko + nt * (8 * 80)));
                asm volatile("ldmatrix.sync.aligned.m8n8.x2.shared.b16 {%0,%1}, [%2];"
                    : "=r"(bl[nt][0]), "=r"(bl[nt][1]) : "r"(bBl + boff + ko + nt * (8 * 80)));
            }
#pragma unroll
            for (int mt = 0; mt < 4; mt++)
#pragma unroll
                for (int nt = 0; nt < 8; nt++) {
                    asm volatile(
                        "mma.sync.aligned.m16n8k16.row.col.f32.bf16.bf16.f32 "
                        "{%0,%1,%2,%3}, {%4,%5,%6,%7}, {%8,%9}, {%0,%1,%2,%3};"
                        : "+f"(acc[mt][nt][0]), "+f"(acc[mt][nt][1]),
                          "+f"(acc[mt][nt][2]), "+f"(acc[mt][nt][3])
                        : "r"(ah[mt][0]), "r"(ah[mt][1]), "r"(ah[mt][2]), "r"(ah[mt][3]),
                          "r"(bh[nt][0]), "r"(bh[nt][1]));
                    asm volatile(
                        "mma.sync.aligned.m16n8k16.row.col.f32.bf16.bf16.f32 "
                        "{%0,%1,%2,%3}, {%4,%5,%6,%7}, {%8,%9}, {%0,%1,%2,%3};"
                        : "+f"(acc[mt][nt][0]), "+f"(acc[mt][nt][1]),
                          "+f"(acc[mt][nt][2]), "+f"(acc[mt][nt][3])
                        : "r"(al[mt][0]), "r"(al[mt][1]), "r"(al[mt][2]), "r"(al[mt][3]),
                          "r"(bh[nt][0]), "r"(bh[nt][1]));
                    asm volatile(
                        "mma.sync.aligned.m16n8k16.row.col.f32.bf16.bf16.f32 "
                        "{%0,%1,%2,%3}, {%4,%5,%6,%7}, {%8,%9}, {%0,%1,%2,%3};"
                        : "+f"(acc[mt][nt][0]), "+f"(acc[mt][nt][1]),
                          "+f"(acc[mt][nt][2]), "+f"(acc[mt][nt][3])
                        : "r"(ah[mt][0]), "r"(ah[mt][1]), "r"(ah[mt][2]), "r"(ah[mt][3]),
                          "r"(bl[nt][0]), "r"(bl[nt][1]));
                }
        }
    }

#pragma unroll
    for (int mt = 0; mt < 4; mt++) {
        int r0 = m0 + wm * 64 + mt * 16 + gid;
#pragma unroll
        for (int nt = 0; nt < 8; nt++) {
            int cl = wn * 64 + nt * 8 + 2 * tg;
            float b0 = shb[cl], b1 = shb[cl + 1];
            *(float2*)(C + (size_t)r0 * N + n0 + cl) =
                make_float2(acc[mt][nt][0] + b0, acc[mt][nt][1] + b1);
            *(float2*)(C + (size_t)(r0 + 8) * N + n0 + cl) =
                make_float2(acc[mt][nt][2] + b0, acc[mt][nt][3] + b1);
        }
    }
}

// ---------------- persistent tensor-core LSTM layer ----------------
// Grid 128 = dir(2) x us(32) x bs(2). Barrier per (dir,bs) group of 32 CTAs.
// Epilogue ownership: thread -> (b = tid>>3, u-pair = (tid&7)*2): gate loads are
// float2, h/output writeback directly coalesced. 3 syncs/step, no staging tile.
#define RP     1040
#define OFF_AHI 0
#define OFF_ALO (64 * RP)
#define OFF_BHI (2 * 64 * RP)
#define OFF_BLO (2 * 64 * RP + 32 * RP)
#define OFF_G0  (2 * 64 * RP + 2 * 32 * RP)
#define OFF_G1  (OFF_G0 + 64 * 33 * 4)
#define RK_SMEM (OFF_G1 + 64 * 33 * 4)   // 216576

__global__ __launch_bounds__(256, 1) void lstm_layer_tc(
    const float* __restrict__ gates_f,
    const float* __restrict__ gates_r,
    const __nv_bfloat16* __restrict__ WhfHi, const __nv_bfloat16* __restrict__ WhfLo,
    const __nv_bfloat16* __restrict__ WhrHi, const __nv_bfloat16* __restrict__ WhrLo,
    __nv_bfloat16* __restrict__ shi,
    __nv_bfloat16* __restrict__ slo,
    float* __restrict__ outbuf,
    int out_mode)
{
    extern __shared__ char sm[];
    uint32_t sb = smem_u32(sm);
    int tid  = threadIdx.x;
    int lane = tid & 31;
    int warp = tid >> 5;
    int gid  = lane >> 2;
    int tg   = lane & 3;

    int bx  = blockIdx.x;
    int dir = bx >> 6;
    int us  = (bx >> 1) & 31;
    int bs  = bx & 1;
    int u0  = us * 16;
    int b0  = bs * 32;
    int grp = dir * 2 + bs;
    volatile unsigned* gbar = &g_bar4[grp * 32];

    const float* gates = dir ? gates_r : gates_f;
    const __nv_bfloat16* whH = dir ? WhrHi : WhfHi;
    const __nv_bfloat16* whL = dir ? WhrLo : WhfLo;

    // ---- stage Whh slice once ----
#pragma unroll
    for (int j = 0; j < 16; j++) {
        int idx = tid + j * 256;
        int row = idx >> 6;
        int ch  = idx & 63;
        int g   = row >> 4;
        int ul  = row & 15;
        size_t soff = (size_t)(g * HH + u0 + ul) * HH + ch * 8;
        *(uint4*)(sm + OFF_AHI + row * RP + ch * 16) = *(const uint4*)(whH + soff);
        *(uint4*)(sm + OFF_ALO + row * RP + ch * 16) = *(const uint4*)(whL + soff);
    }

    int wk = warp >> 2;
    int wm = (warp >> 1) & 1;
    int wn = warp & 1;
    uint32_t apat = (uint32_t)(lane & 15) * RP + (lane >> 4) * 16;
    uint32_t bpat = (uint32_t)((lane & 7) + ((lane >> 4) << 3)) * RP + ((lane >> 3) & 1) * 16;
    uint32_t aBaseHi = sb + OFF_AHI + wm * 32 * RP + apat;
    uint32_t aBaseLo = sb + OFF_ALO + wm * 32 * RP + apat;
    uint32_t bBaseHi = sb + OFF_BHI + wn * 16 * RP + bpat;
    uint32_t bBaseLo = sb + OFF_BLO + wn * 16 * RP + bpat;
    float* gbuf = (float*)(sm + (wk ? OFF_G1 : OFF_G0));
    float* g0f  = (float*)(sm + OFF_G0);
    float* g1f  = (float*)(sm + OFF_G1);

    // epilogue ownership: b = tid>>3 (0..31), u2 = (tid&7)*2 (0..14): two units
    int bown = tid >> 3;
    int u2   = (tid & 7) * 2;
    float cst0 = 0.0f, cst1 = 0.0f;

    for (int s = 0; s < LL; s++) {
        int t   = dir ? (LL - 1 - s) : s;
        int par = s & 1;
        const __nv_bfloat16* hinH = shi + ((dir * 2 + par) * BB) * HH;
        const __nv_bfloat16* hinL = slo + ((dir * 2 + par) * BB) * HH;
        __nv_bfloat16* houtH = shi + ((dir * 2 + (par ^ 1)) * BB) * HH;
        __nv_bfloat16* houtL = slo + ((dir * 2 + (par ^ 1)) * BB) * HH;

        // ---- prefetch this thread's gate inputs (float2 per gate) ----
        float2 pg[4];
        {
            size_t gbase = ((size_t)t * BB + (b0 + bown)) * G4 + (u0 + u2);
#pragma unroll
            for (int g = 0; g < 4; g++)
                pg[g] = __ldcg((const float2*)&gates[gbase + g * HH]);
        }

        // ---- stage h tile (32 b x 512) hi/lo ----
#pragma unroll
        for (int j = 0; j < 8; j++) {
            int idx = tid + j * 256;
            int row = idx >> 6;
            int ch  = idx & 63;
            size_t soff = (size_t)(b0 + row) * HH + ch * 8;
            uint4 vh = __ldcg((const uint4*)(hinH + soff));
            uint4 vl = __ldcg((const uint4*)(hinL + soff));
            *(uint4*)(sm + OFF_BHI + row * RP + ch * 16) = vh;
            *(uint4*)(sm + OFF_BLO + row * RP + ch * 16) = vl;
        }
        __syncthreads();

        // ---- 3-term HMMA over this warp's 16 k-chunks ----
        float t0[2][2][4], t1[2][2][4], t2[2][2][4];
#pragma unroll
        for (int i = 0; i < 2; i++)
#pragma unroll
            for (int j = 0; j < 2; j++)
#pragma unroll
                for (int r = 0; r < 4; r++) { t0[i][j][r] = 0.f; t1[i][j][r] = 0.f; t2[i][j][r] = 0.f; }

#pragma unroll 4
        for (int kc = 0; kc < 16; kc++) {
            uint32_t kb = (uint32_t)(wk * 16 + kc) * 32;
            uint32_t ah[2][4], al[2][4];
#pragma unroll
            for (int mt = 0; mt < 2; mt++) {
                asm volatile("ldmatrix.sync.aligned.m8n8.x4.shared.b16 {%0,%1,%2,%3}, [%4];"
                    : "=r"(ah[mt][0]), "=r"(ah[mt][1]), "=r"(ah[mt][2]), "=r"(ah[mt][3])
                    : "r"(aBaseHi + kb + mt * (16 * RP)));
                asm volatile("ldmatrix.sync.aligned.m8n8.x4.shared.b16 {%0,%1,%2,%3}, [%4];"
                    : "=r"(al[mt][0]), "=r"(al[mt][1]), "=r"(al[mt][2]), "=r"(al[mt][3])
                    : "r"(aBaseLo + kb + mt * (16 * RP)));
            }
            uint32_t bh[4], bl[4];
            asm volatile("ldmatrix.sync.aligned.m8n8.x4.shared.b16 {%0,%1,%2,%3}, [%4];"
                : "=r"(bh[0]), "=r"(bh[1]), "=r"(bh[2]), "=r"(bh[3]) : "r"(bBaseHi + kb));
            asm volatile("ldmatrix.sync.aligned.m8n8.x4.shared.b16 {%0,%1,%2,%3}, [%4];"
                : "=r"(bl[0]), "=r"(bl[1]), "=r"(bl[2]), "=r"(bl[3]) : "r"(bBaseLo + kb));
#pragma unroll
            for (int mt = 0; mt < 2; mt++)
#pragma unroll
                for (int nf = 0; nf < 2; nf++) {
                    asm volatile(
                        "mma.sync.aligned.m16n8k16.row.col.f32.bf16.bf16.f32 "
                        "{%0,%1,%2,%3}, {%4,%5,%6,%7}, {%8,%9}, {%0,%1,%2,%3};"
                        : "+f"(t0[mt][nf][0]), "+f"(t0[mt][nf][1]),
                          "+f"(t0[mt][nf][2]), "+f"(t0[mt][nf][3])
                        : "r"(ah[mt][0]), "r"(ah[mt][1]), "r"(ah[mt][2]), "r"(ah[mt][3]),
                          "r"(bh[nf * 2]), "r"(bh[nf * 2 + 1]));
                    asm volatile(
                        "mma.sync.aligned.m16n8k16.row.col.f32.bf16.bf16.f32 "
                        "{%0,%1,%2,%3}, {%4,%5,%6,%7}, {%8,%9}, {%0,%1,%2,%3};"
                        : "+f"(t1[mt][nf][0]), "+f"(t1[mt][nf][1]),
                          "+f"(t1[mt][nf][2]), "+f"(t1[mt][nf][3])
                        : "r"(al[mt][0]), "r"(al[mt][1]), "r"(al[mt][2]), "r"(al[mt][3]),
                          "r"(bh[nf * 2]), "r"(bh[nf * 2 + 1]));
                    asm volatile(
                        "mma.sync.aligned.m16n8k16.row.col.f32.bf16.bf16.f32 "
                        "{%0,%1,%2,%3}, {%4,%5,%6,%7}, {%8,%9}, {%0,%1,%2,%3};"
                        : "+f"(t2[mt][nf][0]), "+f"(t2[mt][nf][1]),
                          "+f"(t2[mt][nf][2]), "+f"(t2[mt][nf][3])
                        : "r"(ah[mt][0]), "r"(ah[mt][1]), "r"(ah[mt][2]), "r"(ah[mt][3]),
                          "r"(bl[nf * 2]), "r"(bl[nf * 2 + 1]));
                }
        }

        // ---- write k-partials to gate buffer (scalar: pitch 33 odd) ----
#pragma unroll
        for (int mt = 0; mt < 2; mt++) {
            int r0 = wm * 32 + mt * 16 + gid;
#pragma unroll
            for (int nf = 0; nf < 2; nf++) {
                int cl = wn * 16 + nf * 8 + 2 * tg;
                gbuf[r0 * 33 + cl]           = t0[mt][nf][0] + t1[mt][nf][0] + t2[mt][nf][0];
                gbuf[r0 * 33 + cl + 1]       = t0[mt][nf][1] + t1[mt][nf][1] + t2[mt][nf][1];
                gbuf[(r0 + 8) * 33 + cl]     = t0[mt][nf][2] + t1[mt][nf][2] + t2[mt][nf][2];
                gbuf[(r0 + 8) * 33 + cl + 1] = t0[mt][nf][3] + t1[mt][nf][3] + t2[mt][nf][3];
            }
        }
        __syncthreads();

        // ---- epilogue: two units (u2, u2+1) of batch bown; direct writeback ----
        {
            float a0[4], a1[4];
#pragma unroll
            for (int g = 0; g < 4; g++) {
                int r0 = g * 16 + u2;
                a0[g] = g0f[r0 * 33 + bown] + g1f[r0 * 33 + bown];
                a1[g] = g0f[(r0 + 1) * 33 + bown] + g1f[(r0 + 1) * 33 + bown];
            }
            float gi0 = pg[0].x + a0[0], gi1 = pg[0].y + a1[0];
            float gf0 = pg[1].x + a0[1], gf1 = pg[1].y + a1[1];
            float gg0 = pg[2].x + a0[2], gg1 = pg[2].y + a1[2];
            float go0 = pg[3].x + a0[3], go1 = pg[3].y + a1[3];
            float si0 = 1.0f / (1.0f + expf(-gi0)), si1 = 1.0f / (1.0f + expf(-gi1));
            float sf0 = 1.0f / (1.0f + expf(-gf0)), sf1 = 1.0f / (1.0f + expf(-gf1));
            float so0 = 1.0f / (1.0f + expf(-go0)), so1 = 1.0f / (1.0f + expf(-go1));
            cst0 = sf0 * cst0 + si0 * tanhf(gg0);
            cst1 = sf1 * cst1 + si1 * tanhf(gg1);
            float h20 = so0 * tanhf(cst0);
            float h21 = so1 * tanhf(cst1);
            __nv_bfloat16 hh0 = __float2bfloat16(h20);
            __nv_bfloat16 hh1 = __float2bfloat16(h21);
            __nv_bfloat16 hl0 = __float2bfloat16(h20 - __bfloat162float(hh0));
            __nv_bfloat16 hl1 = __float2bfloat16(h21 - __bfloat162float(hh1));
            int bg = b0 + bown;
            size_t hoff = (size_t)bg * HH + u0 + u2;
            __stcg((__nv_bfloat162*)&houtH[hoff], __nv_bfloat162(hh0, hh1));
            __stcg((__nv_bfloat162*)&houtL[hoff], __nv_bfloat162(hl0, hl1));
            size_t orow = out_mode ? ((size_t)bg * LL + t) : ((size_t)t * BB + bg);
            *(float2*)(outbuf + orow * (2 * HH) + dir * HH + u0 + u2) = make_float2(h20, h21);
        }

        // ---- group barrier across 32 CTAs (dir,bs) ----
        __threadfence();
        __syncthreads();
        if (tid == 0) {
            atomicAdd((unsigned*)gbar, 1u);
            unsigned target = (unsigned)(s + 1) * 32u;
            while (*gbar < target) { }
        }
        __syncthreads();
    }
}

// ---------------- host launcher ----------------
extern "C" void kernel_launch(void* const* d_in, const int* in_sizes, int n_in,
                              void* d_out, int out_size)
{
    const float* x       = (const float*)d_in[0];
    const float* Wih_f0  = (const float*)d_in[1];
    const float* Whh_f0  = (const float*)d_in[2];
    const float* bih_f0  = (const float*)d_in[3];
    const float* bhh_f0  = (const float*)d_in[4];
    const float* Wih_r0  = (const float*)d_in[5];
    const float* Whh_r0  = (const float*)d_in[6];
    const float* bih_r0  = (const float*)d_in[7];
    const float* bhh_r0  = (const float*)d_in[8];
    const float* Wih_f1  = (const float*)d_in[9];
    const float* Whh_f1  = (const float*)d_in[10];
    const float* bih_f1  = (const float*)d_in[11];
    const float* bhh_f1  = (const float*)d_in[12];
    const float* Wih_r1  = (const float*)d_in[13];
    const float* Whh_r1  = (const float*)d_in[14];
    const float* bih_r1  = (const float*)d_in[15];
    const float* bhh_r1  = (const float*)d_in[16];

    float *xT, *gf, *gr, *hcat;
    unsigned* bar4;
    __nv_bfloat16 *Ahi, *Alo, *Wfhi, *Wflo, *Wrhi, *Wrlo;
    __nv_bfloat16 *WhfHi, *WhfLo, *WhrHi, *WhrLo, *shi, *slo;
    cudaGetSymbolAddress((void**)&xT,    g_xT);
    cudaGetSymbolAddress((void**)&gf,    g_gates_f);
    cudaGetSymbolAddress((void**)&gr,    g_gates_r);
    cudaGetSymbolAddress((void**)&hcat,  g_hcat);
    cudaGetSymbolAddress((void**)&bar4,  g_bar4);
    cudaGetSymbolAddress((void**)&Ahi,   g_Ahi);
    cudaGetSymbolAddress((void**)&Alo,   g_Alo);
    cudaGetSymbolAddress((void**)&Wfhi,  g_Wfhi);
    cudaGetSymbolAddress((void**)&Wflo,  g_Wflo);
    cudaGetSymbolAddress((void**)&Wrhi,  g_Wrhi);
    cudaGetSymbolAddress((void**)&Wrlo,  g_Wrlo);
    cudaGetSymbolAddress((void**)&WhfHi, g_WhfHi);
    cudaGetSymbolAddress((void**)&WhfLo, g_WhfLo);
    cudaGetSymbolAddress((void**)&WhrHi, g_WhrHi);
    cudaGetSymbolAddress((void**)&WhrLo, g_WhrLo);
    cudaGetSymbolAddress((void**)&shi,   g_shi);
    cudaGetSymbolAddress((void**)&slo,   g_slo);

    cudaFuncSetAttribute(gemm_bf16s,    cudaFuncAttributeMaxDynamicSharedMemorySize, GB_SMEM);
    cudaFuncSetAttribute(lstm_layer_tc, cudaFuncAttributeMaxDynamicSharedMemorySize, RK_SMEM);

    const int M = LL * BB;   // 32768
    const int whn4 = (G4 * HH) / 4;

    transpose_x<<<8192, 256>>>((const float4*)x, (float4*)xT);

    dim3 ggrid(G4 / 256, M / 128);   // (8, 256)

    // ---- layer 0 (K = 256) ----
    {
        int n4 = (LL * BB * II) / 4;
        split_bf16<<<(n4 + 255) / 256, 256>>>((const float4*)xT,
            (__nv_bfloat162*)Ahi, (__nv_bfloat162*)Alo, n4);
        int w4 = (G4 * II) / 4;
        split_bf16<<<(w4 + 255) / 256, 256>>>((const float4*)Wih_f0,
            (__nv_bfloat162*)Wfhi, (__nv_bfloat162*)Wflo, w4);
        split_bf16<<<(w4 + 255) / 256, 256>>>((const float4*)Wih_r0,
            (__nv_bfloat162*)Wrhi, (__nv_bfloat162*)Wrlo, w4);
        gemm_bf16s<<<ggrid, 256, GB_SMEM>>>(M, G4, II, Ahi, Alo, Wfhi, Wflo, bih_f0, bhh_f0, gf);
        gemm_bf16s<<<ggrid, 256, GB_SMEM>>>(M, G4, II, Ahi, Alo, Wrhi, Wrlo, bih_r0, bhh_r0, gr);
        split_bf16<<<(whn4 + 255) / 256, 256>>>((const float4*)Whh_f0,
            (__nv_bfloat162*)WhfHi, (__nv_bfloat162*)WhfLo, whn4);
        split_bf16<<<(whn4 + 255) / 256, 256>>>((const float4*)Whh_r0,
            (__nv_bfloat162*)WhrHi, (__nv_bfloat162*)WhrLo, whn4);
    }
    cudaMemsetAsync(shi, 0, sizeof(__nv_bfloat16) * 2 * 2 * BB * HH, 0);
    cudaMemsetAsync(slo, 0, sizeof(__nv_bfloat16) * 2 * 2 * BB * HH, 0);
    cudaMemsetAsync(bar4, 0, sizeof(unsigned) * 4 * 32, 0);
    lstm_layer_tc<<<128, 256, RK_SMEM>>>(gf, gr, WhfHi, WhfLo, WhrHi, WhrLo,
                                         shi, slo, hcat, 0);

    // ---- layer 1 (K = 1024) ----
    {
        int n4 = (LL * BB * 2 * HH) / 4;
        split_bf16<<<(n4 + 255) / 256, 256>>>((const float4*)hcat,
            (__nv_bfloat162*)Ahi, (__nv_bfloat162*)Alo, n4);
        int w4 = (G4 * 2 * HH) / 4;
        split_bf16<<<(w4 + 255) / 256, 256>>>((const float4*)Wih_f1,
            (__nv_bfloat162*)Wfhi, (__nv_bfloat162*)Wflo, w4);
        split_bf16<<<(w4 + 255) / 256, 256>>>((const float4*)Wih_r1,
            (__nv_bfloat162*)Wrhi, (__nv_bfloat162*)Wrlo, w4);
        gemm_bf16s<<<ggrid, 256, GB_SMEM>>>(M, G4, 2 * HH, Ahi, Alo, Wfhi, Wflo, bih_f1, bhh_f1, gf);
        gemm_bf16s<<<ggrid, 256, GB_SMEM>>>(M, G4, 2 * HH, Ahi, Alo, Wrhi, Wrlo, bih_r1, bhh_r1, gr);
        split_bf16<<<(whn4 + 255) / 256, 256>>>((const float4*)Whh_f1,
            (__nv_bfloat162*)WhfHi, (__nv_bfloat162*)WhfLo, whn4);
        split_bf16<<<(whn4 + 255) / 256, 256>>>((const float4*)Whh_r1,
            (__nv_bfloat162*)WhrHi, (__nv_bfloat162*)WhrLo, whn4);
    }
    cudaMemsetAsync(shi, 0, sizeof(__nv_bfloat16) * 2 * 2 * BB * HH, 0);
    cudaMemsetAsync(slo, 0, sizeof(__nv_bfloat16) * 2 * 2 * BB * HH, 0);
    cudaMemsetAsync(bar4, 0, sizeof(unsigned) * 4 * 32, 0);
    lstm_layer_tc<<<128, 256, RK_SMEM>>>(gf, gr, WhfHi, WhfLo, WhrHi, WhrLo,
                                         shi, slo, (float*)d_out, 1);
}

// round 10
// speedup vs baseline: 2.9515x; 1.0242x over previous
#include <cuda_runtime.h>
#include <cuda_bf16.h>
#include <math.h>
#include <cstdint>

// Problem dims
#define LL 512
#define BB 64
#define II 256
#define HH 512
#define G4 2048   // 4*H

// ---------------- scratch (static device globals; no allocation) ----------------
__device__ float g_xT[(size_t)LL * BB * II];          // [t][b][I]
__device__ float g_gates_f[(size_t)LL * BB * G4];     // [t][b][4H]
__device__ float g_gates_r[(size_t)LL * BB * G4];     // [t][b][4H]
__device__ float g_hcat[(size_t)LL * BB * 2 * HH];    // [t][b][2H]
__device__ unsigned g_bar4[4 * 32];                   // 4 group barriers, 128B apart

// h state as bf16 hi/lo: [dir][parity][b][u]
__device__ __align__(16) __nv_bfloat16 g_shi[2 * 2 * BB * HH];
__device__ __align__(16) __nv_bfloat16 g_slo[2 * 2 * BB * HH];

// bf16 split buffers (input GEMM operands)
__device__ __align__(16) __nv_bfloat16 g_Ahi[(size_t)LL * BB * 2 * HH];
__device__ __align__(16) __nv_bfloat16 g_Alo[(size_t)LL * BB * 2 * HH];
__device__ __align__(16) __nv_bfloat16 g_Wfhi[(size_t)G4 * 2 * HH];
__device__ __align__(16) __nv_bfloat16 g_Wflo[(size_t)G4 * 2 * HH];
__device__ __align__(16) __nv_bfloat16 g_Wrhi[(size_t)G4 * 2 * HH];
__device__ __align__(16) __nv_bfloat16 g_Wrlo[(size_t)G4 * 2 * HH];
// Whh splits for the recurrence ([2048][512] each)
__device__ __align__(16) __nv_bfloat16 g_WhfHi[(size_t)G4 * HH];
__device__ __align__(16) __nv_bfloat16 g_WhfLo[(size_t)G4 * HH];
__device__ __align__(16) __nv_bfloat16 g_WhrHi[(size_t)G4 * HH];
__device__ __align__(16) __nv_bfloat16 g_WhrLo[(size_t)G4 * HH];

__device__ __forceinline__ uint32_t smem_u32(const void* p) {
    uint32_t a;
    asm("{ .reg .u64 t; cvta.to.shared.u64 t, %1; cvt.u32.u64 %0, t; }" : "=r"(a) : "l"(p));
    return a;
}

__device__ __forceinline__ float fsig(float x) {
    return 1.0f / (1.0f + __expf(-x));
}
__device__ __forceinline__ float ftanh(float x) {
    return fmaf(2.0f, fsig(2.0f * x), -1.0f);
}

// ---------------- transpose x[b][l][i] -> xT[l][b][i] ----------------
__global__ void transpose_x(const float4* __restrict__ x, float4* __restrict__ xT) {
    int idx = blockIdx.x * blockDim.x + threadIdx.x;
    int i4 = idx & 63;
    int m  = idx >> 6;
    int t  = m >> 6;
    int b  = m & 63;
    xT[idx] = x[((size_t)(b * LL + t)) * 64 + i4];
}

// ---------------- fp32 -> bf16 hi/lo split ----------------
__global__ void split_bf16(const float4* __restrict__ src,
                           __nv_bfloat162* __restrict__ hi,
                           __nv_bfloat162* __restrict__ lo, int n4) {
    int i = blockIdx.x * blockDim.x + threadIdx.x;
    if (i >= n4) return;
    float4 v = src[i];
    __nv_bfloat16 hx = __float2bfloat16(v.x);
    __nv_bfloat16 hy = __float2bfloat16(v.y);
    __nv_bfloat16 hz = __float2bfloat16(v.z);
    __nv_bfloat16 hw = __float2bfloat16(v.w);
    __nv_bfloat16 lx = __float2bfloat16(v.x - __bfloat162float(hx));
    __nv_bfloat16 ly = __float2bfloat16(v.y - __bfloat162float(hy));
    __nv_bfloat16 lz = __float2bfloat16(v.z - __bfloat162float(hz));
    __nv_bfloat16 lw = __float2bfloat16(v.w - __bfloat162float(hw));
    hi[i * 2 + 0] = __nv_bfloat162(hx, hy);
    hi[i * 2 + 1] = __nv_bfloat162(hz, hw);
    lo[i * 2 + 0] = __nv_bfloat162(lx, ly);
    lo[i * 2 + 1] = __nv_bfloat162(lz, lw);
}

// ---------------- bf16 split-GEMM: 128x128 block, 2-stage, 2 CTAs/SM ----------------
#define GBK   32
#define GTILE 10240                 // 128 * 80
#define GSTG  (4 * GTILE)           // Ahi, Alo, Bhi, Blo = 40960
#define GB_SMEM (2 * GSTG + 512)    // 82432; x2 CTAs = 164864 <= 227KB

__global__ __launch_bounds__(256, 2) void gemm_bf16s(
    int M, int N, int K,
    const __nv_bfloat16* __restrict__ Ahi, const __nv_bfloat16* __restrict__ Alo,
    const __nv_bfloat16* __restrict__ Bhi, const __nv_bfloat16* __restrict__ Blo,
    const float* __restrict__ bias1, const float* __restrict__ bias2,
    float* __restrict__ C)
{
    extern __shared__ char sm[];
    uint32_t sb = smem_u32(sm);
    int tid  = threadIdx.x;
    int lane = tid & 31;
    int warp = tid >> 5;
    int gid  = lane >> 2;
    int tg   = lane & 3;
    int wm   = warp >> 2;     // 0..1 (64 rows)
    int wn   = warp & 3;      // 0..3 (32 cols)
    int n0   = blockIdx.x * 128;
    int m0   = blockIdx.y * 128;

    float* shb = (float*)(sm + 2 * GSTG);
    if (tid < 128) shb[tid] = bias1[n0 + tid] + bias2[n0 + tid];

    const char* srcs[4];
    srcs[0] = (const char*)(Ahi + (size_t)m0 * K);
    srcs[1] = (const char*)(Alo + (size_t)m0 * K);
    srcs[2] = (const char*)(Bhi + (size_t)n0 * K);
    srcs[3] = (const char*)(Blo + (size_t)n0 * K);

#define LOAD_STAGE(kc, bufsel)                                                      \
    {                                                                               \
        _Pragma("unroll")                                                           \
        for (int j = 0; j < 8; j++) {                                               \
            int c    = tid + j * 256;                                               \
            int tile = c >> 9;                                                      \
            int cc   = c & 511;                                                     \
            int row  = cc >> 2, g = cc & 3;                                         \
            uint32_t d = sb + (bufsel) * GSTG + tile * GTILE + row * 80 + g * 16;   \
            const char* s = srcs[tile] + ((size_t)row * K + (kc) * GBK) * 2 + g * 16; \
            asm volatile("cp.async.ca.shared.global [%0], [%1], 16;" :: "r"(d), "l"(s)); \
        }                                                                           \
        asm volatile("cp.async.commit_group;" ::: "memory");                        \
    }

    float acc[4][4][4];
#pragma unroll
    for (int i = 0; i < 4; i++)
#pragma unroll
        for (int j = 0; j < 4; j++)
#pragma unroll
            for (int r = 0; r < 4; r++) acc[i][j][r] = 0.0f;

    int nk = K / GBK;   // >= 8
    LOAD_STAGE(0, 0);
    LOAD_STAGE(1, 1);

    for (int kc = 0; kc < nk; kc++) {
        if (kc + 1 < nk)
            asm volatile("cp.async.wait_group 1;" ::: "memory");
        else
            asm volatile("cp.async.wait_group 0;" ::: "memory");
        __syncthreads();

        int buf = kc & 1;
        uint32_t bAh = sb + buf * GSTG;
        uint32_t bAl = bAh + GTILE;
        uint32_t bBh = bAh + 2 * GTILE;
        uint32_t bBl = bAh + 3 * GTILE;

        uint32_t aoff = (uint32_t)(wm * 64 + (lane & 15)) * 80 + (lane >> 4) * 16;
        uint32_t boff = (uint32_t)(wn * 32 + (lane & 7)) * 80 + ((lane >> 3) & 1) * 16;

#pragma unroll
        for (int ks = 0; ks < 2; ks++) {
            uint32_t ko = ks * 32;
            uint32_t ah[4][4], al[4][4];
#pragma unroll
            for (int mt = 0; mt < 4; mt++) {
                asm volatile("ldmatrix.sync.aligned.m8n8.x4.shared.b16 {%0,%1,%2,%3}, [%4];"
                    : "=r"(ah[mt][0]), "=r"(ah[mt][1]), "=r"(ah[mt][2]), "=r"(ah[mt][3])
                    : "r"(bAh + aoff + ko + mt * (16 * 80)));
                asm volatile("ldmatrix.sync.aligned.m8n8.x4.shared.b16 {%0,%1,%2,%3}, [%4];"
                    : "=r"(al[mt][0]), "=r"(al[mt][1]), "=r"(al[mt][2]), "=r"(al[mt][3])
                    : "r"(bAl + aoff + ko + mt * (16 * 80)));
            }
            uint32_t bh[4][2], bl[4][2];
#pragma unroll
            for (int nt = 0; nt < 4; nt++) {
                asm volatile("ldmatrix.sync.aligned.m8n8.x2.shared.b16 {%0,%1}, [%2];"
                    : "=r"(bh[nt][0]), "=r"(bh[nt][1]) : "r"(bBh + boff + ko + nt * (8 * 80)));
                asm volatile("ldmatrix.sync.aligned.m8n8.x2.shared.b16 {%0,%1}, [%2];"
                    : "=r"(bl[nt][0]), "=r"(bl[nt][1]) : "r"(bBl + boff + ko + nt * (8 * 80)));
            }
#pragma unroll
            for (int mt = 0; mt < 4; mt++)
#pragma unroll
                for (int nt = 0; nt < 4; nt++) {
                    asm volatile(
                        "mma.sync.aligned.m16n8k16.row.col.f32.bf16.bf16.f32 "
                        "{%0,%1,%2,%3}, {%4,%5,%6,%7}, {%8,%9}, {%0,%1,%2,%3};"
                        : "+f"(acc[mt][nt][0]), "+f"(acc[mt][nt][1]),
                          "+f"(acc[mt][nt][2]), "+f"(acc[mt][nt][3])
                        : "r"(ah[mt][0]), "r"(ah[mt][1]), "r"(ah[mt][2]), "r"(ah[mt][3]),
                          "r"(bh[nt][0]), "r"(bh[nt][1]));
                    asm volatile(
                        "mma.sync.aligned.m16n8k16.row.col.f32.bf16.bf16.f32 "
                        "{%0,%1,%2,%3}, {%4,%5,%6,%7}, {%8,%9}, {%0,%1,%2,%3};"
                        : "+f"(acc[mt][nt][0]), "+f"(acc[mt][nt][1]),
                          "+f"(acc[mt][nt][2]), "+f"(acc[mt][nt][3])
                        : "r"(al[mt][0]), "r"(al[mt][1]), "r"(al[mt][2]), "r"(al[mt][3]),
                          "r"(bh[nt][0]), "r"(bh[nt][1]));
                    asm volatile(
                        "mma.sync.aligned.m16n8k16.row.col.f32.bf16.bf16.f32 "
                        "{%0,%1,%2,%3}, {%4,%5,%6,%7}, {%8,%9}, {%0,%1,%2,%3};"
                        : "+f"(acc[mt][nt][0]), "+f"(acc[mt][nt][1]),
                          "+f"(acc[mt][nt][2]), "+f"(acc[mt][nt][3])
                        : "r"(ah[mt][0]), "r"(ah[mt][1]), "r"(ah[mt][2]), "r"(ah[mt][3]),
                          "r"(bl[nt][0]), "r"(bl[nt][1]));
                }
        }
        __syncthreads();
        if (kc + 2 < nk) LOAD_STAGE(kc + 2, buf);
    }

#pragma unroll
    for (int mt = 0; mt < 4; mt++) {
        int r0 = m0 + wm * 64 + mt * 16 + gid;
#pragma unroll
        for (int nt = 0; nt < 4; nt++) {
            int cl = wn * 32 + nt * 8 + 2 * tg;
            float b0 = shb[cl], b1 = shb[cl + 1];
            *(float2*)(C + (size_t)r0 * N + n0 + cl) =
                make_float2(acc[mt][nt][0] + b0, acc[mt][nt][1] + b1);
            *(float2*)(C + (size_t)(r0 + 8) * N + n0 + cl) =
                make_float2(acc[mt][nt][2] + b0, acc[mt][nt][3] + b1);
        }
    }
}

// ---------------- persistent tensor-core LSTM layer ----------------
#define RP     1040
#define OFF_AHI 0
#define OFF_ALO (64 * RP)
#define OFF_BHI (2 * 64 * RP)
#define OFF_BLO (2 * 64 * RP + 32 * RP)
#define OFF_G0  (2 * 64 * RP + 2 * 32 * RP)
#define OFF_G1  (OFF_G0 + 64 * 33 * 4)
#define RK_SMEM (OFF_G1 + 64 * 33 * 4)   // 216576

__global__ __launch_bounds__(256, 1) void lstm_layer_tc(
    const float* __restrict__ gates_f,
    const float* __restrict__ gates_r,
    const __nv_bfloat16* __restrict__ WhfHi, const __nv_bfloat16* __restrict__ WhfLo,
    const __nv_bfloat16* __restrict__ WhrHi, const __nv_bfloat16* __restrict__ WhrLo,
    __nv_bfloat16* __restrict__ shi,
    __nv_bfloat16* __restrict__ slo,
    float* __restrict__ outbuf,
    int out_mode)
{
    extern __shared__ char sm[];
    uint32_t sb = smem_u32(sm);
    int tid  = threadIdx.x;
    int lane = tid & 31;
    int warp = tid >> 5;
    int gid  = lane >> 2;
    int tg   = lane & 3;

    int bx  = blockIdx.x;
    int dir = bx >> 6;
    int us  = (bx >> 1) & 31;
    int bs  = bx & 1;
    int u0  = us * 16;
    int b0  = bs * 32;
    int grp = dir * 2 + bs;
    unsigned* gbar = (unsigned*)&g_bar4[grp * 32];

    const float* gates = dir ? gates_r : gates_f;
    const __nv_bfloat16* whH = dir ? WhrHi : WhfHi;
    const __nv_bfloat16* whL = dir ? WhrLo : WhfLo;

    // ---- stage Whh slice once ----
#pragma unroll
    for (int j = 0; j < 16; j++) {
        int idx = tid + j * 256;
        int row = idx >> 6;
        int ch  = idx & 63;
        int g   = row >> 4;
        int ul  = row & 15;
        size_t soff = (size_t)(g * HH + u0 + ul) * HH + ch * 8;
        *(uint4*)(sm + OFF_AHI + row * RP + ch * 16) = *(const uint4*)(whH + soff);
        *(uint4*)(sm + OFF_ALO + row * RP + ch * 16) = *(const uint4*)(whL + soff);
    }

    int wk = warp >> 2;
    int wm = (warp >> 1) & 1;
    int wn = warp & 1;
    uint32_t apat = (uint32_t)(lane & 15) * RP + (lane >> 4) * 16;
    uint32_t bpat = (uint32_t)((lane & 7) + ((lane >> 4) << 3)) * RP + ((lane >> 3) & 1) * 16;
    uint32_t aBaseHi = sb + OFF_AHI + wm * 32 * RP + apat;
    uint32_t aBaseLo = sb + OFF_ALO + wm * 32 * RP + apat;
    uint32_t bBaseHi = sb + OFF_BHI + wn * 16 * RP + bpat;
    uint32_t bBaseLo = sb + OFF_BLO + wn * 16 * RP + bpat;
    float* gbuf = (float*)(sm + (wk ? OFF_G1 : OFF_G0));
    float* g0f  = (float*)(sm + OFF_G0);
    float* g1f  = (float*)(sm + OFF_G1);

    // epilogue ownership: b = tid>>3 (0..31), u2 = (tid&7)*2 (0..14)
    int bown = tid >> 3;
    int u2   = (tid & 7) * 2;
    float cst0 = 0.0f, cst1 = 0.0f;

    for (int s = 0; s < LL; s++) {
        int t   = dir ? (LL - 1 - s) : s;
        int par = s & 1;
        const __nv_bfloat16* hinH = shi + ((dir * 2 + par) * BB) * HH;
        const __nv_bfloat16* hinL = slo + ((dir * 2 + par) * BB) * HH;
        __nv_bfloat16* houtH = shi + ((dir * 2 + (par ^ 1)) * BB) * HH;
        __nv_bfloat16* houtL = slo + ((dir * 2 + (par ^ 1)) * BB) * HH;

        // ---- prefetch this thread's gate inputs (float2 per gate) ----
        float2 pg[4];
        {
            size_t gbase = ((size_t)t * BB + (b0 + bown)) * G4 + (u0 + u2);
#pragma unroll
            for (int g = 0; g < 4; g++)
                pg[g] = __ldcg((const float2*)&gates[gbase + g * HH]);
        }

        // ---- stage h tile (32 b x 512) hi/lo ----
#pragma unroll
        for (int j = 0; j < 8; j++) {
            int idx = tid + j * 256;
            int row = idx >> 6;
            int ch  = idx & 63;
            size_t soff = (size_t)(b0 + row) * HH + ch * 8;
            uint4 vh = __ldcg((const uint4*)(hinH + soff));
            uint4 vl = __ldcg((const uint4*)(hinL + soff));
            *(uint4*)(sm + OFF_BHI + row * RP + ch * 16) = vh;
            *(uint4*)(sm + OFF_BLO + row * RP + ch * 16) = vl;
        }
        __syncthreads();

        // ---- 3-term HMMA over this warp's 16 k-chunks ----
        float t0[2][2][4], t1[2][2][4], t2[2][2][4];
#pragma unroll
        for (int i = 0; i < 2; i++)
#pragma unroll
            for (int j = 0; j < 2; j++)
#pragma unroll
                for (int r = 0; r < 4; r++) { t0[i][j][r] = 0.f; t1[i][j][r] = 0.f; t2[i][j][r] = 0.f; }

#pragma unroll 4
        for (int kc = 0; kc < 16; kc++) {
            uint32_t kb = (uint32_t)(wk * 16 + kc) * 32;
            uint32_t ah[2][4], al[2][4];
#pragma unroll
            for (int mt = 0; mt < 2; mt++) {
                asm volatile("ldmatrix.sync.aligned.m8n8.x4.shared.b16 {%0,%1,%2,%3}, [%4];"
                    : "=r"(ah[mt][0]), "=r"(ah[mt][1]), "=r"(ah[mt][2]), "=r"(ah[mt][3])
                    : "r"(aBaseHi + kb + mt * (16 * RP)));
                asm volatile("ldmatrix.sync.aligned.m8n8.x4.shared.b16 {%0,%1,%2,%3}, [%4];"
                    : "=r"(al[mt][0]), "=r"(al[mt][1]), "=r"(al[mt][2]), "=r"(al[mt][3])
                    : "r"(aBaseLo + kb + mt * (16 * RP)));
            }
            uint32_t bh[4], bl[4];
            asm volatile("ldmatrix.sync.aligned.m8n8.x4.shared.b16 {%0,%1,%2,%3}, [%4];"
                : "=r"(bh[0]), "=r"(bh[1]), "=r"(bh[2]), "=r"(bh[3]) : "r"(bBaseHi + kb));
            asm volatile("ldmatrix.sync.aligned.m8n8.x4.shared.b16 {%0,%1,%2,%3}, [%4];"
                : "=r"(bl[0]), "=r"(bl[1]), "=r"(bl[2]), "=r"(bl[3]) : "r"(bBaseLo + kb));
#pragma unroll
            for (int mt = 0; mt < 2; mt++)
#pragma unroll
                for (int nf = 0; nf < 2; nf++) {
                    asm volatile(
                        "mma.sync.aligned.m16n8k16.row.col.f32.bf16.bf16.f32 "
                        "{%0,%1,%2,%3}, {%4,%5,%6,%7}, {%8,%9}, {%0,%1,%2,%3};"
                        : "+f"(t0[mt][nf][0]), "+f"(t0[mt][nf][1]),
                          "+f"(t0[mt][nf][2]), "+f"(t0[mt][nf][3])
                        : "r"(ah[mt][0]), "r"(ah[mt][1]), "r"(ah[mt][2]), "r"(ah[mt][3]),
                          "r"(bh[nf * 2]), "r"(bh[nf * 2 + 1]));
                    asm volatile(
                        "mma.sync.aligned.m16n8k16.row.col.f32.bf16.bf16.f32 "
                        "{%0,%1,%2,%3}, {%4,%5,%6,%7}, {%8,%9}, {%0,%1,%2,%3};"
                        : "+f"(t1[mt][nf][0]), "+f"(t1[mt][nf][1]),
                          "+f"(t1[mt][nf][2]), "+f"(t1[mt][nf][3])
                        : "r"(al[mt][0]), "r"(al[mt][1]), "r"(al[mt][2]), "r"(al[mt][3]),
                          "r"(bh[nf * 2]), "r"(bh[nf * 2 + 1]));
                    asm volatile(
                        "mma.sync.aligned.m16n8k16.row.col.f32.bf16.bf16.f32 "
                        "{%0,%1,%2,%3}, {%4,%5,%6,%7}, {%8,%9}, {%0,%1,%2,%3};"
                        : "+f"(t2[mt][nf][0]), "+f"(t2[mt][nf][1]),
                          "+f"(t2[mt][nf][2]), "+f"(t2[mt][nf][3])
                        : "r"(ah[mt][0]), "r"(ah[mt][1]), "r"(ah[mt][2]), "r"(ah[mt][3]),
                          "r"(bl[nf * 2]), "r"(bl[nf * 2 + 1]));
                }
        }

        // ---- write k-partials to gate buffer (scalar: pitch 33 odd) ----
#pragma unroll
        for (int mt = 0; mt < 2; mt++) {
            int r0 = wm * 32 + mt * 16 + gid;
#pragma unroll
            for (int nf = 0; nf < 2; nf++) {
                int cl = wn * 16 + nf * 8 + 2 * tg;
                gbuf[r0 * 33 + cl]           = t0[mt][nf][0] + t1[mt][nf][0] + t2[mt][nf][0];
                gbuf[r0 * 33 + cl + 1]       = t0[mt][nf][1] + t1[mt][nf][1] + t2[mt][nf][1];
                gbuf[(r0 + 8) * 33 + cl]     = t0[mt][nf][2] + t1[mt][nf][2] + t2[mt][nf][2];
                gbuf[(r0 + 8) * 33 + cl + 1] = t0[mt][nf][3] + t1[mt][nf][3] + t2[mt][nf][3];
            }
        }
        __syncthreads();

        // ---- epilogue: two units (u2, u2+1) of batch bown; direct writeback ----
        {
            float a0[4], a1[4];
#pragma unroll
            for (int g = 0; g < 4; g++) {
                int r0 = g * 16 + u2;
                a0[g] = g0f[r0 * 33 + bown] + g1f[r0 * 33 + bown];
                a1[g] = g0f[(r0 + 1) * 33 + bown] + g1f[(r0 + 1) * 33 + bown];
            }
            float gi0 = pg[0].x + a0[0], gi1 = pg[0].y + a1[0];
            float gf0 = pg[1].x + a0[1], gf1 = pg[1].y + a1[1];
            float gg0 = pg[2].x + a0[2], gg1 = pg[2].y + a1[2];
            float go0 = pg[3].x + a0[3], go1 = pg[3].y + a1[3];
            float si0 = fsig(gi0), si1 = fsig(gi1);
            float sf0 = fsig(gf0), sf1 = fsig(gf1);
            float so0 = fsig(go0), so1 = fsig(go1);
            cst0 = sf0 * cst0 + si0 * ftanh(gg0);
            cst1 = sf1 * cst1 + si1 * ftanh(gg1);
            float h20 = so0 * ftanh(cst0);
            float h21 = so1 * ftanh(cst1);
            __nv_bfloat16 hh0 = __float2bfloat16(h20);
            __nv_bfloat16 hh1 = __float2bfloat16(h21);
            __nv_bfloat16 hl0 = __float2bfloat16(h20 - __bfloat162float(hh0));
            __nv_bfloat16 hl1 = __float2bfloat16(h21 - __bfloat162float(hh1));
            int bg = b0 + bown;
            size_t hoff = (size_t)bg * HH + u0 + u2;
            __stcg((__nv_bfloat162*)&houtH[hoff], __nv_bfloat162(hh0, hh1));
            __stcg((__nv_bfloat162*)&houtL[hoff], __nv_bfloat162(hl0, hl1));
            size_t orow = out_mode ? ((size_t)bg * LL + t) : ((size_t)t * BB + bg);
            *(float2*)(outbuf + orow * (2 * HH) + dir * HH + u0 + u2) = make_float2(h20, h21);
        }

        // ---- group barrier across 32 CTAs: release-add + acquire-poll ----
        __syncthreads();
        if (tid == 0) {
            unsigned target = (unsigned)(s + 1) * 32u;
            asm volatile("red.release.gpu.global.add.u32 [%0], %1;"
                         :: "l"(gbar), "r"(1u) : "memory");
            unsigned v;
            do {
                asm volatile("ld.acquire.gpu.global.u32 %0, [%1];"
                             : "=r"(v) : "l"(gbar) : "memory");
            } while (v < target);
        }
        __syncthreads();
    }
}

// ---------------- host launcher ----------------
extern "C" void kernel_launch(void* const* d_in, const int* in_sizes, int n_in,
                              void* d_out, int out_size)
{
    const float* x       = (const float*)d_in[0];
    const float* Wih_f0  = (const float*)d_in[1];
    const float* Whh_f0  = (const float*)d_in[2];
    const float* bih_f0  = (const float*)d_in[3];
    const float* bhh_f0  = (const float*)d_in[4];
    const float* Wih_r0  = (const float*)d_in[5];
    const float* Whh_r0  = (const float*)d_in[6];
    const float* bih_r0  = (const float*)d_in[7];
    const float* bhh_r0  = (const float*)d_in[8];
    const float* Wih_f1  = (const float*)d_in[9];
    const float* Whh_f1  = (const float*)d_in[10];
    const float* bih_f1  = (const float*)d_in[11];
    const float* bhh_f1  = (const float*)d_in[12];
    const float* Wih_r1  = (const float*)d_in[13];
    const float* Whh_r1  = (const float*)d_in[14];
    const float* bih_r1  = (const float*)d_in[15];
    const float* bhh_r1  = (const float*)d_in[16];

    float *xT, *gf, *gr, *hcat;
    unsigned* bar4;
    __nv_bfloat16 *Ahi, *Alo, *Wfhi, *Wflo, *Wrhi, *Wrlo;
    __nv_bfloat16 *WhfHi, *WhfLo, *WhrHi, *WhrLo, *shi, *slo;
    cudaGetSymbolAddress((void**)&xT,    g_xT);
    cudaGetSymbolAddress((void**)&gf,    g_gates_f);
    cudaGetSymbolAddress((void**)&gr,    g_gates_r);
    cudaGetSymbolAddress((void**)&hcat,  g_hcat);
    cudaGetSymbolAddress((void**)&bar4,  g_bar4);
    cudaGetSymbolAddress((void**)&Ahi,   g_Ahi);
    cudaGetSymbolAddress((void**)&Alo,   g_Alo);
    cudaGetSymbolAddress((void**)&Wfhi,  g_Wfhi);
    cudaGetSymbolAddress((void**)&Wflo,  g_Wflo);
    cudaGetSymbolAddress((void**)&Wrhi,  g_Wrhi);
    cudaGetSymbolAddress((void**)&Wrlo,  g_Wrlo);
    cudaGetSymbolAddress((void**)&WhfHi, g_WhfHi);
    cudaGetSymbolAddress((void**)&WhfLo, g_WhfLo);
    cudaGetSymbolAddress((void**)&WhrHi, g_WhrHi);
    cudaGetSymbolAddress((void**)&WhrLo, g_WhrLo);
    cudaGetSymbolAddress((void**)&shi,   g_shi);
    cudaGetSymbolAddress((void**)&slo,   g_slo);

    cudaFuncSetAttribute(gemm_bf16s,    cudaFuncAttributeMaxDynamicSharedMemorySize, GB_SMEM);
    cudaFuncSetAttribute(lstm_layer_tc, cudaFuncAttributeMaxDynamicSharedMemorySize, RK_SMEM);

    const int M = LL * BB;   // 32768
    const int whn4 = (G4 * HH) / 4;

    transpose_x<<<8192, 256>>>((const float4*)x, (float4*)xT);

    dim3 ggrid(G4 / 128, M / 128);   // (16, 256)

    // ---- layer 0 (K = 256) ----
    {
        int n4 = (LL * BB * II) / 4;
        split_bf16<<<(n4 + 255) / 256, 256>>>((const float4*)xT,
            (__nv_bfloat162*)Ahi, (__nv_bfloat162*)Alo, n4);
        int w4 = (G4 * II) / 4;
        split_bf16<<<(w4 + 255) / 256, 256>>>((const float4*)Wih_f0,
            (__nv_bfloat162*)Wfhi, (__nv_bfloat162*)Wflo, w4);
        split_bf16<<<(w4 + 255) / 256, 256>>>((const float4*)Wih_r0,
            (__nv_bfloat162*)Wrhi, (__nv_bfloat162*)Wrlo, w4);
        gemm_bf16s<<<ggrid, 256, GB_SMEM>>>(M, G4, II, Ahi, Alo, Wfhi, Wflo, bih_f0, bhh_f0, gf);
        gemm_bf16s<<<ggrid, 256, GB_SMEM>>>(M, G4, II, Ahi, Alo, Wrhi, Wrlo, bih_r0, bhh_r0, gr);
        split_bf16<<<(whn4 + 255) / 256, 256>>>((const float4*)Whh_f0,
            (__nv_bfloat162*)WhfHi, (__nv_bfloat162*)WhfLo, whn4);
        split_bf16<<<(whn4 + 255) / 256, 256>>>((const float4*)Whh_r0,
            (__nv_bfloat162*)WhrHi, (__nv_bfloat162*)WhrLo, whn4);
    }
    cudaMemsetAsync(shi, 0, sizeof(__nv_bfloat16) * 2 * 2 * BB * HH, 0);
    cudaMemsetAsync(slo, 0, sizeof(__nv_bfloat16) * 2 * 2 * BB * HH, 0);
    cudaMemsetAsync(bar4, 0, sizeof(unsigned) * 4 * 32, 0);
    lstm_layer_tc<<<128, 256, RK_SMEM>>>(gf, gr, WhfHi, WhfLo, WhrHi, WhrLo,
                                         shi, slo, hcat, 0);

    // ---- layer 1 (K = 1024) ----
    {
        int n4 = (LL * BB * 2 * HH) / 4;
        split_bf16<<<(n4 + 255) / 256, 256>>>((const float4*)hcat,
            (__nv_bfloat162*)Ahi, (__nv_bfloat162*)Alo, n4);
        int w4 = (G4 * 2 * HH) / 4;
        split_bf16<<<(w4 + 255) / 256, 256>>>((const float4*)Wih_f1,
            (__nv_bfloat162*)Wfhi, (__nv_bfloat162*)Wflo, w4);
        split_bf16<<<(w4 + 255) / 256, 256>>>((const float4*)Wih_r1,
            (__nv_bfloat162*)Wrhi, (__nv_bfloat162*)Wrlo, w4);
        gemm_bf16s<<<ggrid, 256, GB_SMEM>>>(M, G4, 2 * HH, Ahi, Alo, Wfhi, Wflo, bih_f1, bhh_f1, gf);
        gemm_bf16s<<<ggrid, 256, GB_SMEM>>>(M, G4, 2 * HH, Ahi, Alo, Wrhi, Wrlo, bih_r1, bhh_r1, gr);
        split_bf16<<<(whn4 + 255) / 256, 256>>>((const float4*)Whh_f1,
            (__nv_bfloat162*)WhfHi, (__nv_bfloat162*)WhfLo, whn4);
        split_bf16<<<(whn4 + 255) / 256, 256>>>((const float4*)Whh_r1,
            (__nv_bfloat162*)WhrHi, (__nv_bfloat162*)WhrLo, whn4);
    }
    cudaMemsetAsync(shi, 0, sizeof(__nv_bfloat16) * 2 * 2 * BB * HH, 0);
    cudaMemsetAsync(slo, 0, sizeof(__nv_bfloat16) * 2 * 2 * BB * HH, 0);
    cudaMemsetAsync(bar4, 0, sizeof(unsigned) * 4 * 32, 0);
    lstm_layer_tc<<<128, 256, RK_SMEM>>>(gf, gr, WhfHi, WhfLo, WhrHi, WhrLo,
                                         shi, slo, (float*)d_out, 1);
}

// round 11
// speedup vs baseline: 3.2360x; 1.0964x over previous
#include <cuda_runtime.h>
#include <cuda_bf16.h>
#include <cuda_fp16.h>
#include <math.h>
#include <cstdint>

// Problem dims
#define LL 512
#define BB 64
#define II 256
#define HH 512
#define G4 2048   // 4*H

// ---------------- scratch (static device globals; no allocation) ----------------
__device__ float g_xT[(size_t)LL * BB * II];          // [t][b][I]
__device__ float g_gates_f[(size_t)LL * BB * G4];     // [t][b][4H]
__device__ float g_gates_r[(size_t)LL * BB * G4];     // [t][b][4H]
__device__ float g_hcat[(size_t)LL * BB * 2 * HH];    // [t][b][2H]
__device__ unsigned g_bar4[4 * 32];                   // 4 group barriers, 128B apart

// h state as bf16 hi/lo: [dir][parity][b][u]
__device__ __align__(16) __nv_bfloat16 g_shi[2 * 2 * BB * HH];
__device__ __align__(16) __nv_bfloat16 g_slo[2 * 2 * BB * HH];

// fp16 GEMM operands: A single, W hi/lo
__device__ __align__(16) __half g_Af16[(size_t)LL * BB * 2 * HH];
__device__ __align__(16) __half g_Wfhi[(size_t)G4 * 2 * HH];
__device__ __align__(16) __half g_Wflo[(size_t)G4 * 2 * HH];
__device__ __align__(16) __half g_Wrhi[(size_t)G4 * 2 * HH];
__device__ __align__(16) __half g_Wrlo[(size_t)G4 * 2 * HH];
// Whh bf16 splits for the recurrence ([2048][512] each)
__device__ __align__(16) __nv_bfloat16 g_WhfHi[(size_t)G4 * HH];
__device__ __align__(16) __nv_bfloat16 g_WhfLo[(size_t)G4 * HH];
__device__ __align__(16) __nv_bfloat16 g_WhrHi[(size_t)G4 * HH];
__device__ __align__(16) __nv_bfloat16 g_WhrLo[(size_t)G4 * HH];

__device__ __forceinline__ uint32_t smem_u32(const void* p) {
    uint32_t a;
    asm("{ .reg .u64 t; cvta.to.shared.u64 t, %1; cvt.u32.u64 %0, t; }" : "=r"(a) : "l"(p));
    return a;
}

__device__ __forceinline__ float fsig(float x) {
    return 1.0f / (1.0f + __expf(-x));
}
__device__ __forceinline__ float ftanh(float x) {
    return fmaf(2.0f, fsig(2.0f * x), -1.0f);
}

// ---------------- transpose x[b][l][i] -> xT[l][b][i] ----------------
__global__ void transpose_x(const float4* __restrict__ x, float4* __restrict__ xT) {
    int idx = blockIdx.x * blockDim.x + threadIdx.x;
    int i4 = idx & 63;
    int m  = idx >> 6;
    int t  = m >> 6;
    int b  = m & 63;
    xT[idx] = x[((size_t)(b * LL + t)) * 64 + i4];
}

// ---------------- fp32 -> fp16 convert (A operand) ----------------
__global__ void cvt_f16(const float4* __restrict__ src, __half2* __restrict__ dst, int n4) {
    int i = blockIdx.x * blockDim.x + threadIdx.x;
    if (i >= n4) return;
    float4 v = src[i];
    dst[i * 2 + 0] = __floats2half2_rn(v.x, v.y);
    dst[i * 2 + 1] = __floats2half2_rn(v.z, v.w);
}

// ---------------- fp32 -> fp16 hi/lo split (W operand) ----------------
__global__ void split_f16(const float4* __restrict__ src,
                          __half2* __restrict__ hi,
                          __half2* __restrict__ lo, int n4) {
    int i = blockIdx.x * blockDim.x + threadIdx.x;
    if (i >= n4) return;
    float4 v = src[i];
    __half hx = __float2half_rn(v.x);
    __half hy = __float2half_rn(v.y);
    __half hz = __float2half_rn(v.z);
    __half hw = __float2half_rn(v.w);
    __half lx = __float2half_rn(v.x - __half2float(hx));
    __half ly = __float2half_rn(v.y - __half2float(hy));
    __half lz = __float2half_rn(v.z - __half2float(hz));
    __half lw = __float2half_rn(v.w - __half2float(hw));
    hi[i * 2 + 0] = __halves2half2(hx, hy);
    hi[i * 2 + 1] = __halves2half2(hz, hw);
    lo[i * 2 + 0] = __halves2half2(lx, ly);
    lo[i * 2 + 1] = __halves2half2(lz, lw);
}

// ---------------- fp32 -> bf16 hi/lo split (Whh for recurrence) ----------------
__global__ void split_bf16(const float4* __restrict__ src,
                           __nv_bfloat162* __restrict__ hi,
                           __nv_bfloat162* __restrict__ lo, int n4) {
    int i = blockIdx.x * blockDim.x + threadIdx.x;
    if (i >= n4) return;
    float4 v = src[i];
    __nv_bfloat16 hx = __float2bfloat16(v.x);
    __nv_bfloat16 hy = __float2bfloat16(v.y);
    __nv_bfloat16 hz = __float2bfloat16(v.z);
    __nv_bfloat16 hw = __float2bfloat16(v.w);
    __nv_bfloat16 lx = __float2bfloat16(v.x - __bfloat162float(hx));
    __nv_bfloat16 ly = __float2bfloat16(v.y - __bfloat162float(hy));
    __nv_bfloat16 lz = __float2bfloat16(v.z - __bfloat162float(hz));
    __nv_bfloat16 lw = __float2bfloat16(v.w - __bfloat162float(hw));
    hi[i * 2 + 0] = __nv_bfloat162(hx, hy);
    hi[i * 2 + 1] = __nv_bfloat162(hz, hw);
    lo[i * 2 + 0] = __nv_bfloat162(lx, ly);
    lo[i * 2 + 1] = __nv_bfloat162(lz, lw);
}

// ---------------- fp16 2-term GEMM: C = A_f16 @ (Whi + Wlo)^T + bias ----------------
// 128x128 block, 2-stage, 2 CTAs/SM. smem/stage: A, Bhi, Blo tiles (3 x 10240).
#define GBK   32
#define GTILE 10240                 // 128 * 80
#define GSTG  (3 * GTILE)           // 30720
#define GB_SMEM (2 * GSTG + 512)    // 61952; x2 CTAs = 124KB

__global__ __launch_bounds__(256, 2) void gemm_f16s(
    int M, int N, int K,
    const __half* __restrict__ A,
    const __half* __restrict__ Bhi, const __half* __restrict__ Blo,
    const float* __restrict__ bias1, const float* __restrict__ bias2,
    float* __restrict__ C)
{
    extern __shared__ char sm[];
    uint32_t sb = smem_u32(sm);
    int tid  = threadIdx.x;
    int lane = tid & 31;
    int warp = tid >> 5;
    int gid  = lane >> 2;
    int tg   = lane & 3;
    int wm   = warp >> 2;     // 0..1 (64 rows)
    int wn   = warp & 3;      // 0..3 (32 cols)
    int n0   = blockIdx.x * 128;
    int m0   = blockIdx.y * 128;

    float* shb = (float*)(sm + 2 * GSTG);
    if (tid < 128) shb[tid] = bias1[n0 + tid] + bias2[n0 + tid];

    const char* srcs[3];
    srcs[0] = (const char*)(A   + (size_t)m0 * K);
    srcs[1] = (const char*)(Bhi + (size_t)n0 * K);
    srcs[2] = (const char*)(Blo + (size_t)n0 * K);

#define LOAD_STAGE(kc, bufsel)                                                      \
    {                                                                               \
        _Pragma("unroll")                                                           \
        for (int j = 0; j < 6; j++) {                                               \
            int c    = tid + j * 256;           /* 0..1535 */                       \
            int tile = c >> 9;                                                      \
            int cc   = c & 511;                                                     \
            int row  = cc >> 2, g = cc & 3;                                         \
            uint32_t d = sb + (bufsel) * GSTG + tile * GTILE + row * 80 + g * 16;   \
            const char* s = srcs[tile] + ((size_t)row * K + (kc) * GBK) * 2 + g * 16; \
            asm volatile("cp.async.ca.shared.global [%0], [%1], 16;" :: "r"(d), "l"(s)); \
        }                                                                           \
        asm volatile("cp.async.commit_group;" ::: "memory");                        \
    }

    float acc[4][4][4];
#pragma unroll
    for (int i = 0; i < 4; i++)
#pragma unroll
        for (int j = 0; j < 4; j++)
#pragma unroll
            for (int r = 0; r < 4; r++) acc[i][j][r] = 0.0f;

    int nk = K / GBK;   // >= 8
    LOAD_STAGE(0, 0);
    LOAD_STAGE(1, 1);

    for (int kc = 0; kc < nk; kc++) {
        if (kc + 1 < nk)
            asm volatile("cp.async.wait_group 1;" ::: "memory");
        else
            asm volatile("cp.async.wait_group 0;" ::: "memory");
        __syncthreads();

        int buf = kc & 1;
        uint32_t bA  = sb + buf * GSTG;
        uint32_t bBh = bA + GTILE;
        uint32_t bBl = bA + 2 * GTILE;

        uint32_t aoff = (uint32_t)(wm * 64 + (lane & 15)) * 80 + (lane >> 4) * 16;
        uint32_t boff = (uint32_t)(wn * 32 + (lane & 7)) * 80 + ((lane >> 3) & 1) * 16;

#pragma unroll
        for (int ks = 0; ks < 2; ks++) {
            uint32_t ko = ks * 32;
            uint32_t af[4][4];
#pragma unroll
            for (int mt = 0; mt < 4; mt++) {
                asm volatile("ldmatrix.sync.aligned.m8n8.x4.shared.b16 {%0,%1,%2,%3}, [%4];"
                    : "=r"(af[mt][0]), "=r"(af[mt][1]), "=r"(af[mt][2]), "=r"(af[mt][3])
                    : "r"(bA + aoff + ko + mt * (16 * 80)));
            }
            uint32_t bh[4][2], bl[4][2];
#pragma unroll
            for (int nt = 0; nt < 4; nt++) {
                asm volatile("ldmatrix.sync.aligned.m8n8.x2.shared.b16 {%0,%1}, [%2];"
                    : "=r"(bh[nt][0]), "=r"(bh[nt][1]) : "r"(bBh + boff + ko + nt * (8 * 80)));
                asm volatile("ldmatrix.sync.aligned.m8n8.x2.shared.b16 {%0,%1}, [%2];"
                    : "=r"(bl[nt][0]), "=r"(bl[nt][1]) : "r"(bBl + boff + ko + nt * (8 * 80)));
            }
#pragma unroll
            for (int mt = 0; mt < 4; mt++)
#pragma unroll
                for (int nt = 0; nt < 4; nt++) {
                    asm volatile(
                        "mma.sync.aligned.m16n8k16.row.col.f32.f16.f16.f32 "
                        "{%0,%1,%2,%3}, {%4,%5,%6,%7}, {%8,%9}, {%0,%1,%2,%3};"
                        : "+f"(acc[mt][nt][0]), "+f"(acc[mt][nt][1]),
                          "+f"(acc[mt][nt][2]), "+f"(acc[mt][nt][3])
                        : "r"(af[mt][0]), "r"(af[mt][1]), "r"(af[mt][2]), "r"(af[mt][3]),
                          "r"(bh[nt][0]), "r"(bh[nt][1]));
                    asm volatile(
                        "mma.sync.aligned.m16n8k16.row.col.f32.f16.f16.f32 "
                        "{%0,%1,%2,%3}, {%4,%5,%6,%7}, {%8,%9}, {%0,%1,%2,%3};"
                        : "+f"(acc[mt][nt][0]), "+f"(acc[mt][nt][1]),
                          "+f"(acc[mt][nt][2]), "+f"(acc[mt][nt][3])
                        : "r"(af[mt][0]), "r"(af[mt][1]), "r"(af[mt][2]), "r"(af[mt][3]),
                          "r"(bl[nt][0]), "r"(bl[nt][1]));
                }
        }
        __syncthreads();
        if (kc + 2 < nk) LOAD_STAGE(kc + 2, buf);
    }

#pragma unroll
    for (int mt = 0; mt < 4; mt++) {
        int r0 = m0 + wm * 64 + mt * 16 + gid;
#pragma unroll
        for (int nt = 0; nt < 4; nt++) {
            int cl = wn * 32 + nt * 8 + 2 * tg;
            float b0 = shb[cl], b1 = shb[cl + 1];
            *(float2*)(C + (size_t)r0 * N + n0 + cl) =
                make_float2(acc[mt][nt][0] + b0, acc[mt][nt][1] + b1);
            *(float2*)(C + (size_t)(r0 + 8) * N + n0 + cl) =
                make_float2(acc[mt][nt][2] + b0, acc[mt][nt][3] + b1);
        }
    }
}

// ---------------- persistent tensor-core LSTM layer (unchanged, known-good) ----------------
#define RP     1040
#define OFF_AHI 0
#define OFF_ALO (64 * RP)
#define OFF_BHI (2 * 64 * RP)
#define OFF_BLO (2 * 64 * RP + 32 * RP)
#define OFF_G0  (2 * 64 * RP + 2 * 32 * RP)
#define OFF_G1  (OFF_G0 + 64 * 33 * 4)
#define RK_SMEM (OFF_G1 + 64 * 33 * 4)   // 216576

__global__ __launch_bounds__(256, 1) void lstm_layer_tc(
    const float* __restrict__ gates_f,
    const float* __restrict__ gates_r,
    const __nv_bfloat16* __restrict__ WhfHi, const __nv_bfloat16* __restrict__ WhfLo,
    const __nv_bfloat16* __restrict__ WhrHi, const __nv_bfloat16* __restrict__ WhrLo,
    __nv_bfloat16* __restrict__ shi,
    __nv_bfloat16* __restrict__ slo,
    float* __restrict__ outbuf,
    int out_mode)
{
    extern __shared__ char sm[];
    uint32_t sb = smem_u32(sm);
    int tid  = threadIdx.x;
    int lane = tid & 31;
    int warp = tid >> 5;
    int gid  = lane >> 2;
    int tg   = lane & 3;

    int bx  = blockIdx.x;
    int dir = bx >> 6;
    int us  = (bx >> 1) & 31;
    int bs  = bx & 1;
    int u0  = us * 16;
    int b0  = bs * 32;
    int grp = dir * 2 + bs;
    unsigned* gbar = (unsigned*)&g_bar4[grp * 32];

    const float* gates = dir ? gates_r : gates_f;
    const __nv_bfloat16* whH = dir ? WhrHi : WhfHi;
    const __nv_bfloat16* whL = dir ? WhrLo : WhfLo;

#pragma unroll
    for (int j = 0; j < 16; j++) {
        int idx = tid + j * 256;
        int row = idx >> 6;
        int ch  = idx & 63;
        int g   = row >> 4;
        int ul  = row & 15;
        size_t soff = (size_t)(g * HH + u0 + ul) * HH + ch * 8;
        *(uint4*)(sm + OFF_AHI + row * RP + ch * 16) = *(const uint4*)(whH + soff);
        *(uint4*)(sm + OFF_ALO + row * RP + ch * 16) = *(const uint4*)(whL + soff);
    }

    int wk = warp >> 2;
    int wm = (warp >> 1) & 1;
    int wn = warp & 1;
    uint32_t apat = (uint32_t)(lane & 15) * RP + (lane >> 4) * 16;
    uint32_t bpat = (uint32_t)((lane & 7) + ((lane >> 4) << 3)) * RP + ((lane >> 3) & 1) * 16;
    uint32_t aBaseHi = sb + OFF_AHI + wm * 32 * RP + apat;
    uint32_t aBaseLo = sb + OFF_ALO + wm * 32 * RP + apat;
    uint32_t bBaseHi = sb + OFF_BHI + wn * 16 * RP + bpat;
    uint32_t bBaseLo = sb + OFF_BLO + wn * 16 * RP + bpat;
    float* gbuf = (float*)(sm + (wk ? OFF_G1 : OFF_G0));
    float* g0f  = (float*)(sm + OFF_G0);
    float* g1f  = (float*)(sm + OFF_G1);

    int bown = tid >> 3;
    int u2   = (tid & 7) * 2;
    float cst0 = 0.0f, cst1 = 0.0f;

    for (int s = 0; s < LL; s++) {
        int t   = dir ? (LL - 1 - s) : s;
        int par = s & 1;
        const __nv_bfloat16* hinH = shi + ((dir * 2 + par) * BB) * HH;
        const __nv_bfloat16* hinL = slo + ((dir * 2 + par) * BB) * HH;
        __nv_bfloat16* houtH = shi + ((dir * 2 + (par ^ 1)) * BB) * HH;
        __nv_bfloat16* houtL = slo + ((dir * 2 + (par ^ 1)) * BB) * HH;

        float2 pg[4];
        {
            size_t gbase = ((size_t)t * BB + (b0 + bown)) * G4 + (u0 + u2);
#pragma unroll
            for (int g = 0; g < 4; g++)
                pg[g] = __ldcg((const float2*)&gates[gbase + g * HH]);
        }

#pragma unroll
        for (int j = 0; j < 8; j++) {
            int idx = tid + j * 256;
            int row = idx >> 6;
            int ch  = idx & 63;
            size_t soff = (size_t)(b0 + row) * HH + ch * 8;
            uint4 vh = __ldcg((const uint4*)(hinH + soff));
            uint4 vl = __ldcg((const uint4*)(hinL + soff));
            *(uint4*)(sm + OFF_BHI + row * RP + ch * 16) = vh;
            *(uint4*)(sm + OFF_BLO + row * RP + ch * 16) = vl;
        }
        __syncthreads();

        float t0[2][2][4], t1[2][2][4], t2[2][2][4];
#pragma unroll
        for (int i = 0; i < 2; i++)
#pragma unroll
            for (int j = 0; j < 2; j++)
#pragma unroll
                for (int r = 0; r < 4; r++) { t0[i][j][r] = 0.f; t1[i][j][r] = 0.f; t2[i][j][r] = 0.f; }

#pragma unroll 4
        for (int kc = 0; kc < 16; kc++) {
            uint32_t kb = (uint32_t)(wk * 16 + kc) * 32;
            uint32_t ah[2][4], al[2][4];
#pragma unroll
            for (int mt = 0; mt < 2; mt++) {
                asm volatile("ldmatrix.sync.aligned.m8n8.x4.shared.b16 {%0,%1,%2,%3}, [%4];"
                    : "=r"(ah[mt][0]), "=r"(ah[mt][1]), "=r"(ah[mt][2]), "=r"(ah[mt][3])
                    : "r"(aBaseHi + kb + mt * (16 * RP)));
                asm volatile("ldmatrix.sync.aligned.m8n8.x4.shared.b16 {%0,%1,%2,%3}, [%4];"
                    : "=r"(al[mt][0]), "=r"(al[mt][1]), "=r"(al[mt][2]), "=r"(al[mt][3])
                    : "r"(aBaseLo + kb + mt * (16 * RP)));
            }
            uint32_t bh[4], bl[4];
            asm volatile("ldmatrix.sync.aligned.m8n8.x4.shared.b16 {%0,%1,%2,%3}, [%4];"
                : "=r"(bh[0]), "=r"(bh[1]), "=r"(bh[2]), "=r"(bh[3]) : "r"(bBaseHi + kb));
            asm volatile("ldmatrix.sync.aligned.m8n8.x4.shared.b16 {%0,%1,%2,%3}, [%4];"
                : "=r"(bl[0]), "=r"(bl[1]), "=r"(bl[2]), "=r"(bl[3]) : "r"(bBaseLo + kb));
#pragma unroll
            for (int mt = 0; mt < 2; mt++)
#pragma unroll
                for (int nf = 0; nf < 2; nf++) {
                    asm volatile(
                        "mma.sync.aligned.m16n8k16.row.col.f32.bf16.bf16.f32 "
                        "{%0,%1,%2,%3}, {%4,%5,%6,%7}, {%8,%9}, {%0,%1,%2,%3};"
                        : "+f"(t0[mt][nf][0]), "+f"(t0[mt][nf][1]),
                          "+f"(t0[mt][nf][2]), "+f"(t0[mt][nf][3])
                        : "r"(ah[mt][0]), "r"(ah[mt][1]), "r"(ah[mt][2]), "r"(ah[mt][3]),
                          "r"(bh[nf * 2]), "r"(bh[nf * 2 + 1]));
                    asm volatile(
                        "mma.sync.aligned.m16n8k16.row.col.f32.bf16.bf16.f32 "
                        "{%0,%1,%2,%3}, {%4,%5,%6,%7}, {%8,%9}, {%0,%1,%2,%3};"
                        : "+f"(t1[mt][nf][0]), "+f"(t1[mt][nf][1]),
                          "+f"(t1[mt][nf][2]), "+f"(t1[mt][nf][3])
                        : "r"(al[mt][0]), "r"(al[mt][1]), "r"(al[mt][2]), "r"(al[mt][3]),
                          "r"(bh[nf * 2]), "r"(bh[nf * 2 + 1]));
                    asm volatile(
                        "mma.sync.aligned.m16n8k16.row.col.f32.bf16.bf16.f32 "
                        "{%0,%1,%2,%3}, {%4,%5,%6,%7}, {%8,%9}, {%0,%1,%2,%3};"
                        : "+f"(t2[mt][nf][0]), "+f"(t2[mt][nf][1]),
                          "+f"(t2[mt][nf][2]), "+f"(t2[mt][nf][3])
                        : "r"(ah[mt][0]), "r"(ah[mt][1]), "r"(ah[mt][2]), "r"(ah[mt][3]),
                          "r"(bl[nf * 2]), "r"(bl[nf * 2 + 1]));
                }
        }

#pragma unroll
        for (int mt = 0; mt < 2; mt++) {
            int r0 = wm * 32 + mt * 16 + gid;
#pragma unroll
            for (int nf = 0; nf < 2; nf++) {
                int cl = wn * 16 + nf * 8 + 2 * tg;
                gbuf[r0 * 33 + cl]           = t0[mt][nf][0] + t1[mt][nf][0] + t2[mt][nf][0];
                gbuf[r0 * 33 + cl + 1]       = t0[mt][nf][1] + t1[mt][nf][1] + t2[mt][nf][1];
                gbuf[(r0 + 8) * 33 + cl]     = t0[mt][nf][2] + t1[mt][nf][2] + t2[mt][nf][2];
                gbuf[(r0 + 8) * 33 + cl + 1] = t0[mt][nf][3] + t1[mt][nf][3] + t2[mt][nf][3];
            }
        }
        __syncthreads();

        {
            float a0[4], a1[4];
#pragma unroll
            for (int g = 0; g < 4; g++) {
                int r0 = g * 16 + u2;
                a0[g] = g0f[r0 * 33 + bown] + g1f[r0 * 33 + bown];
                a1[g] = g0f[(r0 + 1) * 33 + bown] + g1f[(r0 + 1) * 33 + bown];
            }
            float gi0 = pg[0].x + a0[0], gi1 = pg[0].y + a1[0];
            float gf0 = pg[1].x + a0[1], gf1 = pg[1].y + a1[1];
            float gg0 = pg[2].x + a0[2], gg1 = pg[2].y + a1[2];
            float go0 = pg[3].x + a0[3], go1 = pg[3].y + a1[3];
            float si0 = fsig(gi0), si1 = fsig(gi1);
            float sf0 = fsig(gf0), sf1 = fsig(gf1);
            float so0 = fsig(go0), so1 = fsig(go1);
            cst0 = sf0 * cst0 + si0 * ftanh(gg0);
            cst1 = sf1 * cst1 + si1 * ftanh(gg1);
            float h20 = so0 * ftanh(cst0);
            float h21 = so1 * ftanh(cst1);
            __nv_bfloat16 hh0 = __float2bfloat16(h20);
            __nv_bfloat16 hh1 = __float2bfloat16(h21);
            __nv_bfloat16 hl0 = __float2bfloat16(h20 - __bfloat162float(hh0));
            __nv_bfloat16 hl1 = __float2bfloat16(h21 - __bfloat162float(hh1));
            int bg = b0 + bown;
            size_t hoff = (size_t)bg * HH + u0 + u2;
            __stcg((__nv_bfloat162*)&houtH[hoff], __nv_bfloat162(hh0, hh1));
            __stcg((__nv_bfloat162*)&houtL[hoff], __nv_bfloat162(hl0, hl1));
            size_t orow = out_mode ? ((size_t)bg * LL + t) : ((size_t)t * BB + bg);
            *(float2*)(outbuf + orow * (2 * HH) + dir * HH + u0 + u2) = make_float2(h20, h21);
        }

        __syncthreads();
        if (tid == 0) {
            unsigned target = (unsigned)(s + 1) * 32u;
            asm volatile("red.release.gpu.global.add.u32 [%0], %1;"
                         :: "l"(gbar), "r"(1u) : "memory");
            unsigned v;
            do {
                asm volatile("ld.acquire.gpu.global.u32 %0, [%1];"
                             : "=r"(v) : "l"(gbar) : "memory");
            } while (v < target);
        }
        __syncthreads();
    }
}

// ---------------- host launcher ----------------
extern "C" void kernel_launch(void* const* d_in, const int* in_sizes, int n_in,
                              void* d_out, int out_size)
{
    const float* x       = (const float*)d_in[0];
    const float* Wih_f0  = (const float*)d_in[1];
    const float* Whh_f0  = (const float*)d_in[2];
    const float* bih_f0  = (const float*)d_in[3];
    const float* bhh_f0  = (const float*)d_in[4];
    const float* Wih_r0  = (const float*)d_in[5];
    const float* Whh_r0  = (const float*)d_in[6];
    const float* bih_r0  = (const float*)d_in[7];
    const float* bhh_r0  = (const float*)d_in[8];
    const float* Wih_f1  = (const float*)d_in[9];
    const float* Whh_f1  = (const float*)d_in[10];
    const float* bih_f1  = (const float*)d_in[11];
    const float* bhh_f1  = (const float*)d_in[12];
    const float* Wih_r1  = (const float*)d_in[13];
    const float* Whh_r1  = (const float*)d_in[14];
    const float* bih_r1  = (const float*)d_in[15];
    const float* bhh_r1  = (const float*)d_in[16];

    float *xT, *gf, *gr, *hcat;
    unsigned* bar4;
    __half *Af16, *Wfhi, *Wflo, *Wrhi, *Wrlo;
    __nv_bfloat16 *WhfHi, *WhfLo, *WhrHi, *WhrLo, *shi, *slo;
    cudaGetSymbolAddress((void**)&xT,    g_xT);
    cudaGetSymbolAddress((void**)&gf,    g_gates_f);
    cudaGetSymbolAddress((void**)&gr,    g_gates_r);
    cudaGetSymbolAddress((void**)&hcat,  g_hcat);
    cudaGetSymbolAddress((void**)&bar4,  g_bar4);
    cudaGetSymbolAddress((void**)&Af16,  g_Af16);
    cudaGetSymbolAddress((void**)&Wfhi,  g_Wfhi);
    cudaGetSymbolAddress((void**)&Wflo,  g_Wflo);
    cudaGetSymbolAddress((void**)&Wrhi,  g_Wrhi);
    cudaGetSymbolAddress((void**)&Wrlo,  g_Wrlo);
    cudaGetSymbolAddress((void**)&WhfHi, g_WhfHi);
    cudaGetSymbolAddress((void**)&WhfLo, g_WhfLo);
    cudaGetSymbolAddress((void**)&WhrHi, g_WhrHi);
    cudaGetSymbolAddress((void**)&WhrLo, g_WhrLo);
    cudaGetSymbolAddress((void**)&shi,   g_shi);
    cudaGetSymbolAddress((void**)&slo,   g_slo);

    cudaFuncSetAttribute(gemm_f16s,     cudaFuncAttributeMaxDynamicSharedMemorySize, GB_SMEM);
    cudaFuncSetAttribute(lstm_layer_tc, cudaFuncAttributeMaxDynamicSharedMemorySize, RK_SMEM);

    const int M = LL * BB;   // 32768
    const int whn4 = (G4 * HH) / 4;

    transpose_x<<<8192, 256>>>((const float4*)x, (float4*)xT);

    dim3 ggrid(G4 / 128, M / 128);   // (16, 256)

    // ---- layer 0 (K = 256) ----
    {
        int n4 = (LL * BB * II) / 4;
        cvt_f16<<<(n4 + 255) / 256, 256>>>((const float4*)xT, (__half2*)Af16, n4);
        int w4 = (G4 * II) / 4;
        split_f16<<<(w4 + 255) / 256, 256>>>((const float4*)Wih_f0,
            (__half2*)Wfhi, (__half2*)Wflo, w4);
        split_f16<<<(w4 + 255) / 256, 256>>>((const float4*)Wih_r0,
            (__half2*)Wrhi, (__half2*)Wrlo, w4);
        gemm_f16s<<<ggrid, 256, GB_SMEM>>>(M, G4, II, Af16, Wfhi, Wflo, bih_f0, bhh_f0, gf);
        gemm_f16s<<<ggrid, 256, GB_SMEM>>>(M, G4, II, Af16, Wrhi, Wrlo, bih_r0, bhh_r0, gr);
        split_bf16<<<(whn4 + 255) / 256, 256>>>((const float4*)Whh_f0,
            (__nv_bfloat162*)WhfHi, (__nv_bfloat162*)WhfLo, whn4);
        split_bf16<<<(whn4 + 255) / 256, 256>>>((const float4*)Whh_r0,
            (__nv_bfloat162*)WhrHi, (__nv_bfloat162*)WhrLo, whn4);
    }
    cudaMemsetAsync(shi, 0, sizeof(__nv_bfloat16) * 2 * 2 * BB * HH, 0);
    cudaMemsetAsync(slo, 0, sizeof(__nv_bfloat16) * 2 * 2 * BB * HH, 0);
    cudaMemsetAsync(bar4, 0, sizeof(unsigned) * 4 * 32, 0);
    lstm_layer_tc<<<128, 256, RK_SMEM>>>(gf, gr, WhfHi, WhfLo, WhrHi, WhrLo,
                                         shi, slo, hcat, 0);

    // ---- layer 1 (K = 1024) ----
    {
        int n4 = (LL * BB * 2 * HH) / 4;
        cvt_f16<<<(n4 + 255) / 256, 256>>>((const float4*)hcat, (__half2*)Af16, n4);
        int w4 = (G4 * 2 * HH) / 4;
        split_f16<<<(w4 + 255) / 256, 256>>>((const float4*)Wih_f1,
            (__half2*)Wfhi, (__half2*)Wflo, w4);
        split_f16<<<(w4 + 255) / 256, 256>>>((const float4*)Wih_r1,
            (__half2*)Wrhi, (__half2*)Wrlo, w4);
        gemm_f16s<<<ggrid, 256, GB_SMEM>>>(M, G4, 2 * HH, Af16, Wfhi, Wflo, bih_f1, bhh_f1, gf);
        gemm_f16s<<<ggrid, 256, GB_SMEM>>>(M, G4, 2 * HH, Af16, Wrhi, Wrlo, bih_r1, bhh_r1, gr);
        split_bf16<<<(whn4 + 255) / 256, 256>>>((const float4*)Whh_f1,
            (__nv_bfloat162*)WhfHi, (__nv_bfloat162*)WhfLo, whn4);
        split_bf16<<<(whn4 + 255) / 256, 256>>>((const float4*)Whh_r1,
            (__nv_bfloat162*)WhrHi, (__nv_bfloat162*)WhrLo, whn4);
    }
    cudaMemsetAsync(shi, 0, sizeof(__nv_bfloat16) * 2 * 2 * BB * HH, 0);
    cudaMemsetAsync(slo, 0, sizeof(__nv_bfloat16) * 2 * 2 * BB * HH, 0);
    cudaMemsetAsync(bar4, 0, sizeof(unsigned) * 4 * 32, 0);
    lstm_layer_tc<<<128, 256, RK_SMEM>>>(gf, gr, WhfHi, WhfLo, WhrHi, WhrLo,
                                         shi, slo, (float*)d_out, 1);
}

// round 12
// speedup vs baseline: 3.7708x; 1.1653x over previous
#include <cuda_runtime.h>
#include <cuda_bf16.h>
#include <cuda_fp16.h>
#include <math.h>
#include <cstdint>

// Problem dims
#define LL 512
#define BB 64
#define II 256
#define HH 512
#define G4 2048   // 4*H

// ---------------- scratch (static device globals; no allocation) ----------------
__device__ float g_xT[(size_t)LL * BB * II];          // [t][b][I]
__device__ float g_gates_f[(size_t)LL * BB * G4];     // [t][b][4H]
__device__ float g_gates_r[(size_t)LL * BB * G4];     // [t][b][4H]
__device__ float g_hcat[(size_t)LL * BB * 2 * HH];    // [t][b][2H]
__device__ unsigned g_bar4[4 * 32];                   // 4 group barriers, 128B apart

// h state as SINGLE fp16: [dir][parity][b][u]
__device__ __align__(16) __half g_sh16[2 * 2 * BB * HH];

// fp16 GEMM operands: A single, W hi/lo
__device__ __align__(16) __half g_Af16[(size_t)LL * BB * 2 * HH];
__device__ __align__(16) __half g_Wfhi[(size_t)G4 * 2 * HH];
__device__ __align__(16) __half g_Wflo[(size_t)G4 * 2 * HH];
__device__ __align__(16) __half g_Wrhi[(size_t)G4 * 2 * HH];
__device__ __align__(16) __half g_Wrlo[(size_t)G4 * 2 * HH];
// Whh fp16 splits for the recurrence ([2048][512] each)
__device__ __align__(16) __half g_WhfHi[(size_t)G4 * HH];
__device__ __align__(16) __half g_WhfLo[(size_t)G4 * HH];
__device__ __align__(16) __half g_WhrHi[(size_t)G4 * HH];
__device__ __align__(16) __half g_WhrLo[(size_t)G4 * HH];

__device__ __forceinline__ uint32_t smem_u32(const void* p) {
    uint32_t a;
    asm("{ .reg .u64 t; cvta.to.shared.u64 t, %1; cvt.u32.u64 %0, t; }" : "=r"(a) : "l"(p));
    return a;
}

__device__ __forceinline__ float fsig(float x) {
    return 1.0f / (1.0f + __expf(-x));
}
__device__ __forceinline__ float ftanh(float x) {
    return fmaf(2.0f, fsig(2.0f * x), -1.0f);
}

// ---------------- transpose x[b][l][i] -> xT[l][b][i] ----------------
__global__ void transpose_x(const float4* __restrict__ x, float4* __restrict__ xT) {
    int idx = blockIdx.x * blockDim.x + threadIdx.x;
    int i4 = idx & 63;
    int m  = idx >> 6;
    int t  = m >> 6;
    int b  = m & 63;
    xT[idx] = x[((size_t)(b * LL + t)) * 64 + i4];
}

// ---------------- fp32 -> fp16 convert (A operand) ----------------
__global__ void cvt_f16(const float4* __restrict__ src, __half2* __restrict__ dst, int n4) {
    int i = blockIdx.x * blockDim.x + threadIdx.x;
    if (i >= n4) return;
    float4 v = src[i];
    dst[i * 2 + 0] = __floats2half2_rn(v.x, v.y);
    dst[i * 2 + 1] = __floats2half2_rn(v.z, v.w);
}

// ---------------- fp32 -> fp16 hi/lo split (W operands) ----------------
__global__ void split_f16(const float4* __restrict__ src,
                          __half2* __restrict__ hi,
                          __half2* __restrict__ lo, int n4) {
    int i = blockIdx.x * blockDim.x + threadIdx.x;
    if (i >= n4) return;
    float4 v = src[i];
    __half hx = __float2half_rn(v.x);
    __half hy = __float2half_rn(v.y);
    __half hz = __float2half_rn(v.z);
    __half hw = __float2half_rn(v.w);
    __half lx = __float2half_rn(v.x - __half2float(hx));
    __half ly = __float2half_rn(v.y - __half2float(hy));
    __half lz = __float2half_rn(v.z - __half2float(hz));
    __half lw = __float2half_rn(v.w - __half2float(hw));
    hi[i * 2 + 0] = __halves2half2(hx, hy);
    hi[i * 2 + 1] = __halves2half2(hz, hw);
    lo[i * 2 + 0] = __halves2half2(lx, ly);
    lo[i * 2 + 1] = __halves2half2(lz, lw);
}

// ---------------- fp16 2-term GEMM (unchanged from R11, known-good) ----------------
#define GBK   32
#define GTILE 10240                 // 128 * 80
#define GSTG  (3 * GTILE)           // 30720
#define GB_SMEM (2 * GSTG + 512)    // 61952; x2 CTAs = 124KB

__global__ __launch_bounds__(256, 2) void gemm_f16s(
    int M, int N, int K,
    const __half* __restrict__ A,
    const __half* __restrict__ Bhi, const __half* __restrict__ Blo,
    const float* __restrict__ bias1, const float* __restrict__ bias2,
    float* __restrict__ C)
{
    extern __shared__ char sm[];
    uint32_t sb = smem_u32(sm);
    int tid  = threadIdx.x;
    int lane = tid & 31;
    int warp = tid >> 5;
    int gid  = lane >> 2;
    int tg   = lane & 3;
    int wm   = warp >> 2;
    int wn   = warp & 3;
    int n0   = blockIdx.x * 128;
    int m0   = blockIdx.y * 128;

    float* shb = (float*)(sm + 2 * GSTG);
    if (tid < 128) shb[tid] = bias1[n0 + tid] + bias2[n0 + tid];

    const char* srcs[3];
    srcs[0] = (const char*)(A   + (size_t)m0 * K);
    srcs[1] = (const char*)(Bhi + (size_t)n0 * K);
    srcs[2] = (const char*)(Blo + (size_t)n0 * K);

#define LOAD_STAGE(kc, bufsel)                                                      \
    {                                                                               \
        _Pragma("unroll")                                                           \
        for (int j = 0; j < 6; j++) {                                               \
            int c    = tid + j * 256;                                               \
            int tile = c >> 9;                                                      \
            int cc   = c & 511;                                                     \
            int row  = cc >> 2, g = cc & 3;                                         \
            uint32_t d = sb + (bufsel) * GSTG + tile * GTILE + row * 80 + g * 16;   \
            const char* s = srcs[tile] + ((size_t)row * K + (kc) * GBK) * 2 + g * 16; \
            asm volatile("cp.async.ca.shared.global [%0], [%1], 16;" :: "r"(d), "l"(s)); \
        }                                                                           \
        asm volatile("cp.async.commit_group;" ::: "memory");                        \
    }

    float acc[4][4][4];
#pragma unroll
    for (int i = 0; i < 4; i++)
#pragma unroll
        for (int j = 0; j < 4; j++)
#pragma unroll
            for (int r = 0; r < 4; r++) acc[i][j][r] = 0.0f;

    int nk = K / GBK;
    LOAD_STAGE(0, 0);
    LOAD_STAGE(1, 1);

    for (int kc = 0; kc < nk; kc++) {
        if (kc + 1 < nk)
            asm volatile("cp.async.wait_group 1;" ::: "memory");
        else
            asm volatile("cp.async.wait_group 0;" ::: "memory");
        __syncthreads();

        int buf = kc & 1;
        uint32_t bA  = sb + buf * GSTG;
        uint32_t bBh = bA + GTILE;
        uint32_t bBl = bA + 2 * GTILE;

        uint32_t aoff = (uint32_t)(wm * 64 + (lane & 15)) * 80 + (lane >> 4) * 16;
        uint32_t boff = (uint32_t)(wn * 32 + (lane & 7)) * 80 + ((lane >> 3) & 1) * 16;

#pragma unroll
        for (int ks = 0; ks < 2; ks++) {
            uint32_t ko = ks * 32;
            uint32_t af[4][4];
#pragma unroll
            for (int mt = 0; mt < 4; mt++) {
                asm volatile("ldmatrix.sync.aligned.m8n8.x4.shared.b16 {%0,%1,%2,%3}, [%4];"
                    : "=r"(af[mt][0]), "=r"(af[mt][1]), "=r"(af[mt][2]), "=r"(af[mt][3])
                    : "r"(bA + aoff + ko + mt * (16 * 80)));
            }
            uint32_t bh[4][2], bl[4][2];
#pragma unroll
            for (int nt = 0; nt < 4; nt++) {
                asm volatile("ldmatrix.sync.aligned.m8n8.x2.shared.b16 {%0,%1}, [%2];"
                    : "=r"(bh[nt][0]), "=r"(bh[nt][1]) : "r"(bBh + boff + ko + nt * (8 * 80)));
                asm volatile("ldmatrix.sync.aligned.m8n8.x2.shared.b16 {%0,%1}, [%2];"
                    : "=r"(bl[nt][0]), "=r"(bl[nt][1]) : "r"(bBl + boff + ko + nt * (8 * 80)));
            }
#pragma unroll
            for (int mt = 0; mt < 4; mt++)
#pragma unroll
                for (int nt = 0; nt < 4; nt++) {
                    asm volatile(
                        "mma.sync.aligned.m16n8k16.row.col.f32.f16.f16.f32 "
                        "{%0,%1,%2,%3}, {%4,%5,%6,%7}, {%8,%9}, {%0,%1,%2,%3};"
                        : "+f"(acc[mt][nt][0]), "+f"(acc[mt][nt][1]),
                          "+f"(acc[mt][nt][2]), "+f"(acc[mt][nt][3])
                        : "r"(af[mt][0]), "r"(af[mt][1]), "r"(af[mt][2]), "r"(af[mt][3]),
                          "r"(bh[nt][0]), "r"(bh[nt][1]));
                    asm volatile(
                        "mma.sync.aligned.m16n8k16.row.col.f32.f16.f16.f32 "
                        "{%0,%1,%2,%3}, {%4,%5,%6,%7}, {%8,%9}, {%0,%1,%2,%3};"
                        : "+f"(acc[mt][nt][0]), "+f"(acc[mt][nt][1]),
                          "+f"(acc[mt][nt][2]), "+f"(acc[mt][nt][3])
                        : "r"(af[mt][0]), "r"(af[mt][1]), "r"(af[mt][2]), "r"(af[mt][3]),
                          "r"(bl[nt][0]), "r"(bl[nt][1]));
                }
        }
        __syncthreads();
        if (kc + 2 < nk) LOAD_STAGE(kc + 2, buf);
    }

#pragma unroll
    for (int mt = 0; mt < 4; mt++) {
        int r0 = m0 + wm * 64 + mt * 16 + gid;
#pragma unroll
        for (int nt = 0; nt < 4; nt++) {
            int cl = wn * 32 + nt * 8 + 2 * tg;
            float b0 = shb[cl], b1 = shb[cl + 1];
            *(float2*)(C + (size_t)r0 * N + n0 + cl) =
                make_float2(acc[mt][nt][0] + b0, acc[mt][nt][1] + b1);
            *(float2*)(C + (size_t)(r0 + 8) * N + n0 + cl) =
                make_float2(acc[mt][nt][2] + b0, acc[mt][nt][3] + b1);
        }
    }
}

// ---------------- persistent tensor-core LSTM layer: 2-term fp16 ----------------
// Per step: gates[64,32] = (Whi + Wlo)[64,512] @ h_f16[32,512]^T; h single fp16.
#define RP     1040
#define OFF_AHI 0
#define OFF_ALO (64 * RP)
#define OFF_B   (2 * 64 * RP)                 // single h tile, 32 rows
#define OFF_G0  (2 * 64 * RP + 32 * RP)
#define OFF_G1  (OFF_G0 + 64 * 33 * 4)
#define RK_SMEM (OFF_G1 + 64 * 33 * 4)        // 183296

__global__ __launch_bounds__(256, 1) void lstm_layer_tc(
    const float* __restrict__ gates_f,
    const float* __restrict__ gates_r,
    const __half* __restrict__ WhfHi, const __half* __restrict__ WhfLo,
    const __half* __restrict__ WhrHi, const __half* __restrict__ WhrLo,
    __half* __restrict__ sh16,
    float* __restrict__ outbuf,
    int out_mode)
{
    extern __shared__ char sm[];
    uint32_t sb = smem_u32(sm);
    int tid  = threadIdx.x;
    int lane = tid & 31;
    int warp = tid >> 5;
    int gid  = lane >> 2;
    int tg   = lane & 3;

    int bx  = blockIdx.x;
    int dir = bx >> 6;
    int us  = (bx >> 1) & 31;
    int bs  = bx & 1;
    int u0  = us * 16;
    int b0  = bs * 32;
    int grp = dir * 2 + bs;
    unsigned* gbar = (unsigned*)&g_bar4[grp * 32];

    const float* gates = dir ? gates_r : gates_f;
    const __half* whH = dir ? WhrHi : WhfHi;
    const __half* whL = dir ? WhrLo : WhfLo;

    // ---- stage Whh slice once (hi & lo) ----
#pragma unroll
    for (int j = 0; j < 16; j++) {
        int idx = tid + j * 256;
        int row = idx >> 6;
        int ch  = idx & 63;
        int g   = row >> 4;
        int ul  = row & 15;
        size_t soff = (size_t)(g * HH + u0 + ul) * HH + ch * 8;
        *(uint4*)(sm + OFF_AHI + row * RP + ch * 16) = *(const uint4*)(whH + soff);
        *(uint4*)(sm + OFF_ALO + row * RP + ch * 16) = *(const uint4*)(whL + soff);
    }

    int wk = warp >> 2;
    int wm = (warp >> 1) & 1;
    int wn = warp & 1;
    uint32_t apat = (uint32_t)(lane & 15) * RP + (lane >> 4) * 16;
    uint32_t bpat = (uint32_t)((lane & 7) + ((lane >> 4) << 3)) * RP + ((lane >> 3) & 1) * 16;
    uint32_t aBaseHi = sb + OFF_AHI + wm * 32 * RP + apat;
    uint32_t aBaseLo = sb + OFF_ALO + wm * 32 * RP + apat;
    uint32_t bBase   = sb + OFF_B   + wn * 16 * RP + bpat;
    float* gbuf = (float*)(sm + (wk ? OFF_G1 : OFF_G0));
    float* g0f  = (float*)(sm + OFF_G0);
    float* g1f  = (float*)(sm + OFF_G1);

    int bown = tid >> 3;
    int u2   = (tid & 7) * 2;
    float cst0 = 0.0f, cst1 = 0.0f;

    for (int s = 0; s < LL; s++) {
        int t   = dir ? (LL - 1 - s) : s;
        int par = s & 1;
        const __half* hin  = sh16 + ((dir * 2 + par) * BB) * HH;
        __half*       hout = sh16 + ((dir * 2 + (par ^ 1)) * BB) * HH;

        // ---- prefetch this thread's gate inputs (float2 per gate) ----
        float2 pg[4];
        {
            size_t gbase = ((size_t)t * BB + (b0 + bown)) * G4 + (u0 + u2);
#pragma unroll
            for (int g = 0; g < 4; g++)
                pg[g] = __ldcg((const float2*)&gates[gbase + g * HH]);
        }

        // ---- stage h tile (32 b x 512 fp16, single stream) ----
#pragma unroll
        for (int j = 0; j < 8; j++) {
            int idx = tid + j * 256;
            int row = idx >> 6;
            int ch  = idx & 63;
            uint4 v = __ldcg((const uint4*)(hin + (size_t)(b0 + row) * HH + ch * 8));
            *(uint4*)(sm + OFF_B + row * RP + ch * 16) = v;
        }
        __syncthreads();

        // ---- 2-term HMMA over this warp's 16 k-chunks ----
        float t0[2][2][4], t1[2][2][4];
#pragma unroll
        for (int i = 0; i < 2; i++)
#pragma unroll
            for (int j = 0; j < 2; j++)
#pragma unroll
                for (int r = 0; r < 4; r++) { t0[i][j][r] = 0.f; t1[i][j][r] = 0.f; }

#pragma unroll 4
        for (int kc = 0; kc < 16; kc++) {
            uint32_t kb = (uint32_t)(wk * 16 + kc) * 32;
            uint32_t ah[2][4], al[2][4];
#pragma unroll
            for (int mt = 0; mt < 2; mt++) {
                asm volatile("ldmatrix.sync.aligned.m8n8.x4.shared.b16 {%0,%1,%2,%3}, [%4];"
                    : "=r"(ah[mt][0]), "=r"(ah[mt][1]), "=r"(ah[mt][2]), "=r"(ah[mt][3])
                    : "r"(aBaseHi + kb + mt * (16 * RP)));
                asm volatile("ldmatrix.sync.aligned.m8n8.x4.shared.b16 {%0,%1,%2,%3}, [%4];"
                    : "=r"(al[mt][0]), "=r"(al[mt][1]), "=r"(al[mt][2]), "=r"(al[mt][3])
                    : "r"(aBaseLo + kb + mt * (16 * RP)));
            }
            uint32_t bf[4];
            asm volatile("ldmatrix.sync.aligned.m8n8.x4.shared.b16 {%0,%1,%2,%3}, [%4];"
                : "=r"(bf[0]), "=r"(bf[1]), "=r"(bf[2]), "=r"(bf[3]) : "r"(bBase + kb));
#pragma unroll
            for (int mt = 0; mt < 2; mt++)
#pragma unroll
                for (int nf = 0; nf < 2; nf++) {
                    asm volatile(
                        "mma.sync.aligned.m16n8k16.row.col.f32.f16.f16.f32 "
                        "{%0,%1,%2,%3}, {%4,%5,%6,%7}, {%8,%9}, {%0,%1,%2,%3};"
                        : "+f"(t0[mt][nf][0]), "+f"(t0[mt][nf][1]),
                          "+f"(t0[mt][nf][2]), "+f"(t0[mt][nf][3])
                        : "r"(ah[mt][0]), "r"(ah[mt][1]), "r"(ah[mt][2]), "r"(ah[mt][3]),
                          "r"(bf[nf * 2]), "r"(bf[nf * 2 + 1]));
                    asm volatile(
                        "mma.sync.aligned.m16n8k16.row.col.f32.f16.f16.f32 "
                        "{%0,%1,%2,%3}, {%4,%5,%6,%7}, {%8,%9}, {%0,%1,%2,%3};"
                        : "+f"(t1[mt][nf][0]), "+f"(t1[mt][nf][1]),
                          "+f"(t1[mt][nf][2]), "+f"(t1[mt][nf][3])
                        : "r"(al[mt][0]), "r"(al[mt][1]), "r"(al[mt][2]), "r"(al[mt][3]),
                          "r"(bf[nf * 2]), "r"(bf[nf * 2 + 1]));
                }
        }

        // ---- write k-partials to gate buffer (scalar: pitch 33 odd) ----
#pragma unroll
        for (int mt = 0; mt < 2; mt++) {
            int r0 = wm * 32 + mt * 16 + gid;
#pragma unroll
            for (int nf = 0; nf < 2; nf++) {
                int cl = wn * 16 + nf * 8 + 2 * tg;
                gbuf[r0 * 33 + cl]           = t0[mt][nf][0] + t1[mt][nf][0];
                gbuf[r0 * 33 + cl + 1]       = t0[mt][nf][1] + t1[mt][nf][1];
                gbuf[(r0 + 8) * 33 + cl]     = t0[mt][nf][2] + t1[mt][nf][2];
                gbuf[(r0 + 8) * 33 + cl + 1] = t0[mt][nf][3] + t1[mt][nf][3];
            }
        }
        __syncthreads();

        // ---- epilogue: two units (u2, u2+1) of batch bown; direct writeback ----
        {
            float a0[4], a1[4];
#pragma unroll
            for (int g = 0; g < 4; g++) {
                int r0 = g * 16 + u2;
                a0[g] = g0f[r0 * 33 + bown] + g1f[r0 * 33 + bown];
                a1[g] = g0f[(r0 + 1) * 33 + bown] + g1f[(r0 + 1) * 33 + bown];
            }
            float gi0 = pg[0].x + a0[0], gi1 = pg[0].y + a1[0];
            float gf0 = pg[1].x + a0[1], gf1 = pg[1].y + a1[1];
            float gg0 = pg[2].x + a0[2], gg1 = pg[2].y + a1[2];
            float go0 = pg[3].x + a0[3], go1 = pg[3].y + a1[3];
            float si0 = fsig(gi0), si1 = fsig(gi1);
            float sf0 = fsig(gf0), sf1 = fsig(gf1);
            float so0 = fsig(go0), so1 = fsig(go1);
            cst0 = sf0 * cst0 + si0 * ftanh(gg0);
            cst1 = sf1 * cst1 + si1 * ftanh(gg1);
            float h20 = so0 * ftanh(cst0);
            float h21 = so1 * ftanh(cst1);
            int bg = b0 + bown;
            size_t hoff = (size_t)bg * HH + u0 + u2;
            __stcg((__half2*)&hout[hoff], __floats2half2_rn(h20, h21));
            size_t orow = out_mode ? ((size_t)bg * LL + t) : ((size_t)t * BB + bg);
            *(float2*)(outbuf + orow * (2 * HH) + dir * HH + u0 + u2) = make_float2(h20, h21);
        }

        // ---- group barrier across 32 CTAs: release-add + acquire-poll ----
        __syncthreads();
        if (tid == 0) {
            unsigned target = (unsigned)(s + 1) * 32u;
            asm volatile("red.release.gpu.global.add.u32 [%0], %1;"
                         :: "l"(gbar), "r"(1u) : "memory");
            unsigned v;
            do {
                asm volatile("ld.acquire.gpu.global.u32 %0, [%1];"
                             : "=r"(v) : "l"(gbar) : "memory");
            } while (v < target);
        }
        __syncthreads();
    }
}

// ---------------- host launcher ----------------
extern "C" void kernel_launch(void* const* d_in, const int* in_sizes, int n_in,
                              void* d_out, int out_size)
{
    const float* x       = (const float*)d_in[0];
    const float* Wih_f0  = (const float*)d_in[1];
    const float* Whh_f0  = (const float*)d_in[2];
    const float* bih_f0  = (const float*)d_in[3];
    const float* bhh_f0  = (const float*)d_in[4];
    const float* Wih_r0  = (const float*)d_in[5];
    const float* Whh_r0  = (const float*)d_in[6];
    const float* bih_r0  = (const float*)d_in[7];
    const float* bhh_r0  = (const float*)d_in[8];
    const float* Wih_f1  = (const float*)d_in[9];
    const float* Whh_f1  = (const float*)d_in[10];
    const float* bih_f1  = (const float*)d_in[11];
    const float* bhh_f1  = (const float*)d_in[12];
    const float* Wih_r1  = (const float*)d_in[13];
    const float* Whh_r1  = (const float*)d_in[14];
    const float* bih_r1  = (const float*)d_in[15];
    const float* bhh_r1  = (const float*)d_in[16];

    float *xT, *gf, *gr, *hcat;
    unsigned* bar4;
    __half *Af16, *Wfhi, *Wflo, *Wrhi, *Wrlo;
    __half *WhfHi, *WhfLo, *WhrHi, *WhrLo, *sh16;
    cudaGetSymbolAddress((void**)&xT,    g_xT);
    cudaGetSymbolAddress((void**)&gf,    g_gates_f);
    cudaGetSymbolAddress((void**)&gr,    g_gates_r);
    cudaGetSymbolAddress((void**)&hcat,  g_hcat);
    cudaGetSymbolAddress((void**)&bar4,  g_bar4);
    cudaGetSymbolAddress((void**)&Af16,  g_Af16);
    cudaGetSymbolAddress((void**)&Wfhi,  g_Wfhi);
    cudaGetSymbolAddress((void**)&Wflo,  g_Wflo);
    cudaGetSymbolAddress((void**)&Wrhi,  g_Wrhi);
    cudaGetSymbolAddress((void**)&Wrlo,  g_Wrlo);
    cudaGetSymbolAddress((void**)&WhfHi, g_WhfHi);
    cudaGetSymbolAddress((void**)&WhfLo, g_WhfLo);
    cudaGetSymbolAddress((void**)&WhrHi, g_WhrHi);
    cudaGetSymbolAddress((void**)&WhrLo, g_WhrLo);
    cudaGetSymbolAddress((void**)&sh16,  g_sh16);

    cudaFuncSetAttribute(gemm_f16s,     cudaFuncAttributeMaxDynamicSharedMemorySize, GB_SMEM);
    cudaFuncSetAttribute(lstm_layer_tc, cudaFuncAttributeMaxDynamicSharedMemorySize, RK_SMEM);

    const int M = LL * BB;   // 32768
    const int whn4 = (G4 * HH) / 4;

    transpose_x<<<8192, 256>>>((const float4*)x, (float4*)xT);

    dim3 ggrid(G4 / 128, M / 128);   // (16, 256)

    // ---- layer 0 (K = 256) ----
    {
        int n4 = (LL * BB * II) / 4;
        cvt_f16<<<(n4 + 255) / 256, 256>>>((const float4*)xT, (__half2*)Af16, n4);
        int w4 = (G4 * II) / 4;
        split_f16<<<(w4 + 255) / 256, 256>>>((const float4*)Wih_f0,
            (__half2*)Wfhi, (__half2*)Wflo, w4);
        split_f16<<<(w4 + 255) / 256, 256>>>((const float4*)Wih_r0,
            (__half2*)Wrhi, (__half2*)Wrlo, w4);
        gemm_f16s<<<ggrid, 256, GB_SMEM>>>(M, G4, II, Af16, Wfhi, Wflo, bih_f0, bhh_f0, gf);
        gemm_f16s<<<ggrid, 256, GB_SMEM>>>(M, G4, II, Af16, Wrhi, Wrlo, bih_r0, bhh_r0, gr);
        split_f16<<<(whn4 + 255) / 256, 256>>>((const float4*)Whh_f0,
            (__half2*)WhfHi, (__half2*)WhfLo, whn4);
        split_f16<<<(whn4 + 255) / 256, 256>>>((const float4*)Whh_r0,
            (__half2*)WhrHi, (__half2*)WhrLo, whn4);
    }
    cudaMemsetAsync(sh16, 0, sizeof(__half) * 2 * 2 * BB * HH, 0);
    cudaMemsetAsync(bar4, 0, sizeof(unsigned) * 4 * 32, 0);
    lstm_layer_tc<<<128, 256, RK_SMEM>>>(gf, gr, WhfHi, WhfLo, WhrHi, WhrLo,
                                         sh16, hcat, 0);

    // ---- layer 1 (K = 1024) ----
    {
        int n4 = (LL * BB * 2 * HH) / 4;
        cvt_f16<<<(n4 + 255) / 256, 256>>>((const float4*)hcat, (__half2*)Af16, n4);
        int w4 = (G4 * 2 * HH) / 4;
        split_f16<<<(w4 + 255) / 256, 256>>>((const float4*)Wih_f1,
            (__half2*)Wfhi, (__half2*)Wflo, w4);
        split_f16<<<(w4 + 255) / 256, 256>>>((const float4*)Wih_r1,
            (__half2*)Wrhi, (__half2*)Wrlo, w4);
        gemm_f16s<<<ggrid, 256, GB_SMEM>>>(M, G4, 2 * HH, Af16, Wfhi, Wflo, bih_f1, bhh_f1, gf);
        gemm_f16s<<<ggrid, 256, GB_SMEM>>>(M, G4, 2 * HH, Af16, Wrhi, Wrlo, bih_r1, bhh_r1, gr);
        split_f16<<<(whn4 + 255) / 256, 256>>>((const float4*)Whh_f1,
            (__half2*)WhfHi, (__half2*)WhfLo, whn4);
        split_f16<<<(whn4 + 255) / 256, 256>>>((const float4*)Whh_r1,
            (__half2*)WhrHi, (__half2*)WhrLo, whn4);
    }
    cudaMemsetAsync(sh16, 0, sizeof(__half) * 2 * 2 * BB * HH, 0);
    cudaMemsetAsync(bar4, 0, sizeof(unsigned) * 4 * 32, 0);
    lstm_layer_tc<<<128, 256, RK_SMEM>>>(gf, gr, WhfHi, WhfLo, WhrHi, WhrLo,
                                         sh16, (float*)d_out, 1);
}

// round 13
// speedup vs baseline: 4.2442x; 1.1255x over previous
#include <cuda_runtime.h>
#include <cuda_bf16.h>
#include <cuda_fp16.h>
#include <math.h>
#include <cstdint>

// Problem dims
#define LL 512
#define BB 64
#define II 256
#define HH 512
#define G4 2048   // 4*H

// ---------------- scratch (static device globals; no allocation) ----------------
__device__ float g_xT[(size_t)LL * BB * II];          // [t][b][I]
__device__ float g_gates_f[(size_t)LL * BB * G4];     // [t][b][4H]
__device__ float g_gates_r[(size_t)LL * BB * G4];     // [t][b][4H]
__device__ float g_hcat[(size_t)LL * BB * 2 * HH];    // [t][b][2H]
__device__ unsigned g_bar4[4 * 32];                   // 4 group barriers, 128B apart

// h state as SINGLE fp16: [dir][parity][b][u]
__device__ __align__(16) __half g_sh16[2 * 2 * BB * HH];

// fp16 GEMM operands: A single, W single (per dir)
__device__ __align__(16) __half g_Af16[(size_t)LL * BB * 2 * HH];
__device__ __align__(16) __half g_Wf16f[(size_t)G4 * 2 * HH];
__device__ __align__(16) __half g_Wf16r[(size_t)G4 * 2 * HH];
// Whh fp16 splits for the recurrence ([2048][512] each)
__device__ __align__(16) __half g_WhfHi[(size_t)G4 * HH];
__device__ __align__(16) __half g_WhfLo[(size_t)G4 * HH];
__device__ __align__(16) __half g_WhrHi[(size_t)G4 * HH];
__device__ __align__(16) __half g_WhrLo[(size_t)G4 * HH];

__device__ __forceinline__ uint32_t smem_u32(const void* p) {
    uint32_t a;
    asm("{ .reg .u64 t; cvta.to.shared.u64 t, %1; cvt.u32.u64 %0, t; }" : "=r"(a) : "l"(p));
    return a;
}

__device__ __forceinline__ float fsig(float x) {
    return 1.0f / (1.0f + __expf(-x));
}
__device__ __forceinline__ float ftanh(float x) {
    return fmaf(2.0f, fsig(2.0f * x), -1.0f);
}

// ---------------- transpose x[b][l][i] -> xT[l][b][i] ----------------
__global__ void transpose_x(const float4* __restrict__ x, float4* __restrict__ xT) {
    int idx = blockIdx.x * blockDim.x + threadIdx.x;
    int i4 = idx & 63;
    int m  = idx >> 6;
    int t  = m >> 6;
    int b  = m & 63;
    xT[idx] = x[((size_t)(b * LL + t)) * 64 + i4];
}

// ---------------- fp32 -> fp16 convert ----------------
__global__ void cvt_f16(const float4* __restrict__ src, __half2* __restrict__ dst, int n4) {
    int i = blockIdx.x * blockDim.x + threadIdx.x;
    if (i >= n4) return;
    float4 v = src[i];
    dst[i * 2 + 0] = __floats2half2_rn(v.x, v.y);
    dst[i * 2 + 1] = __floats2half2_rn(v.z, v.w);
}

// ---------------- fp32 -> fp16 hi/lo split (Whh for recurrence) ----------------
__global__ void split_f16(const float4* __restrict__ src,
                          __half2* __restrict__ hi,
                          __half2* __restrict__ lo, int n4) {
    int i = blockIdx.x * blockDim.x + threadIdx.x;
    if (i >= n4) return;
    float4 v = src[i];
    __half hx = __float2half_rn(v.x);
    __half hy = __float2half_rn(v.y);
    __half hz = __float2half_rn(v.z);
    __half hw = __float2half_rn(v.w);
    __half lx = __float2half_rn(v.x - __half2float(hx));
    __half ly = __float2half_rn(v.y - __half2float(hy));
    __half lz = __float2half_rn(v.z - __half2float(hz));
    __half lw = __float2half_rn(v.w - __half2float(hw));
    hi[i * 2 + 0] = __halves2half2(hx, hy);
    hi[i * 2 + 1] = __halves2half2(hz, hw);
    lo[i * 2 + 0] = __halves2half2(lx, ly);
    lo[i * 2 + 1] = __halves2half2(lz, lw);
}

// ---------------- plain fp16 GEMM: C = A_f16 @ W_f16^T + bias ----------------
// 128x128 block, 2-stage, 2 CTAs/SM. smem/stage: A + B tiles (2 x 10240).
#define GBK   32
#define GTILE 10240                 // 128 * 80
#define GSTG  (2 * GTILE)           // 20480
#define GB_SMEM (2 * GSTG + 512)    // 41472; x2 CTAs = 83KB

__global__ __launch_bounds__(256, 2) void gemm_f16(
    int M, int N, int K,
    const __half* __restrict__ A,
    const __half* __restrict__ B,
    const float* __restrict__ bias1, const float* __restrict__ bias2,
    float* __restrict__ C)
{
    extern __shared__ char sm[];
    uint32_t sb = smem_u32(sm);
    int tid  = threadIdx.x;
    int lane = tid & 31;
    int warp = tid >> 5;
    int gid  = lane >> 2;
    int tg   = lane & 3;
    int wm   = warp >> 2;
    int wn   = warp & 3;
    int n0   = blockIdx.x * 128;
    int m0   = blockIdx.y * 128;

    float* shb = (float*)(sm + 2 * GSTG);
    if (tid < 128) shb[tid] = bias1[n0 + tid] + bias2[n0 + tid];

    const char* srcs[2];
    srcs[0] = (const char*)(A + (size_t)m0 * K);
    srcs[1] = (const char*)(B + (size_t)n0 * K);

#define LOAD_STAGE(kc, bufsel)                                                      \
    {                                                                               \
        _Pragma("unroll")                                                           \
        for (int j = 0; j < 4; j++) {                                               \
            int c    = tid + j * 256;           /* 0..1023 */                       \
            int tile = c >> 9;                                                      \
            int cc   = c & 511;                                                     \
            int row  = cc >> 2, g = cc & 3;                                         \
            uint32_t d = sb + (bufsel) * GSTG + tile * GTILE + row * 80 + g * 16;   \
            const char* s = srcs[tile] + ((size_t)row * K + (kc) * GBK) * 2 + g * 16; \
            asm volatile("cp.async.ca.shared.global [%0], [%1], 16;" :: "r"(d), "l"(s)); \
        }                                                                           \
        asm volatile("cp.async.commit_group;" ::: "memory");                        \
    }

    float acc[4][4][4];
#pragma unroll
    for (int i = 0; i < 4; i++)
#pragma unroll
        for (int j = 0; j < 4; j++)
#pragma unroll
            for (int r = 0; r < 4; r++) acc[i][j][r] = 0.0f;

    int nk = K / GBK;
    LOAD_STAGE(0, 0);
    LOAD_STAGE(1, 1);

    for (int kc = 0; kc < nk; kc++) {
        if (kc + 1 < nk)
            asm volatile("cp.async.wait_group 1;" ::: "memory");
        else
            asm volatile("cp.async.wait_group 0;" ::: "memory");
        __syncthreads();

        int buf = kc & 1;
        uint32_t bA = sb + buf * GSTG;
        uint32_t bB = bA + GTILE;

        uint32_t aoff = (uint32_t)(wm * 64 + (lane & 15)) * 80 + (lane >> 4) * 16;
        uint32_t boff = (uint32_t)(wn * 32 + (lane & 7)) * 80 + ((lane >> 3) & 1) * 16;

#pragma unroll
        for (int ks = 0; ks < 2; ks++) {
            uint32_t ko = ks * 32;
            uint32_t af[4][4];
#pragma unroll
            for (int mt = 0; mt < 4; mt++) {
                asm volatile("ldmatrix.sync.aligned.m8n8.x4.shared.b16 {%0,%1,%2,%3}, [%4];"
                    : "=r"(af[mt][0]), "=r"(af[mt][1]), "=r"(af[mt][2]), "=r"(af[mt][3])
                    : "r"(bA + aoff + ko + mt * (16 * 80)));
            }
            uint32_t bfr[4][2];
#pragma unroll
            for (int nt = 0; nt < 4; nt++) {
                asm volatile("ldmatrix.sync.aligned.m8n8.x2.shared.b16 {%0,%1}, [%2];"
                    : "=r"(bfr[nt][0]), "=r"(bfr[nt][1]) : "r"(bB + boff + ko + nt * (8 * 80)));
            }
#pragma unroll
            for (int mt = 0; mt < 4; mt++)
#pragma unroll
                for (int nt = 0; nt < 4; nt++) {
                    asm volatile(
                        "mma.sync.aligned.m16n8k16.row.col.f32.f16.f16.f32 "
                        "{%0,%1,%2,%3}, {%4,%5,%6,%7}, {%8,%9}, {%0,%1,%2,%3};"
                        : "+f"(acc[mt][nt][0]), "+f"(acc[mt][nt][1]),
                          "+f"(acc[mt][nt][2]), "+f"(acc[mt][nt][3])
                        : "r"(af[mt][0]), "r"(af[mt][1]), "r"(af[mt][2]), "r"(af[mt][3]),
                          "r"(bfr[nt][0]), "r"(bfr[nt][1]));
                }
        }
        __syncthreads();
        if (kc + 2 < nk) LOAD_STAGE(kc + 2, buf);
    }

#pragma unroll
    for (int mt = 0; mt < 4; mt++) {
        int r0 = m0 + wm * 64 + mt * 16 + gid;
#pragma unroll
        for (int nt = 0; nt < 4; nt++) {
            int cl = wn * 32 + nt * 8 + 2 * tg;
            float b0 = shb[cl], b1 = shb[cl + 1];
            *(float2*)(C + (size_t)r0 * N + n0 + cl) =
                make_float2(acc[mt][nt][0] + b0, acc[mt][nt][1] + b1);
            *(float2*)(C + (size_t)(r0 + 8) * N + n0 + cl) =
                make_float2(acc[mt][nt][2] + b0, acc[mt][nt][3] + b1);
        }
    }
}

// ---------------- persistent tensor-core LSTM layer: 2-term fp16 (unchanged) ----------------
#define RP     1040
#define OFF_AHI 0
#define OFF_ALO (64 * RP)
#define OFF_B   (2 * 64 * RP)
#define OFF_G0  (2 * 64 * RP + 32 * RP)
#define OFF_G1  (OFF_G0 + 64 * 33 * 4)
#define RK_SMEM (OFF_G1 + 64 * 33 * 4)        // 183296

__global__ __launch_bounds__(256, 1) void lstm_layer_tc(
    const float* __restrict__ gates_f,
    const float* __restrict__ gates_r,
    const __half* __restrict__ WhfHi, const __half* __restrict__ WhfLo,
    const __half* __restrict__ WhrHi, const __half* __restrict__ WhrLo,
    __half* __restrict__ sh16,
    float* __restrict__ outbuf,
    int out_mode)
{
    extern __shared__ char sm[];
    uint32_t sb = smem_u32(sm);
    int tid  = threadIdx.x;
    int lane = tid & 31;
    int warp = tid >> 5;
    int gid  = lane >> 2;
    int tg   = lane & 3;

    int bx  = blockIdx.x;
    int dir = bx >> 6;
    int us  = (bx >> 1) & 31;
    int bs  = bx & 1;
    int u0  = us * 16;
    int b0  = bs * 32;
    int grp = dir * 2 + bs;
    unsigned* gbar = (unsigned*)&g_bar4[grp * 32];

    const float* gates = dir ? gates_r : gates_f;
    const __half* whH = dir ? WhrHi : WhfHi;
    const __half* whL = dir ? WhrLo : WhfLo;

#pragma unroll
    for (int j = 0; j < 16; j++) {
        int idx = tid + j * 256;
        int row = idx >> 6;
        int ch  = idx & 63;
        int g   = row >> 4;
        int ul  = row & 15;
        size_t soff = (size_t)(g * HH + u0 + ul) * HH + ch * 8;
        *(uint4*)(sm + OFF_AHI + row * RP + ch * 16) = *(const uint4*)(whH + soff);
        *(uint4*)(sm + OFF_ALO + row * RP + ch * 16) = *(const uint4*)(whL + soff);
    }

    int wk = warp >> 2;
    int wm = (warp >> 1) & 1;
    int wn = warp & 1;
    uint32_t apat = (uint32_t)(lane & 15) * RP + (lane >> 4) * 16;
    uint32_t bpat = (uint32_t)((lane & 7) + ((lane >> 4) << 3)) * RP + ((lane >> 3) & 1) * 16;
    uint32_t aBaseHi = sb + OFF_AHI + wm * 32 * RP + apat;
    uint32_t aBaseLo = sb + OFF_ALO + wm * 32 * RP + apat;
    uint32_t bBase   = sb + OFF_B   + wn * 16 * RP + bpat;
    float* gbuf = (float*)(sm + (wk ? OFF_G1 : OFF_G0));
    float* g0f  = (float*)(sm + OFF_G0);
    float* g1f  = (float*)(sm + OFF_G1);

    int bown = tid >> 3;
    int u2   = (tid & 7) * 2;
    float cst0 = 0.0f, cst1 = 0.0f;

    for (int s = 0; s < LL; s++) {
        int t   = dir ? (LL - 1 - s) : s;
        int par = s & 1;
        const __half* hin  = sh16 + ((dir * 2 + par) * BB) * HH;
        __half*       hout = sh16 + ((dir * 2 + (par ^ 1)) * BB) * HH;

        float2 pg[4];
        {
            size_t gbase = ((size_t)t * BB + (b0 + bown)) * G4 + (u0 + u2);
#pragma unroll
            for (int g = 0; g < 4; g++)
                pg[g] = __ldcg((const float2*)&gates[gbase + g * HH]);
        }

#pragma unroll
        for (int j = 0; j < 8; j++) {
            int idx = tid + j * 256;
            int row = idx >> 6;
            int ch  = idx & 63;
            uint4 v = __ldcg((const uint4*)(hin + (size_t)(b0 + row) * HH + ch * 8));
            *(uint4*)(sm + OFF_B + row * RP + ch * 16) = v;
        }
        __syncthreads();

        float t0[2][2][4], t1[2][2][4];
#pragma unroll
        for (int i = 0; i < 2; i++)
#pragma unroll
            for (int j = 0; j < 2; j++)
#pragma unroll
                for (int r = 0; r < 4; r++) { t0[i][j][r] = 0.f; t1[i][j][r] = 0.f; }

#pragma unroll 4
        for (int kc = 0; kc < 16; kc++) {
            uint32_t kb = (uint32_t)(wk * 16 + kc) * 32;
            uint32_t ah[2][4], al[2][4];
#pragma unroll
            for (int mt = 0; mt < 2; mt++) {
                asm volatile("ldmatrix.sync.aligned.m8n8.x4.shared.b16 {%0,%1,%2,%3}, [%4];"
                    : "=r"(ah[mt][0]), "=r"(ah[mt][1]), "=r"(ah[mt][2]), "=r"(ah[mt][3])
                    : "r"(aBaseHi + kb + mt * (16 * RP)));
                asm volatile("ldmatrix.sync.aligned.m8n8.x4.shared.b16 {%0,%1,%2,%3}, [%4];"
                    : "=r"(al[mt][0]), "=r"(al[mt][1]), "=r"(al[mt][2]), "=r"(al[mt][3])
                    : "r"(aBaseLo + kb + mt * (16 * RP)));
            }
            uint32_t bf[4];
            asm volatile("ldmatrix.sync.aligned.m8n8.x4.shared.b16 {%0,%1,%2,%3}, [%4];"
                : "=r"(bf[0]), "=r"(bf[1]), "=r"(bf[2]), "=r"(bf[3]) : "r"(bBase + kb));
#pragma unroll
            for (int mt = 0; mt < 2; mt++)
#pragma unroll
                for (int nf = 0; nf < 2; nf++) {
                    asm volatile(
                        "mma.sync.aligned.m16n8k16.row.col.f32.f16.f16.f32 "
                        "{%0,%1,%2,%3}, {%4,%5,%6,%7}, {%8,%9}, {%0,%1,%2,%3};"
                        : "+f"(t0[mt][nf][0]), "+f"(t0[mt][nf][1]),
                          "+f"(t0[mt][nf][2]), "+f"(t0[mt][nf][3])
                        : "r"(ah[mt][0]), "r"(ah[mt][1]), "r"(ah[mt][2]), "r"(ah[mt][3]),
                          "r"(bf[nf * 2]), "r"(bf[nf * 2 + 1]));
                    asm volatile(
                        "mma.sync.aligned.m16n8k16.row.col.f32.f16.f16.f32 "
                        "{%0,%1,%2,%3}, {%4,%5,%6,%7}, {%8,%9}, {%0,%1,%2,%3};"
                        : "+f"(t1[mt][nf][0]), "+f"(t1[mt][nf][1]),
                          "+f"(t1[mt][nf][2]), "+f"(t1[mt][nf][3])
                        : "r"(al[mt][0]), "r"(al[mt][1]), "r"(al[mt][2]), "r"(al[mt][3]),
                          "r"(bf[nf * 2]), "r"(bf[nf * 2 + 1]));
                }
        }

#pragma unroll
        for (int mt = 0; mt < 2; mt++) {
            int r0 = wm * 32 + mt * 16 + gid;
#pragma unroll
            for (int nf = 0; nf < 2; nf++) {
                int cl = wn * 16 + nf * 8 + 2 * tg;
                gbuf[r0 * 33 + cl]           = t0[mt][nf][0] + t1[mt][nf][0];
                gbuf[r0 * 33 + cl + 1]       = t0[mt][nf][1] + t1[mt][nf][1];
                gbuf[(r0 + 8) * 33 + cl]     = t0[mt][nf][2] + t1[mt][nf][2];
                gbuf[(r0 + 8) * 33 + cl + 1] = t0[mt][nf][3] + t1[mt][nf][3];
            }
        }
        __syncthreads();

        {
            float a0[4], a1[4];
#pragma unroll
            for (int g = 0; g < 4; g++) {
                int r0 = g * 16 + u2;
                a0[g] = g0f[r0 * 33 + bown] + g1f[r0 * 33 + bown];
                a1[g] = g0f[(r0 + 1) * 33 + bown] + g1f[(r0 + 1) * 33 + bown];
            }
            float gi0 = pg[0].x + a0[0], gi1 = pg[0].y + a1[0];
            float gf0 = pg[1].x + a0[1], gf1 = pg[1].y + a1[1];
            float gg0 = pg[2].x + a0[2], gg1 = pg[2].y + a1[2];
            float go0 = pg[3].x + a0[3], go1 = pg[3].y + a1[3];
            float si0 = fsig(gi0), si1 = fsig(gi1);
            float sf0 = fsig(gf0), sf1 = fsig(gf1);
            float so0 = fsig(go0), so1 = fsig(go1);
            cst0 = sf0 * cst0 + si0 * ftanh(gg0);
            cst1 = sf1 * cst1 + si1 * ftanh(gg1);
            float h20 = so0 * ftanh(cst0);
            float h21 = so1 * ftanh(cst1);
            int bg = b0 + bown;
            size_t hoff = (size_t)bg * HH + u0 + u2;
            __stcg((__half2*)&hout[hoff], __floats2half2_rn(h20, h21));
            size_t orow = out_mode ? ((size_t)bg * LL + t) : ((size_t)t * BB + bg);
            *(float2*)(outbuf + orow * (2 * HH) + dir * HH + u0 + u2) = make_float2(h20, h21);
        }

        __syncthreads();
        if (tid == 0) {
            unsigned target = (unsigned)(s + 1) * 32u;
            asm volatile("red.release.gpu.global.add.u32 [%0], %1;"
                         :: "l"(gbar), "r"(1u) : "memory");
            unsigned v;
            do {
                asm volatile("ld.acquire.gpu.global.u32 %0, [%1];"
                             : "=r"(v) : "l"(gbar) : "memory");
            } while (v < target);
        }
        __syncthreads();
    }
}

// ---------------- host launcher ----------------
extern "C" void kernel_launch(void* const* d_in, const int* in_sizes, int n_in,
                              void* d_out, int out_size)
{
    const float* x       = (const float*)d_in[0];
    const float* Wih_f0  = (const float*)d_in[1];
    const float* Whh_f0  = (const float*)d_in[2];
    const float* bih_f0  = (const float*)d_in[3];
    const float* bhh_f0  = (const float*)d_in[4];
    const float* Wih_r0  = (const float*)d_in[5];
    const float* Whh_r0  = (const float*)d_in[6];
    const float* bih_r0  = (const float*)d_in[7];
    const float* bhh_r0  = (const float*)d_in[8];
    const float* Wih_f1  = (const float*)d_in[9];
    const float* Whh_f1  = (const float*)d_in[10];
    const float* bih_f1  = (const float*)d_in[11];
    const float* bhh_f1  = (const float*)d_in[12];
    const float* Wih_r1  = (const float*)d_in[13];
    const float* Whh_r1  = (const float*)d_in[14];
    const float* bih_r1  = (const float*)d_in[15];
    const float* bhh_r1  = (const float*)d_in[16];

    float *xT, *gf, *gr, *hcat;
    unsigned* bar4;
    __half *Af16, *Wf16f, *Wf16r;
    __half *WhfHi, *WhfLo, *WhrHi, *WhrLo, *sh16;
    cudaGetSymbolAddress((void**)&xT,    g_xT);
    cudaGetSymbolAddress((void**)&gf,    g_gates_f);
    cudaGetSymbolAddress((void**)&gr,    g_gates_r);
    cudaGetSymbolAddress((void**)&hcat,  g_hcat);
    cudaGetSymbolAddress((void**)&bar4,  g_bar4);
    cudaGetSymbolAddress((void**)&Af16,  g_Af16);
    cudaGetSymbolAddress((void**)&Wf16f, g_Wf16f);
    cudaGetSymbolAddress((void**)&Wf16r, g_Wf16r);
    cudaGetSymbolAddress((void**)&WhfHi, g_WhfHi);
    cudaGetSymbolAddress((void**)&WhfLo, g_WhfLo);
    cudaGetSymbolAddress((void**)&WhrHi, g_WhrHi);
    cudaGetSymbolAddress((void**)&WhrLo, g_WhrLo);
    cudaGetSymbolAddress((void**)&sh16,  g_sh16);

    cudaFuncSetAttribute(gemm_f16,      cudaFuncAttributeMaxDynamicSharedMemorySize, GB_SMEM);
    cudaFuncSetAttribute(lstm_layer_tc, cudaFuncAttributeMaxDynamicSharedMemorySize, RK_SMEM);

    const int M = LL * BB;   // 32768
    const int whn4 = (G4 * HH) / 4;

    transpose_x<<<8192, 256>>>((const float4*)x, (float4*)xT);

    dim3 ggrid(G4 / 128, M / 128);   // (16, 256)

    // ---- layer 0 (K = 256) ----
    {
        int n4 = (LL * BB * II) / 4;
        cvt_f16<<<(n4 + 255) / 256, 256>>>((const float4*)xT, (__half2*)Af16, n4);
        int w4 = (G4 * II) / 4;
        cvt_f16<<<(w4 + 255) / 256, 256>>>((const float4*)Wih_f0, (__half2*)Wf16f, w4);
        cvt_f16<<<(w4 + 255) / 256, 256>>>((const float4*)Wih_r0, (__half2*)Wf16r, w4);
        gemm_f16<<<ggrid, 256, GB_SMEM>>>(M, G4, II, Af16, Wf16f, bih_f0, bhh_f0, gf);
        gemm_f16<<<ggrid, 256, GB_SMEM>>>(M, G4, II, Af16, Wf16r, bih_r0, bhh_r0, gr);
        split_f16<<<(whn4 + 255) / 256, 256>>>((const float4*)Whh_f0,
            (__half2*)WhfHi, (__half2*)WhfLo, whn4);
        split_f16<<<(whn4 + 255) / 256, 256>>>((const float4*)Whh_r0,
            (__half2*)WhrHi, (__half2*)WhrLo, whn4);
    }
    cudaMemsetAsync(sh16, 0, sizeof(__half) * 2 * 2 * BB * HH, 0);
    cudaMemsetAsync(bar4, 0, sizeof(unsigned) * 4 * 32, 0);
    lstm_layer_tc<<<128, 256, RK_SMEM>>>(gf, gr, WhfHi, WhfLo, WhrHi, WhrLo,
                                         sh16, hcat, 0);

    // ---- layer 1 (K = 1024) ----
    {
        int n4 = (LL * BB * 2 * HH) / 4;
        cvt_f16<<<(n4 + 255) / 256, 256>>>((const float4*)hcat, (__half2*)Af16, n4);
        int w4 = (G4 * 2 * HH) / 4;
        cvt_f16<<<(w4 + 255) / 256, 256>>>((const float4*)Wih_f1, (__half2*)Wf16f, w4);
        cvt_f16<<<(w4 + 255) / 256, 256>>>((const float4*)Wih_r1, (__half2*)Wf16r, w4);
        gemm_f16<<<ggrid, 256, GB_SMEM>>>(M, G4, 2 * HH, Af16, Wf16f, bih_f1, bhh_f1, gf);
        gemm_f16<<<ggrid, 256, GB_SMEM>>>(M, G4, 2 * HH, Af16, Wf16r, bih_r1, bhh_r1, gr);
        split_f16<<<(whn4 + 255) / 256, 256>>>((const float4*)Whh_f1,
            (__half2*)WhfHi, (__half2*)WhfLo, whn4);
        split_f16<<<(whn4 + 255) / 256, 256>>>((const float4*)Whh_r1,
            (__half2*)WhrHi, (__half2*)WhrLo, whn4);
    }
    cudaMemsetAsync(sh16, 0, sizeof(__half) * 2 * 2 * BB * HH, 0);
    cudaMemsetAsync(bar4, 0, sizeof(unsigned) * 4 * 32, 0);
    lstm_layer_tc<<<128, 256, RK_SMEM>>>(gf, gr, WhfHi, WhfLo, WhrHi, WhrLo,
                                         sh16, (float*)d_out, 1);
}

// round 14
// speedup vs baseline: 4.7476x; 1.1186x over previous
#include <cuda_runtime.h>
#include <cuda_bf16.h>
#include <cuda_fp16.h>
#include <math.h>
#include <cstdint>

// Problem dims
#define LL 512
#define BB 64
#define II 256
#define HH 512
#define G4 2048   // 4*H

// ---------------- scratch (static device globals; no allocation) ----------------
__device__ float g_gates_f[(size_t)LL * BB * G4];     // [t][b][4H]
__device__ float g_gates_r[(size_t)LL * BB * G4];     // [t][b][4H]
__device__ unsigned g_bar4[4 * 32];                   // 4 group barriers, 128B apart

// h state as SINGLE fp16: [dir][parity][b][u]
__device__ __align__(16) __half g_sh16[2 * 2 * BB * HH];

// fp16 GEMM operands: A single (layer0: xT fp16; layer1: hcat fp16), W single per dir
__device__ __align__(16) __half g_Af16[(size_t)LL * BB * 2 * HH];
__device__ __align__(16) __half g_Wf16f[(size_t)G4 * 2 * HH];
__device__ __align__(16) __half g_Wf16r[(size_t)G4 * 2 * HH];
// Whh fp16 (single) for the recurrence ([2048][512] each)
__device__ __align__(16) __half g_Whf16f[(size_t)G4 * HH];
__device__ __align__(16) __half g_Whf16r[(size_t)G4 * HH];

__device__ __forceinline__ uint32_t smem_u32(const void* p) {
    uint32_t a;
    asm("{ .reg .u64 t; cvta.to.shared.u64 t, %1; cvt.u32.u64 %0, t; }" : "=r"(a) : "l"(p));
    return a;
}

__device__ __forceinline__ float fsig(float x) {
    return 1.0f / (1.0f + __expf(-x));
}
__device__ __forceinline__ float ftanh(float x) {
    return fmaf(2.0f, fsig(2.0f * x), -1.0f);
}

// ---------------- transpose + convert: x[b][l][i] fp32 -> Af16[l*BB+b][i] fp16 ----------------
__global__ void transpose_cvt_x(const float4* __restrict__ x, __half2* __restrict__ xT) {
    int idx = blockIdx.x * blockDim.x + threadIdx.x;   // over LL*BB*(II/4)
    int i4 = idx & 63;            // II/4 = 64
    int m  = idx >> 6;            // t*64 + b
    int t  = m >> 6;
    int b  = m & 63;
    float4 v = x[((size_t)(b * LL + t)) * 64 + i4];
    xT[idx * 2 + 0] = __floats2half2_rn(v.x, v.y);
    xT[idx * 2 + 1] = __floats2half2_rn(v.z, v.w);
}

// ---------------- fp32 -> fp16 convert ----------------
__global__ void cvt_f16(const float4* __restrict__ src, __half2* __restrict__ dst, int n4) {
    int i = blockIdx.x * blockDim.x + threadIdx.x;
    if (i >= n4) return;
    float4 v = src[i];
    dst[i * 2 + 0] = __floats2half2_rn(v.x, v.y);
    dst[i * 2 + 1] = __floats2half2_rn(v.z, v.w);
}

// ---------------- plain fp16 GEMM: C = A_f16 @ W_f16^T + bias (unchanged, known-good) ----------------
#define GBK   32
#define GTILE 10240                 // 128 * 80
#define GSTG  (2 * GTILE)           // 20480
#define GB_SMEM (2 * GSTG + 512)    // 41472; x2 CTAs = 83KB

__global__ __launch_bounds__(256, 2) void gemm_f16(
    int M, int N, int K,
    const __half* __restrict__ A,
    const __half* __restrict__ B,
    const float* __restrict__ bias1, const float* __restrict__ bias2,
    float* __restrict__ C)
{
    extern __shared__ char sm[];
    uint32_t sb = smem_u32(sm);
    int tid  = threadIdx.x;
    int lane = tid & 31;
    int warp = tid >> 5;
    int gid  = lane >> 2;
    int tg   = lane & 3;
    int wm   = warp >> 2;
    int wn   = warp & 3;
    int n0   = blockIdx.x * 128;
    int m0   = blockIdx.y * 128;

    float* shb = (float*)(sm + 2 * GSTG);
    if (tid < 128) shb[tid] = bias1[n0 + tid] + bias2[n0 + tid];

    const char* srcs[2];
    srcs[0] = (const char*)(A + (size_t)m0 * K);
    srcs[1] = (const char*)(B + (size_t)n0 * K);

#define LOAD_STAGE(kc, bufsel)                                                      \
    {                                                                               \
        _Pragma("unroll")                                                           \
        for (int j = 0; j < 4; j++) {                                               \
            int c    = tid + j * 256;                                               \
            int tile = c >> 9;                                                      \
            int cc   = c & 511;                                                     \
            int row  = cc >> 2, g = cc & 3;                                         \
            uint32_t d = sb + (bufsel) * GSTG + tile * GTILE + row * 80 + g * 16;   \
            const char* s = srcs[tile] + ((size_t)row * K + (kc) * GBK) * 2 + g * 16; \
            asm volatile("cp.async.ca.shared.global [%0], [%1], 16;" :: "r"(d), "l"(s)); \
        }                                                                           \
        asm volatile("cp.async.commit_group;" ::: "memory");                        \
    }

    float acc[4][4][4];
#pragma unroll
    for (int i = 0; i < 4; i++)
#pragma unroll
        for (int j = 0; j < 4; j++)
#pragma unroll
            for (int r = 0; r < 4; r++) acc[i][j][r] = 0.0f;

    int nk = K / GBK;
    LOAD_STAGE(0, 0);
    LOAD_STAGE(1, 1);

    for (int kc = 0; kc < nk; kc++) {
        if (kc + 1 < nk)
            asm volatile("cp.async.wait_group 1;" ::: "memory");
        else
            asm volatile("cp.async.wait_group 0;" ::: "memory");
        __syncthreads();

        int buf = kc & 1;
        uint32_t bA = sb + buf * GSTG;
        uint32_t bB = bA + GTILE;

        uint32_t aoff = (uint32_t)(wm * 64 + (lane & 15)) * 80 + (lane >> 4) * 16;
        uint32_t boff = (uint32_t)(wn * 32 + (lane & 7)) * 80 + ((lane >> 3) & 1) * 16;

#pragma unroll
        for (int ks = 0; ks < 2; ks++) {
            uint32_t ko = ks * 32;
            uint32_t af[4][4];
#pragma unroll
            for (int mt = 0; mt < 4; mt++) {
                asm volatile("ldmatrix.sync.aligned.m8n8.x4.shared.b16 {%0,%1,%2,%3}, [%4];"
                    : "=r"(af[mt][0]), "=r"(af[mt][1]), "=r"(af[mt][2]), "=r"(af[mt][3])
                    : "r"(bA + aoff + ko + mt * (16 * 80)));
            }
            uint32_t bfr[4][2];
#pragma unroll
            for (int nt = 0; nt < 4; nt++) {
                asm volatile("ldmatrix.sync.aligned.m8n8.x2.shared.b16 {%0,%1}, [%2];"
                    : "=r"(bfr[nt][0]), "=r"(bfr[nt][1]) : "r"(bB + boff + ko + nt * (8 * 80)));
            }
#pragma unroll
            for (int mt = 0; mt < 4; mt++)
#pragma unroll
                for (int nt = 0; nt < 4; nt++) {
                    asm volatile(
                        "mma.sync.aligned.m16n8k16.row.col.f32.f16.f16.f32 "
                        "{%0,%1,%2,%3}, {%4,%5,%6,%7}, {%8,%9}, {%0,%1,%2,%3};"
                        : "+f"(acc[mt][nt][0]), "+f"(acc[mt][nt][1]),
                          "+f"(acc[mt][nt][2]), "+f"(acc[mt][nt][3])
                        : "r"(af[mt][0]), "r"(af[mt][1]), "r"(af[mt][2]), "r"(af[mt][3]),
                          "r"(bfr[nt][0]), "r"(bfr[nt][1]));
                }
        }
        __syncthreads();
        if (kc + 2 < nk) LOAD_STAGE(kc + 2, buf);
    }

#pragma unroll
    for (int mt = 0; mt < 4; mt++) {
        int r0 = m0 + wm * 64 + mt * 16 + gid;
#pragma unroll
        for (int nt = 0; nt < 4; nt++) {
            int cl = wn * 32 + nt * 8 + 2 * tg;
            float b0 = shb[cl], b1 = shb[cl + 1];
            *(float2*)(C + (size_t)r0 * N + n0 + cl) =
                make_float2(acc[mt][nt][0] + b0, acc[mt][nt][1] + b1);
            *(float2*)(C + (size_t)(r0 + 8) * N + n0 + cl) =
                make_float2(acc[mt][nt][2] + b0, acc[mt][nt][3] + b1);
        }
    }
}

// ---------------- persistent tensor-core LSTM layer: single-term fp16 ----------------
// out_mode 0: write fp16 layer output into Af16 [t*BB+b][2H] (feeds layer-1 GEMM).
// out_mode 1: write fp32 into d_out [b*LL+t][2H].
#define RP     1040
#define OFF_A  0
#define OFF_B  (64 * RP)
#define OFF_G0 (64 * RP + 32 * RP)
#define OFF_G1 (OFF_G0 + 64 * 33 * 4)
#define RK_SMEM (OFF_G1 + 64 * 33 * 4)        // 116736

__global__ __launch_bounds__(256, 1) void lstm_layer_tc(
    const float* __restrict__ gates_f,
    const float* __restrict__ gates_r,
    const __half* __restrict__ Whf16f, const __half* __restrict__ Whf16r,
    __half* __restrict__ sh16,
    void* __restrict__ outbuf,
    int out_mode)
{
    extern __shared__ char sm[];
    uint32_t sb = smem_u32(sm);
    int tid  = threadIdx.x;
    int lane = tid & 31;
    int warp = tid >> 5;
    int gid  = lane >> 2;
    int tg   = lane & 3;

    int bx  = blockIdx.x;
    int dir = bx >> 6;
    int us  = (bx >> 1) & 31;
    int bs  = bx & 1;
    int u0  = us * 16;
    int b0  = bs * 32;
    int grp = dir * 2 + bs;
    unsigned* gbar = (unsigned*)&g_bar4[grp * 32];

    const float* gates = dir ? gates_r : gates_f;
    const __half* wh = dir ? Whf16r : Whf16f;

    // ---- stage Whh slice once (single fp16) ----
#pragma unroll
    for (int j = 0; j < 16; j++) {
        int idx = tid + j * 256;        // 0..4095
        int row = idx >> 6;             // 0..63
        int ch  = idx & 63;
        int g   = row >> 4;
        int ul  = row & 15;
        size_t soff = (size_t)(g * HH + u0 + ul) * HH + ch * 8;
        *(uint4*)(sm + OFF_A + row * RP + ch * 16) = *(const uint4*)(wh + soff);
    }

    int wk = warp >> 2;
    int wm = (warp >> 1) & 1;
    int wn = warp & 1;
    uint32_t apat = (uint32_t)(lane & 15) * RP + (lane >> 4) * 16;
    uint32_t bpat = (uint32_t)((lane & 7) + ((lane >> 4) << 3)) * RP + ((lane >> 3) & 1) * 16;
    uint32_t aBase = sb + OFF_A + wm * 32 * RP + apat;
    uint32_t bBase = sb + OFF_B + wn * 16 * RP + bpat;
    float* gbuf = (float*)(sm + (wk ? OFF_G1 : OFF_G0));
    float* g0f  = (float*)(sm + OFF_G0);
    float* g1f  = (float*)(sm + OFF_G1);

    int bown = tid >> 3;
    int u2   = (tid & 7) * 2;
    float cst0 = 0.0f, cst1 = 0.0f;

    for (int s = 0; s < LL; s++) {
        int t   = dir ? (LL - 1 - s) : s;
        int par = s & 1;
        const __half* hin  = sh16 + ((dir * 2 + par) * BB) * HH;
        __half*       hout = sh16 + ((dir * 2 + (par ^ 1)) * BB) * HH;

        // ---- prefetch this thread's gate inputs (float2 per gate) ----
        float2 pg[4];
        {
            size_t gbase = ((size_t)t * BB + (b0 + bown)) * G4 + (u0 + u2);
#pragma unroll
            for (int g = 0; g < 4; g++)
                pg[g] = __ldcg((const float2*)&gates[gbase + g * HH]);
        }

        // ---- stage h tile (32 b x 512 fp16) ----
#pragma unroll
        for (int j = 0; j < 8; j++) {
            int idx = tid + j * 256;
            int row = idx >> 6;
            int ch  = idx & 63;
            uint4 v = __ldcg((const uint4*)(hin + (size_t)(b0 + row) * HH + ch * 8));
            *(uint4*)(sm + OFF_B + row * RP + ch * 16) = v;
        }
        __syncthreads();

        // ---- single-term HMMA over this warp's 16 k-chunks ----
        float t0[2][2][4];
#pragma unroll
        for (int i = 0; i < 2; i++)
#pragma unroll
            for (int j = 0; j < 2; j++)
#pragma unroll
                for (int r = 0; r < 4; r++) t0[i][j][r] = 0.f;

#pragma unroll 4
        for (int kc = 0; kc < 16; kc++) {
            uint32_t kb = (uint32_t)(wk * 16 + kc) * 32;
            uint32_t af[2][4];
#pragma unroll
            for (int mt = 0; mt < 2; mt++) {
                asm volatile("ldmatrix.sync.aligned.m8n8.x4.shared.b16 {%0,%1,%2,%3}, [%4];"
                    : "=r"(af[mt][0]), "=r"(af[mt][1]), "=r"(af[mt][2]), "=r"(af[mt][3])
                    : "r"(aBase + kb + mt * (16 * RP)));
            }
            uint32_t bf[4];
            asm volatile("ldmatrix.sync.aligned.m8n8.x4.shared.b16 {%0,%1,%2,%3}, [%4];"
                : "=r"(bf[0]), "=r"(bf[1]), "=r"(bf[2]), "=r"(bf[3]) : "r"(bBase + kb));
#pragma unroll
            for (int mt = 0; mt < 2; mt++)
#pragma unroll
                for (int nf = 0; nf < 2; nf++) {
                    asm volatile(
                        "mma.sync.aligned.m16n8k16.row.col.f32.f16.f16.f32 "
                        "{%0,%1,%2,%3}, {%4,%5,%6,%7}, {%8,%9}, {%0,%1,%2,%3};"
                        : "+f"(t0[mt][nf][0]), "+f"(t0[mt][nf][1]),
                          "+f"(t0[mt][nf][2]), "+f"(t0[mt][nf][3])
                        : "r"(af[mt][0]), "r"(af[mt][1]), "r"(af[mt][2]), "r"(af[mt][3]),
                          "r"(bf[nf * 2]), "r"(bf[nf * 2 + 1]));
                }
        }

        // ---- write k-partials to gate buffer (scalar: pitch 33 odd) ----
#pragma unroll
        for (int mt = 0; mt < 2; mt++) {
            int r0 = wm * 32 + mt * 16 + gid;
#pragma unroll
            for (int nf = 0; nf < 2; nf++) {
                int cl = wn * 16 + nf * 8 + 2 * tg;
                gbuf[r0 * 33 + cl]           = t0[mt][nf][0];
                gbuf[r0 * 33 + cl + 1]       = t0[mt][nf][1];
                gbuf[(r0 + 8) * 33 + cl]     = t0[mt][nf][2];
                gbuf[(r0 + 8) * 33 + cl + 1] = t0[mt][nf][3];
            }
        }
        __syncthreads();

        // ---- epilogue ----
        {
            float a0[4], a1[4];
#pragma unroll
            for (int g = 0; g < 4; g++) {
                int r0 = g * 16 + u2;
                a0[g] = g0f[r0 * 33 + bown] + g1f[r0 * 33 + bown];
                a1[g] = g0f[(r0 + 1) * 33 + bown] + g1f[(r0 + 1) * 33 + bown];
            }
            float gi0 = pg[0].x + a0[0], gi1 = pg[0].y + a1[0];
            float gf0 = pg[1].x + a0[1], gf1 = pg[1].y + a1[1];
            float gg0 = pg[2].x + a0[2], gg1 = pg[2].y + a1[2];
            float go0 = pg[3].x + a0[3], go1 = pg[3].y + a1[3];
            float si0 = fsig(gi0), si1 = fsig(gi1);
            float sf0 = fsig(gf0), sf1 = fsig(gf1);
            float so0 = fsig(go0), so1 = fsig(go1);
            cst0 = sf0 * cst0 + si0 * ftanh(gg0);
            cst1 = sf1 * cst1 + si1 * ftanh(gg1);
            float h20 = so0 * ftanh(cst0);
            float h21 = so1 * ftanh(cst1);
            int bg = b0 + bown;
            size_t hoff = (size_t)bg * HH + u0 + u2;
            __half2 hp = __floats2half2_rn(h20, h21);
            __stcg((__half2*)&hout[hoff], hp);
            if (out_mode) {
                size_t orow = (size_t)bg * LL + t;
                *(float2*)((float*)outbuf + orow * (2 * HH) + dir * HH + u0 + u2) =
                    make_float2(h20, h21);
            } else {
                size_t orow = (size_t)t * BB + bg;
                *((__half2*)((__half*)outbuf + orow * (2 * HH) + dir * HH + u0 + u2)) = hp;
            }
        }

        // ---- group barrier across 32 CTAs ----
        __syncthreads();
        if (tid == 0) {
            unsigned target = (unsigned)(s + 1) * 32u;
            asm volatile("red.release.gpu.global.add.u32 [%0], %1;"
                         :: "l"(gbar), "r"(1u) : "memory");
            unsigned v;
            do {
                asm volatile("ld.acquire.gpu.global.u32 %0, [%1];"
                             : "=r"(v) : "l"(gbar) : "memory");
            } while (v < target);
        }
        __syncthreads();
    }
}

// ---------------- host launcher ----------------
extern "C" void kernel_launch(void* const* d_in, const int* in_sizes, int n_in,
                              void* d_out, int out_size)
{
    const float* x       = (const float*)d_in[0];
    const float* Wih_f0  = (const float*)d_in[1];
    const float* Whh_f0  = (const float*)d_in[2];
    const float* bih_f0  = (const float*)d_in[3];
    const float* bhh_f0  = (const float*)d_in[4];
    const float* Wih_r0  = (const float*)d_in[5];
    const float* Whh_r0  = (const float*)d_in[6];
    const float* bih_r0  = (const float*)d_in[7];
    const float* bhh_r0  = (const float*)d_in[8];
    const float* Wih_f1  = (const float*)d_in[9];
    const float* Whh_f1  = (const float*)d_in[10];
    const float* bih_f1  = (const float*)d_in[11];
    const float* bhh_f1  = (const float*)d_in[12];
    const float* Wih_r1  = (const float*)d_in[13];
    const float* Whh_r1  = (const float*)d_in[14];
    const float* bih_r1  = (const float*)d_in[15];
    const float* bhh_r1  = (const float*)d_in[16];

    float *gf, *gr;
    unsigned* bar4;
    __half *Af16, *Wf16f, *Wf16r, *Whf16f, *Whf16r, *sh16;
    cudaGetSymbolAddress((void**)&gf,     g_gates_f);
    cudaGetSymbolAddress((void**)&gr,     g_gates_r);
    cudaGetSymbolAddress((void**)&bar4,   g_bar4);
    cudaGetSymbolAddress((void**)&Af16,   g_Af16);
    cudaGetSymbolAddress((void**)&Wf16f,  g_Wf16f);
    cudaGetSymbolAddress((void**)&Wf16r,  g_Wf16r);
    cudaGetSymbolAddress((void**)&Whf16f, g_Whf16f);
    cudaGetSymbolAddress((void**)&Whf16r, g_Whf16r);
    cudaGetSymbolAddress((void**)&sh16,   g_sh16);

    cudaFuncSetAttribute(gemm_f16,      cudaFuncAttributeMaxDynamicSharedMemorySize, GB_SMEM);
    cudaFuncSetAttribute(lstm_layer_tc, cudaFuncAttributeMaxDynamicSharedMemorySize, RK_SMEM);

    const int M = LL * BB;   // 32768
    const int whn4 = (G4 * HH) / 4;

    // x -> Af16 [t*BB+b][I] fp16 (fused transpose+convert)
    transpose_cvt_x<<<8192, 256>>>((const float4*)x, (__half2*)Af16);

    dim3 ggrid(G4 / 128, M / 128);   // (16, 256)

    // ---- layer 0 (K = 256) ----
    {
        int w4 = (G4 * II) / 4;
        cvt_f16<<<(w4 + 255) / 256, 256>>>((const float4*)Wih_f0, (__half2*)Wf16f, w4);
        cvt_f16<<<(w4 + 255) / 256, 256>>>((const float4*)Wih_r0, (__half2*)Wf16r, w4);
        gemm_f16<<<ggrid, 256, GB_SMEM>>>(M, G4, II, Af16, Wf16f, bih_f0, bhh_f0, gf);
        gemm_f16<<<ggrid, 256, GB_SMEM>>>(M, G4, II, Af16, Wf16r, bih_r0, bhh_r0, gr);
        cvt_f16<<<(whn4 + 255) / 256, 256>>>((const float4*)Whh_f0, (__half2*)Whf16f, whn4);
        cvt_f16<<<(whn4 + 255) / 256, 256>>>((const float4*)Whh_r0, (__half2*)Whf16r, whn4);
    }
    cudaMemsetAsync(sh16, 0, sizeof(__half) * 2 * 2 * BB * HH, 0);
    cudaMemsetAsync(bar4, 0, sizeof(unsigned) * 4 * 32, 0);
    // layer-0 recurrence writes fp16 output DIRECTLY into Af16 (layer-1 A operand)
    lstm_layer_tc<<<128, 256, RK_SMEM>>>(gf, gr, Whf16f, Whf16r, sh16, Af16, 0);

    // ---- layer 1 (K = 1024) ----
    {
        int w4 = (G4 * 2 * HH) / 4;
        cvt_f16<<<(w4 + 255) / 256, 256>>>((const float4*)Wih_f1, (__half2*)Wf16f, w4);
        cvt_f16<<<(w4 + 255) / 256, 256>>>((const float4*)Wih_r1, (__half2*)Wf16r, w4);
        gemm_f16<<<ggrid, 256, GB_SMEM>>>(M, G4, 2 * HH, Af16, Wf16f, bih_f1, bhh_f1, gf);
        gemm_f16<<<ggrid, 256, GB_SMEM>>>(M, G4, 2 * HH, Af16, Wf16r, bih_r1, bhh_r1, gr);
        cvt_f16<<<(whn4 + 255) / 256, 256>>>((const float4*)Whh_f1, (__half2*)Whf16f, whn4);
        cvt_f16<<<(whn4 + 255) / 256, 256>>>((const float4*)Whh_r1, (__half2*)Whf16r, whn4);
    }
    cudaMemsetAsync(sh16, 0, sizeof(__half) * 2 * 2 * BB * HH, 0);
    cudaMemsetAsync(bar4, 0, sizeof(unsigned) * 4 * 32, 0);
    lstm_layer_tc<<<128, 256, RK_SMEM>>>(gf, gr, Whf16f, Whf16r, sh16, d_out, 1);
}